// round 2
// baseline (speedup 1.0000x reference)
#include <cuda_runtime.h>
#include <math.h>

// Shapes
#define NBT   32          // B*T
#define CCH   192         // C
#define LHW   1024        // H*W
#define NTT   16          // T
#define NBHW  2048        // B*H*W
#define TOT   (NBT*CCH*LHW)   // 6291456, same as NBHW*CCH*NTT

// Scratch (device globals — no runtime allocation allowed)
__device__ float g_xs [TOT];         // pass1 input (bt,c,hw); reused as z in pass2
__device__ float g_nrm[TOT];         // groupnorm output (both passes)
__device__ float g_qkv[NBT*3*CCH*LHW]; // qkv (both passes; sizes equal)
__device__ float g_att[TOT];         // attention output (both passes)
__device__ float g_y  [TOT];         // y after proj+res (pass1)
__device__ float g_yt [TOT];         // y transposed to (bhw,c,t)

// ---------------------------------------------------------------------------
// Transposes
// ---------------------------------------------------------------------------
__global__ void k_transpose1(const float* __restrict__ x) {
    int o = blockIdx.x * 256 + threadIdx.x;
    if (o >= TOT) return;
    int hw = o & 1023;
    int c  = (o >> 10) % CCH;
    int bt = o / (CCH * LHW);
    int b = bt >> 4, t = bt & 15;
    g_xs[o] = x[((b * CCH + c) * 16 + t) * 1024 + hw];
}

__global__ void k_transpose2() {  // y (bt,c,hw) -> yt (bhw,c,t)
    int o = blockIdx.x * 256 + threadIdx.x;
    if (o >= TOT) return;
    int t   = o & 15;
    int c   = (o >> 4) % CCH;
    int bhw = o / (CCH * NTT);
    int b = bhw >> 10, hw = bhw & 1023;
    g_yt[o] = g_y[((b * 16 + t) * CCH + c) * 1024 + hw];
}

__global__ void k_transpose3(float* __restrict__ out) {  // z (bhw,c,t) -> (b,c,t,h,w)
    int o = blockIdx.x * 256 + threadIdx.x;
    if (o >= TOT) return;
    int hw = o & 1023;
    int t  = (o >> 10) & 15;
    int c  = (o >> 14) % CCH;
    int b  = o / (CCH * NTT * LHW);
    out[o] = g_xs[((b * 1024 + hw) * CCH + c) * 16 + t];
}

// ---------------------------------------------------------------------------
// GroupNorm(32 groups, C=192 -> 6 channels/group). One block per (n, group).
// Group data is contiguous: 6*L floats.
// ---------------------------------------------------------------------------
__global__ void k_groupnorm(const float* __restrict__ X, const float* __restrict__ gam,
                            const float* __restrict__ bet, float* __restrict__ out, int L) {
    int n = blockIdx.x >> 5;
    int g = blockIdx.x & 31;
    int len = 6 * L;
    const float* base = X + (size_t)(n * CCH + g * 6) * L;
    float* ob = out + (size_t)(n * CCH + g * 6) * L;
    float s = 0.f, q = 0.f;
    for (int i = threadIdx.x; i < len; i += 128) { float v = base[i]; s += v; q += v * v; }
    __shared__ float rs[128], rq[128];
    rs[threadIdx.x] = s; rq[threadIdx.x] = q;
    __syncthreads();
    for (int st = 64; st > 0; st >>= 1) {
        if (threadIdx.x < st) { rs[threadIdx.x] += rs[threadIdx.x + st]; rq[threadIdx.x] += rq[threadIdx.x + st]; }
        __syncthreads();
    }
    float mean = rs[0] / len;
    float var  = rq[0] / len - mean * mean;
    float inv  = rsqrtf(var + 1e-5f);
    for (int i = threadIdx.x; i < len; i += 128) {
        int c = g * 6 + i / L;
        ob[i] = (base[i] - mean) * inv * gam[c] + bet[c];
    }
}

// ---------------------------------------------------------------------------
// Pointwise conv (1x1): out[n][o][l] = bias[o] + sum_c W[o][c]*X[n][c][l] (+res)
// block = (LT, OT); smem = Cin*LT (X tile) + OT*Cin (W rows)
// ---------------------------------------------------------------------------
__global__ void k_conv1x1(const float* __restrict__ X, const float* __restrict__ W,
                          const float* __restrict__ bias, const float* __restrict__ res,
                          float* __restrict__ out, int Cin, int Cout, int L) {
    extern __shared__ float sm[];
    int LT = blockDim.x, OT = blockDim.y;
    float* Xs = sm;                // Cin*LT
    float* Ws = sm + Cin * LT;     // OT*Cin
    int n  = blockIdx.y;
    int l0 = blockIdx.x * LT;
    int tid = threadIdx.y * LT + threadIdx.x;
    int nt  = LT * OT;
    for (int i = tid; i < Cin * LT; i += nt)
        Xs[i] = X[(size_t)(n * Cin + i / LT) * L + l0 + (i % LT)];
    __syncthreads();
    int l = l0 + threadIdx.x;
    for (int o0 = 0; o0 < Cout; o0 += OT) {
        for (int i = tid; i < OT * Cin; i += nt)
            Ws[i] = W[(size_t)o0 * Cin + i];
        __syncthreads();
        int o = o0 + threadIdx.y;
        float acc = bias[o];
        const float* wr = Ws + threadIdx.y * Cin;
        #pragma unroll 8
        for (int c = 0; c < Cin; c++) acc += wr[c] * Xs[c * LT + threadIdx.x];
        if (res) acc += res[(size_t)(n * Cout + o) * L + l];
        out[(size_t)(n * Cout + o) * L + l] = acc;
        __syncthreads();
    }
}

// ---------------------------------------------------------------------------
// Attention pass 1: L=1024, ch=64. Block = (bh, 16-query tile), 256 threads.
// smem: qs[64][16] + S[16][1028 (pad)] + Vs[64][128]  = 102656 B
// ---------------------------------------------------------------------------
#define SP 1028
#define ATTN1_SMEM ((1024 + 16 * SP + 64 * 128) * 4)

__global__ void k_attn1(const float* __restrict__ qkv, float* __restrict__ out) {
    extern __shared__ float sm[];
    float* qs = sm;                   // 64*16
    float* S  = sm + 1024;            // 16*SP
    float* Vs = sm + 1024 + 16 * SP;  // 64*128
    int bh = blockIdx.y;              // 0..95
    int n = bh / 3, h = bh % 3;
    int q0 = blockIdx.x * 16;
    const float* Q = qkv + (size_t)(n * 576 + h * 192) * 1024;
    const float* K = Q + 64 * 1024;
    const float* V = Q + 128 * 1024;
    int tid = threadIdx.x;

    // load scaled Q tile: qs[c][q]
    for (int i = tid; i < 1024; i += 256) {
        int c = i >> 4, q = i & 15;
        qs[i] = Q[c * 1024 + q0 + q] * 0.125f;  // ch^-0.5 folded onto q
    }
    __syncthreads();

    // scores: S[q][s] for all 1024 keys
    for (int j = 0; j < 4; j++) {
        int s = tid + j * 256;
        float acc[16];
        #pragma unroll
        for (int q = 0; q < 16; q++) acc[q] = 0.f;
        for (int c = 0; c < 64; c++) {
            float kv = K[c * 1024 + s];
            #pragma unroll
            for (int q = 0; q < 16; q++) acc[q] += qs[c * 16 + q] * kv;
        }
        #pragma unroll
        for (int q = 0; q < 16; q++) S[q * SP + s] = acc[q];
    }
    __syncthreads();

    // softmax per row (warp per 2 rows)
    int w = tid >> 5, lane = tid & 31;
    for (int r = w; r < 16; r += 8) {
        float* row = S + r * SP;
        float m = -1e30f;
        for (int s = lane; s < 1024; s += 32) m = fmaxf(m, row[s]);
        #pragma unroll
        for (int off = 16; off; off >>= 1) m = fmaxf(m, __shfl_xor_sync(0xffffffffu, m, off));
        float sum = 0.f;
        for (int s = lane; s < 1024; s += 32) { float e = expf(row[s] - m); row[s] = e; sum += e; }
        #pragma unroll
        for (int off = 16; off; off >>= 1) sum += __shfl_xor_sync(0xffffffffu, sum, off);
        float inv = 1.f / sum;
        for (int s = lane; s < 1024; s += 32) row[s] *= inv;
    }
    __syncthreads();

    // output: O[c][q] = sum_s V[c][s] * S[q][s], V staged through smem in 128-key tiles
    int q  = tid & 15;
    int cb = (tid >> 4) << 2;
    float a0 = 0.f, a1 = 0.f, a2 = 0.f, a3 = 0.f;
    for (int s0 = 0; s0 < 1024; s0 += 128) {
        for (int i = tid; i < 64 * 128; i += 256)
            Vs[i] = V[(i >> 7) * 1024 + s0 + (i & 127)];
        __syncthreads();
        const float4* S4 = (const float4*)(S + q * SP + s0);
        const float4* V4 = (const float4*)Vs;
        #pragma unroll 4
        for (int s4 = 0; s4 < 32; s4++) {
            float4 sv = S4[s4];
            float4 v0 = V4[(cb + 0) * 32 + s4];
            float4 v1 = V4[(cb + 1) * 32 + s4];
            float4 v2 = V4[(cb + 2) * 32 + s4];
            float4 v3 = V4[(cb + 3) * 32 + s4];
            a0 += sv.x * v0.x + sv.y * v0.y + sv.z * v0.z + sv.w * v0.w;
            a1 += sv.x * v1.x + sv.y * v1.y + sv.z * v1.z + sv.w * v1.w;
            a2 += sv.x * v2.x + sv.y * v2.y + sv.z * v2.z + sv.w * v2.w;
            a3 += sv.x * v3.x + sv.y * v3.y + sv.z * v3.z + sv.w * v3.w;
        }
        __syncthreads();
    }
    size_t ob = (size_t)(n * 192 + h * 64 + cb) * 1024 + q0 + q;
    out[ob + 0 * 1024] = a0;
    out[ob + 1 * 1024] = a1;
    out[ob + 2 * 1024] = a2;
    out[ob + 3 * 1024] = a3;
}

// ---------------------------------------------------------------------------
// Attention pass 2: L=16, ch=64. One block per bh (6144 blocks), 256 threads.
// ---------------------------------------------------------------------------
__global__ void k_attn2(const float* __restrict__ qkv, float* __restrict__ out) {
    __shared__ float qs[1024], ks[1024], vs[1024], S[16 * 17];
    int bh = blockIdx.x;
    int n = bh / 3, h = bh % 3;
    const float* B = qkv + (size_t)(n * 576 + h * 192) * 16;
    int tid = threadIdx.x;
    for (int i = tid; i < 1024; i += 256) {
        qs[i] = B[i] * 0.125f;
        ks[i] = B[1024 + i];
        vs[i] = B[2048 + i];
    }
    __syncthreads();
    {
        int q = tid >> 4, s = tid & 15;
        float a = 0.f;
        #pragma unroll
        for (int c = 0; c < 64; c++) a += qs[c * 16 + q] * ks[c * 16 + s];
        S[q * 17 + s] = a;
    }
    __syncthreads();
    if (tid < 16) {
        float* row = S + tid * 17;
        float m = -1e30f;
        #pragma unroll
        for (int s = 0; s < 16; s++) m = fmaxf(m, row[s]);
        float sum = 0.f;
        #pragma unroll
        for (int s = 0; s < 16; s++) { float e = expf(row[s] - m); row[s] = e; sum += e; }
        float inv = 1.f / sum;
        #pragma unroll
        for (int s = 0; s < 16; s++) row[s] *= inv;
    }
    __syncthreads();
    {
        int q  = tid & 15;
        int cb = (tid >> 4) << 2;
        float a0 = 0.f, a1 = 0.f, a2 = 0.f, a3 = 0.f;
        #pragma unroll
        for (int s = 0; s < 16; s++) {
            float sv = S[q * 17 + s];
            a0 += vs[(cb + 0) * 16 + s] * sv;
            a1 += vs[(cb + 1) * 16 + s] * sv;
            a2 += vs[(cb + 2) * 16 + s] * sv;
            a3 += vs[(cb + 3) * 16 + s] * sv;
        }
        size_t ob = (size_t)(n * 192 + h * 64 + cb) * 16 + q;
        out[ob + 0 * 16] = a0;
        out[ob + 1 * 16] = a1;
        out[ob + 2 * 16] = a2;
        out[ob + 3 * 16] = a3;
    }
}

// ---------------------------------------------------------------------------
extern "C" void kernel_launch(void* const* d_in, const int* in_sizes, int n_in,
                              void* d_out, int out_size) {
    const float* x       = (const float*)d_in[0];
    const float* norm_g  = (const float*)d_in[1];
    const float* norm_b  = (const float*)d_in[2];
    const float* qkv_w   = (const float*)d_in[3];
    const float* qkv_b   = (const float*)d_in[4];
    const float* proj_w  = (const float*)d_in[5];
    const float* proj_b  = (const float*)d_in[6];
    const float* normt_g = (const float*)d_in[7];
    const float* normt_b = (const float*)d_in[8];
    const float* qkvt_w  = (const float*)d_in[9];
    const float* qkvt_b  = (const float*)d_in[10];
    const float* projt_w = (const float*)d_in[11];
    const float* projt_b = (const float*)d_in[12];
    float* out = (float*)d_out;

    float *xs, *nrm, *qkv, *att, *y, *yt;
    cudaGetSymbolAddress((void**)&xs,  g_xs);
    cudaGetSymbolAddress((void**)&nrm, g_nrm);
    cudaGetSymbolAddress((void**)&qkv, g_qkv);
    cudaGetSymbolAddress((void**)&att, g_att);
    cudaGetSymbolAddress((void**)&y,   g_y);
    cudaGetSymbolAddress((void**)&yt,  g_yt);

    cudaFuncSetAttribute(k_attn1, cudaFuncAttributeMaxDynamicSharedMemorySize, ATTN1_SMEM);

    int nb = (TOT + 255) / 256;

    // ---- pass 1 (spatial, L=1024) ----
    k_transpose1<<<nb, 256>>>(x);
    k_groupnorm<<<NBT * 32, 128>>>(xs, norm_g, norm_b, nrm, 1024);
    {
        dim3 blk(32, 8);
        size_t smem = (192 * 32 + 8 * 192) * sizeof(float);
        k_conv1x1<<<dim3(32, NBT), blk, smem>>>(nrm, qkv_w, qkv_b, nullptr, qkv, 192, 576, 1024);
    }
    k_attn1<<<dim3(64, 96), 256, ATTN1_SMEM>>>(qkv, att);
    {
        dim3 blk(32, 8);
        size_t smem = (192 * 32 + 8 * 192) * sizeof(float);
        k_conv1x1<<<dim3(32, NBT), blk, smem>>>(att, proj_w, proj_b, xs, y, 192, 192, 1024);
    }
    // ---- pass 2 (temporal, L=16) ----
    k_transpose2<<<nb, 256>>>();
    k_groupnorm<<<NBHW * 32, 128>>>(yt, normt_g, normt_b, nrm, 16);
    {
        dim3 blk(16, 16);
        size_t smem = (192 * 16 + 16 * 192) * sizeof(float);
        k_conv1x1<<<dim3(1, NBHW), blk, smem>>>(nrm, qkvt_w, qkvt_b, nullptr, qkv, 192, 576, 16);
    }
    k_attn2<<<NBHW * 3, 256>>>(qkv, att);
    {
        dim3 blk(16, 16);
        size_t smem = (192 * 16 + 16 * 192) * sizeof(float);
        k_conv1x1<<<dim3(1, NBHW), blk, smem>>>(att, projt_w, projt_b, yt, xs, 192, 192, 16);
    }
    k_transpose3<<<nb, 256>>>(out);
}

// round 3
// speedup vs baseline: 2.8386x; 2.8386x over previous
#include <cuda_runtime.h>
#include <math.h>

// Shapes
#define NBT   32
#define CCH   192
#define LHW   1024
#define NTT   16
#define NBHW  2048
#define TOT   (NBT*CCH*LHW)

typedef unsigned long long ull;

// Scratch
__device__ float g_xs [TOT];
__device__ float g_nrm[TOT];
__device__ float g_qkv[NBT*3*CCH*LHW];
__device__ float g_att[TOT];
__device__ float g_y  [TOT];
__device__ float g_yt [TOT];

// ---- packed f32x2 helpers ------------------------------------------------
__device__ __forceinline__ void ffma2(ull &d, ull a, ull b) {
    asm("fma.rn.f32x2 %0, %1, %2, %0;" : "+l"(d) : "l"(a), "l"(b));
}
__device__ __forceinline__ ull dup2(float x) {
    ull r; asm("mov.b64 %0, {%1, %1};" : "=l"(r) : "f"(x)); return r;
}
__device__ __forceinline__ float2 unpk(ull p) {
    float2 r; asm("mov.b64 {%0, %1}, %2;" : "=f"(r.x), "=f"(r.y) : "l"(p)); return r;
}
__device__ __forceinline__ float hadd2(ull p) { float2 r = unpk(p); return r.x + r.y; }

// ---------------------------------------------------------------------------
// Transposes
// ---------------------------------------------------------------------------
__global__ void k_transpose1(const float* __restrict__ x) {
    int o = blockIdx.x * 256 + threadIdx.x;
    if (o >= TOT) return;
    int hw = o & 1023;
    int c  = (o >> 10) % CCH;
    int bt = o / (CCH * LHW);
    int b = bt >> 4, t = bt & 15;
    g_xs[o] = x[((b * CCH + c) * 16 + t) * 1024 + hw];
}

__global__ void k_transpose2() {
    int o = blockIdx.x * 256 + threadIdx.x;
    if (o >= TOT) return;
    int t   = o & 15;
    int c   = (o >> 4) % CCH;
    int bhw = o / (CCH * NTT);
    int b = bhw >> 10, hw = bhw & 1023;
    g_yt[o] = g_y[((b * 16 + t) * CCH + c) * 1024 + hw];
}

__global__ void k_transpose3(float* __restrict__ out) {
    int o = blockIdx.x * 256 + threadIdx.x;
    if (o >= TOT) return;
    int hw = o & 1023;
    int t  = (o >> 10) & 15;
    int c  = (o >> 14) % CCH;
    int b  = o / (CCH * NTT * LHW);
    out[o] = g_xs[((b * 1024 + hw) * CCH + c) * 16 + t];
}

// ---------------------------------------------------------------------------
// GroupNorm
// ---------------------------------------------------------------------------
__global__ void k_groupnorm(const float* __restrict__ X, const float* __restrict__ gam,
                            const float* __restrict__ bet, float* __restrict__ out, int L) {
    int n = blockIdx.x >> 5;
    int g = blockIdx.x & 31;
    int len = 6 * L;
    const float* base = X + (size_t)(n * CCH + g * 6) * L;
    float* ob = out + (size_t)(n * CCH + g * 6) * L;
    float s = 0.f, q = 0.f;
    for (int i = threadIdx.x; i < len; i += 128) { float v = base[i]; s += v; q += v * v; }
    __shared__ float rs[128], rq[128];
    rs[threadIdx.x] = s; rq[threadIdx.x] = q;
    __syncthreads();
    for (int st = 64; st > 0; st >>= 1) {
        if (threadIdx.x < st) { rs[threadIdx.x] += rs[threadIdx.x + st]; rq[threadIdx.x] += rq[threadIdx.x + st]; }
        __syncthreads();
    }
    float mean = rs[0] / len;
    float var  = rq[0] / len - mean * mean;
    float inv  = rsqrtf(var + 1e-5f);
    for (int i = threadIdx.x; i < len; i += 128) {
        int c = g * 6 + i / L;
        ob[i] = (base[i] - mean) * inv * gam[c] + bet[c];
    }
}

// ---------------------------------------------------------------------------
// Unified 1x1 conv as tiled GEMM, f32x2 packed over o-pairs.
// Column space: g in [0, N*L) flattened, n = g>>ls, l = g&(L-1). 128 cols/block.
// Block tile: 64 o x 128 cols. Thread: 8 o x 4 cols. KC=16 Cin chunk.
// ---------------------------------------------------------------------------
__global__ __launch_bounds__(256) void k_conv(
    const float* __restrict__ X, const float* __restrict__ W,
    const float* __restrict__ bias, const float* __restrict__ res,
    float* __restrict__ out, int Cin, int Cout, int ls) {
    __shared__ float Xs[16][128];
    __shared__ float Ws[16][64];
    const int L = 1 << ls, Lm1 = L - 1;
    const int tid = threadIdx.x;
    const int og = tid >> 5;        // 0..7 (8 o each)
    const int lg = tid & 31;        // 0..31 (4 cols each)
    const int g0 = blockIdx.x * 128;
    const int o0 = blockIdx.y * 64;

    ull acc[4][4];
    #pragma unroll
    for (int p = 0; p < 4; p++)
        #pragma unroll
        for (int j = 0; j < 4; j++) acc[p][j] = 0ull;

    const int xk  = tid >> 5;         // X load: k row
    const int xc4 = (tid & 31) * 4;   // X load: col*4
    const int wo  = tid & 63;         // W load: o
    const int wk4 = (tid >> 6) * 4;   // W load: k base

    for (int cc = 0; cc < Cin; cc += 16) {
        // stage X chunk
        #pragma unroll
        for (int r = 0; r < 2; r++) {
            int k = xk + r * 8;
            int g = g0 + xc4;
            const float* src = X + ((size_t)(g >> ls) * Cin + cc + k) * L + (g & Lm1);
            *(float4*)&Xs[k][xc4] = *(const float4*)src;
        }
        // stage W chunk transposed to [k][o]
        {
            float4 wv = *(const float4*)(W + (size_t)(o0 + wo) * Cin + cc + wk4);
            Ws[wk4 + 0][wo] = wv.x;
            Ws[wk4 + 1][wo] = wv.y;
            Ws[wk4 + 2][wo] = wv.z;
            Ws[wk4 + 3][wo] = wv.w;
        }
        __syncthreads();
        #pragma unroll
        for (int k = 0; k < 16; k++) {
            ulonglong2 w01 = *(const ulonglong2*)&Ws[k][og * 8];
            ulonglong2 w23 = *(const ulonglong2*)&Ws[k][og * 8 + 4];
            float4 xv = *(const float4*)&Xs[k][lg * 4];
            ull x0 = dup2(xv.x), x1 = dup2(xv.y), x2 = dup2(xv.z), x3 = dup2(xv.w);
            ffma2(acc[0][0], w01.x, x0); ffma2(acc[0][1], w01.x, x1);
            ffma2(acc[0][2], w01.x, x2); ffma2(acc[0][3], w01.x, x3);
            ffma2(acc[1][0], w01.y, x0); ffma2(acc[1][1], w01.y, x1);
            ffma2(acc[1][2], w01.y, x2); ffma2(acc[1][3], w01.y, x3);
            ffma2(acc[2][0], w23.x, x0); ffma2(acc[2][1], w23.x, x1);
            ffma2(acc[2][2], w23.x, x2); ffma2(acc[2][3], w23.x, x3);
            ffma2(acc[3][0], w23.y, x0); ffma2(acc[3][1], w23.y, x1);
            ffma2(acc[3][2], w23.y, x2); ffma2(acc[3][3], w23.y, x3);
        }
        __syncthreads();
    }

    // epilogue
    const int gl = g0 + lg * 4;
    const int n = gl >> ls, l = gl & Lm1;
    #pragma unroll
    for (int p = 0; p < 4; p++) {
        float2 u0 = unpk(acc[p][0]), u1 = unpk(acc[p][1]);
        float2 u2 = unpk(acc[p][2]), u3 = unpk(acc[p][3]);
        int oe = o0 + og * 8 + 2 * p;
        float be = bias[oe], bo = bias[oe + 1];
        float4 re = make_float4(u0.x + be, u1.x + be, u2.x + be, u3.x + be);
        float4 ro = make_float4(u0.y + bo, u1.y + bo, u2.y + bo, u3.y + bo);
        size_t ae = ((size_t)n * Cout + oe) * L + l;
        size_t ao = ae + L;
        if (res) {
            float4 qe = *(const float4*)(res + ae);
            float4 qo = *(const float4*)(res + ao);
            re.x += qe.x; re.y += qe.y; re.z += qe.z; re.w += qe.w;
            ro.x += qo.x; ro.y += qo.y; ro.z += qo.z; ro.w += qo.w;
        }
        *(float4*)(out + ae) = re;
        *(float4*)(out + ao) = ro;
    }
}

// ---------------------------------------------------------------------------
// Attention pass 1: L=1024, ch=64. Block = (bh, 16-query tile), 256 threads.
// ---------------------------------------------------------------------------
#define SP 1028
#define ATTN1_SMEM ((1024 + 16 * SP + 64 * 128) * 4)

__global__ __launch_bounds__(256, 2) void k_attn1(const float* __restrict__ qkv,
                                                  float* __restrict__ out) {
    extern __shared__ float sm[];
    float* qs = sm;                   // [64][16]
    float* S  = sm + 1024;            // [16][SP]
    float* Vs = sm + 1024 + 16 * SP;  // [64][128]
    int bh = blockIdx.y;
    int n = bh / 3, h = bh % 3;
    int q0 = blockIdx.x * 16;
    const float* Q = qkv + (size_t)(n * 576 + h * 192) * 1024;
    const float* K = Q + 64 * 1024;
    const float* V = Q + 128 * 1024;
    int tid = threadIdx.x;

    // load scaled Q tile: qs[c][q]
    for (int i = tid; i < 1024; i += 256) {
        int c = i >> 4, q = i & 15;
        qs[i] = Q[c * 1024 + q0 + q] * 0.125f;
    }
    __syncthreads();

    // ---- QK^T: thread = 4 consecutive s, all 16 q; q-pair packed ----
    {
        const int s4 = tid * 4;
        ull acc[8][4];
        #pragma unroll
        for (int p = 0; p < 8; p++)
            #pragma unroll
            for (int j = 0; j < 4; j++) acc[p][j] = 0ull;

        float4 k4 = *(const float4*)(K + s4);   // c = 0
        #pragma unroll 4
        for (int c = 0; c < 64; c++) {
            float4 kn;
            if (c < 63) kn = *(const float4*)(K + (c + 1) * 1024 + s4);
            ulonglong2 qa = *(const ulonglong2*)&qs[c * 16];
            ulonglong2 qb = *(const ulonglong2*)&qs[c * 16 + 4];
            ulonglong2 qc = *(const ulonglong2*)&qs[c * 16 + 8];
            ulonglong2 qd = *(const ulonglong2*)&qs[c * 16 + 12];
            ull k0 = dup2(k4.x), k1 = dup2(k4.y), k2 = dup2(k4.z), k3 = dup2(k4.w);
            ffma2(acc[0][0], qa.x, k0); ffma2(acc[0][1], qa.x, k1);
            ffma2(acc[0][2], qa.x, k2); ffma2(acc[0][3], qa.x, k3);
            ffma2(acc[1][0], qa.y, k0); ffma2(acc[1][1], qa.y, k1);
            ffma2(acc[1][2], qa.y, k2); ffma2(acc[1][3], qa.y, k3);
            ffma2(acc[2][0], qb.x, k0); ffma2(acc[2][1], qb.x, k1);
            ffma2(acc[2][2], qb.x, k2); ffma2(acc[2][3], qb.x, k3);
            ffma2(acc[3][0], qb.y, k0); ffma2(acc[3][1], qb.y, k1);
            ffma2(acc[3][2], qb.y, k2); ffma2(acc[3][3], qb.y, k3);
            ffma2(acc[4][0], qc.x, k0); ffma2(acc[4][1], qc.x, k1);
            ffma2(acc[4][2], qc.x, k2); ffma2(acc[4][3], qc.x, k3);
            ffma2(acc[5][0], qc.y, k0); ffma2(acc[5][1], qc.y, k1);
            ffma2(acc[5][2], qc.y, k2); ffma2(acc[5][3], qc.y, k3);
            ffma2(acc[6][0], qd.x, k0); ffma2(acc[6][1], qd.x, k1);
            ffma2(acc[6][2], qd.x, k2); ffma2(acc[6][3], qd.x, k3);
            ffma2(acc[7][0], qd.y, k0); ffma2(acc[7][1], qd.y, k1);
            ffma2(acc[7][2], qd.y, k2); ffma2(acc[7][3], qd.y, k3);
            k4 = kn;
        }
        // write S rows
        #pragma unroll
        for (int p = 0; p < 8; p++) {
            float2 u0 = unpk(acc[p][0]), u1 = unpk(acc[p][1]);
            float2 u2 = unpk(acc[p][2]), u3 = unpk(acc[p][3]);
            *(float4*)&S[(2 * p)     * SP + s4] = make_float4(u0.x, u1.x, u2.x, u3.x);
            *(float4*)&S[(2 * p + 1) * SP + s4] = make_float4(u0.y, u1.y, u2.y, u3.y);
        }
    }
    __syncthreads();

    // softmax per row
    {
        int w = tid >> 5, lane = tid & 31;
        for (int r = w; r < 16; r += 8) {
            float* row = S + r * SP;
            float m = -1e30f;
            for (int s = lane; s < 1024; s += 32) m = fmaxf(m, row[s]);
            #pragma unroll
            for (int off = 16; off; off >>= 1) m = fmaxf(m, __shfl_xor_sync(0xffffffffu, m, off));
            float sum = 0.f;
            for (int s = lane; s < 1024; s += 32) { float e = __expf(row[s] - m); row[s] = e; sum += e; }
            #pragma unroll
            for (int off = 16; off; off >>= 1) sum += __shfl_xor_sync(0xffffffffu, sum, off);
            float inv = 1.f / sum;
            for (int s = lane; s < 1024; s += 32) row[s] *= inv;
        }
    }
    __syncthreads();

    // ---- AV: thread = 4 c x 1 q; s-pair packed (no dup needed) ----
    {
        int q  = tid & 15;
        int cb = (tid >> 4) << 2;
        ull acc2[4] = {0ull, 0ull, 0ull, 0ull};
        for (int s0 = 0; s0 < 1024; s0 += 128) {
            #pragma unroll
            for (int r = 0; r < 8; r++) {
                int i = tid + r * 256;           // float4 index over 64x128/4
                int c = i >> 5, sl = (i & 31) * 4;
                *(float4*)&Vs[c * 128 + sl] = *(const float4*)(V + c * 1024 + s0 + sl);
            }
            __syncthreads();
            const float* Srow = S + q * SP + s0;
            #pragma unroll 8
            for (int s4 = 0; s4 < 128; s4 += 4) {
                ulonglong2 sv = *(const ulonglong2*)(Srow + s4);
                #pragma unroll
                for (int j = 0; j < 4; j++) {
                    ulonglong2 vv = *(const ulonglong2*)&Vs[(cb + j) * 128 + s4];
                    ffma2(acc2[j], vv.x, sv.x);
                    ffma2(acc2[j], vv.y, sv.y);
                }
            }
            __syncthreads();
        }
        size_t ob = (size_t)(n * 192 + h * 64 + cb) * 1024 + q0 + q;
        out[ob + 0 * 1024] = hadd2(acc2[0]);
        out[ob + 1 * 1024] = hadd2(acc2[1]);
        out[ob + 2 * 1024] = hadd2(acc2[2]);
        out[ob + 3 * 1024] = hadd2(acc2[3]);
    }
}

// ---------------------------------------------------------------------------
// Attention pass 2: L=16
// ---------------------------------------------------------------------------
__global__ void k_attn2(const float* __restrict__ qkv, float* __restrict__ out) {
    __shared__ float qs[1024], ks[1024], vs[1024], S[16 * 17];
    int bh = blockIdx.x;
    int n = bh / 3, h = bh % 3;
    const float* B = qkv + (size_t)(n * 576 + h * 192) * 16;
    int tid = threadIdx.x;
    for (int i = tid; i < 1024; i += 256) {
        qs[i] = B[i] * 0.125f;
        ks[i] = B[1024 + i];
        vs[i] = B[2048 + i];
    }
    __syncthreads();
    {
        int q = tid >> 4, s = tid & 15;
        float a = 0.f;
        #pragma unroll
        for (int c = 0; c < 64; c++) a += qs[c * 16 + q] * ks[c * 16 + s];
        S[q * 17 + s] = a;
    }
    __syncthreads();
    if (tid < 16) {
        float* row = S + tid * 17;
        float m = -1e30f;
        #pragma unroll
        for (int s = 0; s < 16; s++) m = fmaxf(m, row[s]);
        float sum = 0.f;
        #pragma unroll
        for (int s = 0; s < 16; s++) { float e = __expf(row[s] - m); row[s] = e; sum += e; }
        float inv = 1.f / sum;
        #pragma unroll
        for (int s = 0; s < 16; s++) row[s] *= inv;
    }
    __syncthreads();
    {
        int q  = tid & 15;
        int cb = (tid >> 4) << 2;
        float a0 = 0.f, a1 = 0.f, a2 = 0.f, a3 = 0.f;
        #pragma unroll
        for (int s = 0; s < 16; s++) {
            float sv = S[q * 17 + s];
            a0 += vs[(cb + 0) * 16 + s] * sv;
            a1 += vs[(cb + 1) * 16 + s] * sv;
            a2 += vs[(cb + 2) * 16 + s] * sv;
            a3 += vs[(cb + 3) * 16 + s] * sv;
        }
        size_t ob = (size_t)(n * 192 + h * 64 + cb) * 16 + q;
        out[ob + 0 * 16] = a0;
        out[ob + 1 * 16] = a1;
        out[ob + 2 * 16] = a2;
        out[ob + 3 * 16] = a3;
    }
}

// ---------------------------------------------------------------------------
extern "C" void kernel_launch(void* const* d_in, const int* in_sizes, int n_in,
                              void* d_out, int out_size) {
    const float* x       = (const float*)d_in[0];
    const float* norm_g  = (const float*)d_in[1];
    const float* norm_b  = (const float*)d_in[2];
    const float* qkv_w   = (const float*)d_in[3];
    const float* qkv_b   = (const float*)d_in[4];
    const float* proj_w  = (const float*)d_in[5];
    const float* proj_b  = (const float*)d_in[6];
    const float* normt_g = (const float*)d_in[7];
    const float* normt_b = (const float*)d_in[8];
    const float* qkvt_w  = (const float*)d_in[9];
    const float* qkvt_b  = (const float*)d_in[10];
    const float* projt_w = (const float*)d_in[11];
    const float* projt_b = (const float*)d_in[12];
    float* out = (float*)d_out;

    float *xs, *nrm, *qkv, *att, *y, *yt;
    cudaGetSymbolAddress((void**)&xs,  g_xs);
    cudaGetSymbolAddress((void**)&nrm, g_nrm);
    cudaGetSymbolAddress((void**)&qkv, g_qkv);
    cudaGetSymbolAddress((void**)&att, g_att);
    cudaGetSymbolAddress((void**)&y,   g_y);
    cudaGetSymbolAddress((void**)&yt,  g_yt);

    cudaFuncSetAttribute(k_attn1, cudaFuncAttributeMaxDynamicSharedMemorySize, ATTN1_SMEM);

    int nb = (TOT + 255) / 256;

    // ---- pass 1 (spatial, L=1024) ----
    k_transpose1<<<nb, 256>>>(x);
    k_groupnorm<<<NBT * 32, 128>>>(xs, norm_g, norm_b, nrm, 1024);
    k_conv<<<dim3(256, 9), 256>>>(nrm, qkv_w, qkv_b, nullptr, qkv, 192, 576, 10);
    k_attn1<<<dim3(64, 96), 256, ATTN1_SMEM>>>(qkv, att);
    k_conv<<<dim3(256, 3), 256>>>(att, proj_w, proj_b, xs, y, 192, 192, 10);

    // ---- pass 2 (temporal, L=16) ----
    k_transpose2<<<nb, 256>>>();
    k_groupnorm<<<NBHW * 32, 128>>>(yt, normt_g, normt_b, nrm, 16);
    k_conv<<<dim3(256, 9), 256>>>(nrm, qkvt_w, qkvt_b, nullptr, qkv, 192, 576, 4);
    k_attn2<<<NBHW * 3, 256>>>(qkv, att);
    k_conv<<<dim3(256, 3), 256>>>(att, projt_w, projt_b, yt, xs, 192, 192, 4);

    k_transpose3<<<nb, 256>>>(out);
}

// round 4
// speedup vs baseline: 4.9522x; 1.7446x over previous
#include <cuda_runtime.h>
#include <math.h>

// Shapes
#define NBT   32
#define CCH   192
#define LHW   1024
#define NTT   16
#define NBHW  2048
#define TOT   (NBT*CCH*LHW)

typedef unsigned long long ull;
typedef unsigned int uint32;

// Scratch
__device__ float g_xs [TOT];
__device__ float g_nrm[TOT];
__device__ float g_qkv[NBT*3*CCH*LHW];
__device__ float g_att[TOT];
__device__ float g_y  [TOT];
__device__ float g_yt [TOT];

// ---- packed f32x2 helpers ------------------------------------------------
__device__ __forceinline__ void ffma2(ull &d, ull a, ull b) {
    asm("fma.rn.f32x2 %0, %1, %2, %0;" : "+l"(d) : "l"(a), "l"(b));
}
__device__ __forceinline__ ull dup2(float x) {
    ull r; asm("mov.b64 %0, {%1, %1};" : "=l"(r) : "f"(x)); return r;
}
__device__ __forceinline__ float2 unpk(ull p) {
    float2 r; asm("mov.b64 {%0, %1}, %2;" : "=f"(r.x), "=f"(r.y) : "l"(p)); return r;
}
__device__ __forceinline__ float hadd2(ull p) { float2 r = unpk(p); return r.x + r.y; }

// ---- tf32 helpers ---------------------------------------------------------
__device__ __forceinline__ float tf32r(float x) {
    uint32 u; asm("cvt.rna.tf32.f32 %0, %1;" : "=r"(u) : "f"(x));
    return __uint_as_float(u);
}
__device__ __forceinline__ void mma8(float4 &c, const uint32* a, uint32 b0, uint32 b1) {
    asm("mma.sync.aligned.m16n8k8.row.col.f32.tf32.tf32.f32 "
        "{%0,%1,%2,%3},{%4,%5,%6,%7},{%8,%9},{%0,%1,%2,%3};"
        : "+f"(c.x), "+f"(c.y), "+f"(c.z), "+f"(c.w)
        : "r"(a[0]), "r"(a[1]), "r"(a[2]), "r"(a[3]), "r"(b0), "r"(b1));
}

// ---------------------------------------------------------------------------
// Transposes
// ---------------------------------------------------------------------------
__global__ void k_transpose1(const float* __restrict__ x) {
    int o = blockIdx.x * 256 + threadIdx.x;
    if (o >= TOT) return;
    int hw = o & 1023;
    int c  = (o >> 10) % CCH;
    int bt = o / (CCH * LHW);
    int b = bt >> 4, t = bt & 15;
    g_xs[o] = x[((b * CCH + c) * 16 + t) * 1024 + hw];
}

__global__ void k_transpose2() {
    int o = blockIdx.x * 256 + threadIdx.x;
    if (o >= TOT) return;
    int t   = o & 15;
    int c   = (o >> 4) % CCH;
    int bhw = o / (CCH * NTT);
    int b = bhw >> 10, hw = bhw & 1023;
    g_yt[o] = g_y[((b * 16 + t) * CCH + c) * 1024 + hw];
}

__global__ void k_transpose3(float* __restrict__ out) {
    int o = blockIdx.x * 256 + threadIdx.x;
    if (o >= TOT) return;
    int hw = o & 1023;
    int t  = (o >> 10) & 15;
    int c  = (o >> 14) % CCH;
    int b  = o / (CCH * NTT * LHW);
    out[o] = g_xs[((b * 1024 + hw) * CCH + c) * 16 + t];
}

// ---------------------------------------------------------------------------
// GroupNorm
// ---------------------------------------------------------------------------
__global__ void k_groupnorm(const float* __restrict__ X, const float* __restrict__ gam,
                            const float* __restrict__ bet, float* __restrict__ out, int L) {
    int n = blockIdx.x >> 5;
    int g = blockIdx.x & 31;
    int len = 6 * L;
    const float* base = X + (size_t)(n * CCH + g * 6) * L;
    float* ob = out + (size_t)(n * CCH + g * 6) * L;
    float s = 0.f, q = 0.f;
    for (int i = threadIdx.x; i < len; i += 128) { float v = base[i]; s += v; q += v * v; }
    __shared__ float rs[128], rq[128];
    rs[threadIdx.x] = s; rq[threadIdx.x] = q;
    __syncthreads();
    for (int st = 64; st > 0; st >>= 1) {
        if (threadIdx.x < st) { rs[threadIdx.x] += rs[threadIdx.x + st]; rq[threadIdx.x] += rq[threadIdx.x + st]; }
        __syncthreads();
    }
    float mean = rs[0] / len;
    float var  = rq[0] / len - mean * mean;
    float inv  = rsqrtf(var + 1e-5f);
    for (int i = threadIdx.x; i < len; i += 128) {
        int c = g * 6 + i / L;
        ob[i] = (base[i] - mean) * inv * gam[c] + bet[c];
    }
}

// ---------------------------------------------------------------------------
// Unified 1x1 conv as tiled GEMM, f32x2 packed over o-pairs.
// ---------------------------------------------------------------------------
__global__ __launch_bounds__(256) void k_conv(
    const float* __restrict__ X, const float* __restrict__ W,
    const float* __restrict__ bias, const float* __restrict__ res,
    float* __restrict__ out, int Cin, int Cout, int ls) {
    __shared__ float Xs[16][128];
    __shared__ float Ws[16][64];
    const int L = 1 << ls, Lm1 = L - 1;
    const int tid = threadIdx.x;
    const int og = tid >> 5;
    const int lg = tid & 31;
    const int g0 = blockIdx.x * 128;
    const int o0 = blockIdx.y * 64;

    ull acc[4][4];
    #pragma unroll
    for (int p = 0; p < 4; p++)
        #pragma unroll
        for (int j = 0; j < 4; j++) acc[p][j] = 0ull;

    const int xk  = tid >> 5;
    const int xc4 = (tid & 31) * 4;
    const int wo  = tid & 63;
    const int wk4 = (tid >> 6) * 4;

    for (int cc = 0; cc < Cin; cc += 16) {
        #pragma unroll
        for (int r = 0; r < 2; r++) {
            int k = xk + r * 8;
            int g = g0 + xc4;
            const float* src = X + ((size_t)(g >> ls) * Cin + cc + k) * L + (g & Lm1);
            *(float4*)&Xs[k][xc4] = *(const float4*)src;
        }
        {
            float4 wv = *(const float4*)(W + (size_t)(o0 + wo) * Cin + cc + wk4);
            Ws[wk4 + 0][wo] = wv.x;
            Ws[wk4 + 1][wo] = wv.y;
            Ws[wk4 + 2][wo] = wv.z;
            Ws[wk4 + 3][wo] = wv.w;
        }
        __syncthreads();
        #pragma unroll
        for (int k = 0; k < 16; k++) {
            ulonglong2 w01 = *(const ulonglong2*)&Ws[k][og * 8];
            ulonglong2 w23 = *(const ulonglong2*)&Ws[k][og * 8 + 4];
            float4 xv = *(const float4*)&Xs[k][lg * 4];
            ull x0 = dup2(xv.x), x1 = dup2(xv.y), x2 = dup2(xv.z), x3 = dup2(xv.w);
            ffma2(acc[0][0], w01.x, x0); ffma2(acc[0][1], w01.x, x1);
            ffma2(acc[0][2], w01.x, x2); ffma2(acc[0][3], w01.x, x3);
            ffma2(acc[1][0], w01.y, x0); ffma2(acc[1][1], w01.y, x1);
            ffma2(acc[1][2], w01.y, x2); ffma2(acc[1][3], w01.y, x3);
            ffma2(acc[2][0], w23.x, x0); ffma2(acc[2][1], w23.x, x1);
            ffma2(acc[2][2], w23.x, x2); ffma2(acc[2][3], w23.x, x3);
            ffma2(acc[3][0], w23.y, x0); ffma2(acc[3][1], w23.y, x1);
            ffma2(acc[3][2], w23.y, x2); ffma2(acc[3][3], w23.y, x3);
        }
        __syncthreads();
    }

    const int gl = g0 + lg * 4;
    const int n = gl >> ls, l = gl & Lm1;
    #pragma unroll
    for (int p = 0; p < 4; p++) {
        float2 u0 = unpk(acc[p][0]), u1 = unpk(acc[p][1]);
        float2 u2 = unpk(acc[p][2]), u3 = unpk(acc[p][3]);
        int oe = o0 + og * 8 + 2 * p;
        float be = bias[oe], bo = bias[oe + 1];
        float4 re = make_float4(u0.x + be, u1.x + be, u2.x + be, u3.x + be);
        float4 ro = make_float4(u0.y + bo, u1.y + bo, u2.y + bo, u3.y + bo);
        size_t ae = ((size_t)n * Cout + oe) * L + l;
        size_t ao = ae + L;
        if (res) {
            float4 qe = *(const float4*)(res + ae);
            float4 qo = *(const float4*)(res + ao);
            re.x += qe.x; re.y += qe.y; re.z += qe.z; re.w += qe.w;
            ro.x += qo.x; ro.y += qo.y; ro.z += qo.z; ro.w += qo.w;
        }
        *(float4*)(out + ae) = re;
        *(float4*)(out + ao) = ro;
    }
}

// ---------------------------------------------------------------------------
// Attention pass 1: flash-style tf32 MMA. Block = 64 queries, 128 thr / 4 warps.
// Warp w owns q rows [16w, 16w+16). Loop over 16 key tiles of 64.
// smem: Qs[64][72](d,q)  Ks[64][72](d,s, reused as Os)  Vs[64][68](d,s)  Ps[64][68](q,s)
// ---------------------------------------------------------------------------
#define RQ 72
#define RV 68
#define ATTN1_SMEM ((64*RQ*2 + 64*RV*2) * 4)

__global__ __launch_bounds__(128, 2) void k_attn1(const float* __restrict__ qkv,
                                                  float* __restrict__ out) {
    extern __shared__ float sm[];
    float* Qs = sm;                  // [64][RQ] (d, q)
    float* Ks = sm + 64 * RQ;        // [64][RQ] (d, s); reused as Os (d, q)
    float* Vs = sm + 2 * 64 * RQ;    // [64][RV] (d, s)
    float* Ps = Vs + 64 * RV;        // [64][RV] (q, s)

    const int tid  = threadIdx.x;
    const int lane = tid & 31, w = tid >> 5;
    const int r  = lane >> 2;        // group id (row / n-col)
    const int k2 = lane & 3;         // thread-in-group (k index)
    const int bh = blockIdx.y;
    const int n = bh / 3, h = bh % 3;
    const int q0 = blockIdx.x * 64;
    const float* Q = qkv + (size_t)(n * 576 + h * 192) * 1024;
    const float* K = Q + 64 * 1024;
    const float* V = Q + 128 * 1024;

    const int dr = tid >> 4, c4 = (tid & 15) * 4;

    // ---- stage Q (scale 0.125 folded, tf32) ----
    #pragma unroll
    for (int i = 0; i < 8; i++) {
        int d = dr + 8 * i;
        float4 v = *(const float4*)(Q + d * 1024 + q0 + c4);
        float4 t = make_float4(tf32r(v.x * 0.125f), tf32r(v.y * 0.125f),
                               tf32r(v.z * 0.125f), tf32r(v.w * 0.125f));
        *(float4*)&Qs[d * RQ + c4] = t;
    }
    __syncthreads();

    // ---- Q fragments (A: m=q, k=d), persistent in registers ----
    uint32 qa[8][4];
    #pragma unroll
    for (int ks = 0; ks < 8; ks++) {
        int d0 = ks * 8 + k2;
        qa[ks][0] = __float_as_uint(Qs[d0 * RQ + 16 * w + r]);
        qa[ks][1] = __float_as_uint(Qs[d0 * RQ + 16 * w + r + 8]);
        qa[ks][2] = __float_as_uint(Qs[(d0 + 4) * RQ + 16 * w + r]);
        qa[ks][3] = __float_as_uint(Qs[(d0 + 4) * RQ + 16 * w + r + 8]);
    }

    float4 o[8];
    #pragma unroll
    for (int nt = 0; nt < 8; nt++) o[nt] = make_float4(0.f, 0.f, 0.f, 0.f);
    float m0 = -1e30f, m1 = -1e30f, s0 = 0.f, s1 = 0.f;

    for (int kt = 0; kt < 16; kt++) {
        __syncthreads();
        const int sb = kt * 64;
        // ---- stage K, V tiles (tf32) ----
        #pragma unroll
        for (int i = 0; i < 8; i++) {
            int d = dr + 8 * i;
            float4 kv = *(const float4*)(K + d * 1024 + sb + c4);
            *(float4*)&Ks[d * RQ + c4] = make_float4(tf32r(kv.x), tf32r(kv.y),
                                                     tf32r(kv.z), tf32r(kv.w));
            float4 vv = *(const float4*)(V + d * 1024 + sb + c4);
            *(float4*)&Vs[d * RV + c4] = make_float4(tf32r(vv.x), tf32r(vv.y),
                                                     tf32r(vv.z), tf32r(vv.w));
        }
        __syncthreads();

        // ---- S = Q K^T (warp: 16q x 64s) ----
        float4 sc[8];
        #pragma unroll
        for (int nt = 0; nt < 8; nt++) sc[nt] = make_float4(0.f, 0.f, 0.f, 0.f);
        #pragma unroll
        for (int ks = 0; ks < 8; ks++) {
            int d0 = ks * 8 + k2;
            const float* kr0 = Ks + d0 * RQ + r;
            const float* kr1 = Ks + (d0 + 4) * RQ + r;
            #pragma unroll
            for (int nt = 0; nt < 8; nt++) {
                uint32 b0 = __float_as_uint(kr0[nt * 8]);
                uint32 b1 = __float_as_uint(kr1[nt * 8]);
                mma8(sc[nt], qa[ks], b0, b1);
            }
        }

        // ---- online softmax (rows r=q%16 and r+8 per thread) ----
        float tm0 = -1e30f, tm1 = -1e30f;
        #pragma unroll
        for (int nt = 0; nt < 8; nt++) {
            tm0 = fmaxf(tm0, fmaxf(sc[nt].x, sc[nt].y));
            tm1 = fmaxf(tm1, fmaxf(sc[nt].z, sc[nt].w));
        }
        tm0 = fmaxf(tm0, __shfl_xor_sync(0xffffffffu, tm0, 1));
        tm0 = fmaxf(tm0, __shfl_xor_sync(0xffffffffu, tm0, 2));
        tm1 = fmaxf(tm1, __shfl_xor_sync(0xffffffffu, tm1, 1));
        tm1 = fmaxf(tm1, __shfl_xor_sync(0xffffffffu, tm1, 2));
        float nm0 = fmaxf(m0, tm0), nm1 = fmaxf(m1, tm1);
        float a0 = __expf(m0 - nm0), a1 = __expf(m1 - nm1);
        float t0 = 0.f, t1 = 0.f;
        float* pr0 = Ps + (16 * w + r) * RV;
        float* pr1 = Ps + (16 * w + r + 8) * RV;
        #pragma unroll
        for (int nt = 0; nt < 8; nt++) {
            float px = __expf(sc[nt].x - nm0), py = __expf(sc[nt].y - nm0);
            float pz = __expf(sc[nt].z - nm1), pw = __expf(sc[nt].w - nm1);
            t0 += px + py; t1 += pz + pw;
            int col = nt * 8 + 2 * k2;
            *(float2*)&pr0[col] = make_float2(tf32r(px), tf32r(py));
            *(float2*)&pr1[col] = make_float2(tf32r(pz), tf32r(pw));
            o[nt].x *= a0; o[nt].y *= a0;
            o[nt].z *= a1; o[nt].w *= a1;
        }
        t0 += __shfl_xor_sync(0xffffffffu, t0, 1);
        t0 += __shfl_xor_sync(0xffffffffu, t0, 2);
        t1 += __shfl_xor_sync(0xffffffffu, t1, 1);
        t1 += __shfl_xor_sync(0xffffffffu, t1, 2);
        s0 = s0 * a0 + t0;
        s1 = s1 * a1 + t1;
        m0 = nm0; m1 = nm1;
        __syncwarp();

        // ---- O += P V (warp: 16q x 64d) ----
        #pragma unroll
        for (int ks = 0; ks < 8; ks++) {
            int scol = ks * 8 + k2;
            uint32 a[4];
            a[0] = __float_as_uint(pr0[scol]);
            a[1] = __float_as_uint(pr1[scol]);
            a[2] = __float_as_uint(pr0[scol + 4]);
            a[3] = __float_as_uint(pr1[scol + 4]);
            #pragma unroll
            for (int nt = 0; nt < 8; nt++) {
                uint32 b0 = __float_as_uint(Vs[(nt * 8 + r) * RV + scol]);
                uint32 b1 = __float_as_uint(Vs[(nt * 8 + r) * RV + scol + 4]);
                mma8(o[nt], a, b0, b1);
            }
        }
    }

    // ---- normalize + write through smem (coalesce) ----
    float i0 = 1.f / s0, i1 = 1.f / s1;
    __syncthreads();
    #pragma unroll
    for (int nt = 0; nt < 8; nt++) {
        int d0 = nt * 8 + 2 * k2;
        Ks[d0 * RQ + 16 * w + r]           = o[nt].x * i0;
        Ks[(d0 + 1) * RQ + 16 * w + r]     = o[nt].y * i0;
        Ks[d0 * RQ + 16 * w + r + 8]       = o[nt].z * i1;
        Ks[(d0 + 1) * RQ + 16 * w + r + 8] = o[nt].w * i1;
    }
    __syncthreads();
    const int cb = n * 192 + h * 64;
    #pragma unroll
    for (int i = 0; i < 8; i++) {
        int d = dr + 8 * i;
        *(float4*)(out + (size_t)(cb + d) * 1024 + q0 + c4) = *(const float4*)&Ks[d * RQ + c4];
    }
}

// ---------------------------------------------------------------------------
// Attention pass 2: L=16
// ---------------------------------------------------------------------------
__global__ void k_attn2(const float* __restrict__ qkv, float* __restrict__ out) {
    __shared__ float qs[1024], ks[1024], vs[1024], S[16 * 17];
    int bh = blockIdx.x;
    int n = bh / 3, h = bh % 3;
    const float* B = qkv + (size_t)(n * 576 + h * 192) * 16;
    int tid = threadIdx.x;
    for (int i = tid; i < 1024; i += 256) {
        qs[i] = B[i] * 0.125f;
        ks[i] = B[1024 + i];
        vs[i] = B[2048 + i];
    }
    __syncthreads();
    {
        int q = tid >> 4, s = tid & 15;
        float a = 0.f;
        #pragma unroll
        for (int c = 0; c < 64; c++) a += qs[c * 16 + q] * ks[c * 16 + s];
        S[q * 17 + s] = a;
    }
    __syncthreads();
    if (tid < 16) {
        float* row = S + tid * 17;
        float m = -1e30f;
        #pragma unroll
        for (int s = 0; s < 16; s++) m = fmaxf(m, row[s]);
        float sum = 0.f;
        #pragma unroll
        for (int s = 0; s < 16; s++) { float e = __expf(row[s] - m); row[s] = e; sum += e; }
        float inv = 1.f / sum;
        #pragma unroll
        for (int s = 0; s < 16; s++) row[s] *= inv;
    }
    __syncthreads();
    {
        int q  = tid & 15;
        int cb = (tid >> 4) << 2;
        float a0 = 0.f, a1 = 0.f, a2 = 0.f, a3 = 0.f;
        #pragma unroll
        for (int s = 0; s < 16; s++) {
            float sv = S[q * 17 + s];
            a0 += vs[(cb + 0) * 16 + s] * sv;
            a1 += vs[(cb + 1) * 16 + s] * sv;
            a2 += vs[(cb + 2) * 16 + s] * sv;
            a3 += vs[(cb + 3) * 16 + s] * sv;
        }
        size_t ob = (size_t)(n * 192 + h * 64 + cb) * 16 + q;
        out[ob + 0 * 16] = a0;
        out[ob + 1 * 16] = a1;
        out[ob + 2 * 16] = a2;
        out[ob + 3 * 16] = a3;
    }
}

// ---------------------------------------------------------------------------
extern "C" void kernel_launch(void* const* d_in, const int* in_sizes, int n_in,
                              void* d_out, int out_size) {
    const float* x       = (const float*)d_in[0];
    const float* norm_g  = (const float*)d_in[1];
    const float* norm_b  = (const float*)d_in[2];
    const float* qkv_w   = (const float*)d_in[3];
    const float* qkv_b   = (const float*)d_in[4];
    const float* proj_w  = (const float*)d_in[5];
    const float* proj_b  = (const float*)d_in[6];
    const float* normt_g = (const float*)d_in[7];
    const float* normt_b = (const float*)d_in[8];
    const float* qkvt_w  = (const float*)d_in[9];
    const float* qkvt_b  = (const float*)d_in[10];
    const float* projt_w = (const float*)d_in[11];
    const float* projt_b = (const float*)d_in[12];
    float* out = (float*)d_out;

    float *xs, *nrm, *qkv, *att, *y, *yt;
    cudaGetSymbolAddress((void**)&xs,  g_xs);
    cudaGetSymbolAddress((void**)&nrm, g_nrm);
    cudaGetSymbolAddress((void**)&qkv, g_qkv);
    cudaGetSymbolAddress((void**)&att, g_att);
    cudaGetSymbolAddress((void**)&y,   g_y);
    cudaGetSymbolAddress((void**)&yt,  g_yt);

    cudaFuncSetAttribute(k_attn1, cudaFuncAttributeMaxDynamicSharedMemorySize, ATTN1_SMEM);

    int nb = (TOT + 255) / 256;

    // ---- pass 1 (spatial, L=1024) ----
    k_transpose1<<<nb, 256>>>(x);
    k_groupnorm<<<NBT * 32, 128>>>(xs, norm_g, norm_b, nrm, 1024);
    k_conv<<<dim3(256, 9), 256>>>(nrm, qkv_w, qkv_b, nullptr, qkv, 192, 576, 10);
    k_attn1<<<dim3(16, 96), 128, ATTN1_SMEM>>>(qkv, att);
    k_conv<<<dim3(256, 3), 256>>>(att, proj_w, proj_b, xs, y, 192, 192, 10);

    // ---- pass 2 (temporal, L=16) ----
    k_transpose2<<<nb, 256>>>();
    k_groupnorm<<<NBHW * 32, 128>>>(yt, normt_g, normt_b, nrm, 16);
    k_conv<<<dim3(256, 9), 256>>>(nrm, qkvt_w, qkvt_b, nullptr, qkv, 192, 576, 4);
    k_attn2<<<NBHW * 3, 256>>>(qkv, att);
    k_conv<<<dim3(256, 3), 256>>>(att, projt_w, projt_b, yt, xs, 192, 192, 4);

    k_transpose3<<<nb, 256>>>(out);
}

// round 5
// speedup vs baseline: 5.5609x; 1.1229x over previous
#include <cuda_runtime.h>
#include <math.h>

// Shapes
#define NBT   32
#define CCH   192
#define LHW   1024
#define NTT   16
#define NBHW  2048
#define TOT   (NBT*CCH*LHW)

typedef unsigned long long ull;
typedef unsigned int uint32;

// Scratch
__device__ float g_xs [TOT];
__device__ float g_nrm[TOT];
__device__ float g_qkv[NBT*3*CCH*LHW];
__device__ float g_att[TOT];
__device__ float g_y  [TOT];
__device__ float g_yt [TOT];

// ---- tf32 helpers ---------------------------------------------------------
__device__ __forceinline__ float tf32r(float x) {
    uint32 u; asm("cvt.rna.tf32.f32 %0, %1;" : "=r"(u) : "f"(x));
    return __uint_as_float(u);
}
__device__ __forceinline__ void mma8(float4 &c, const uint32* a, uint32 b0, uint32 b1) {
    asm("mma.sync.aligned.m16n8k8.row.col.f32.tf32.tf32.f32 "
        "{%0,%1,%2,%3},{%4,%5,%6,%7},{%8,%9},{%0,%1,%2,%3};"
        : "+f"(c.x), "+f"(c.y), "+f"(c.z), "+f"(c.w)
        : "r"(a[0]), "r"(a[1]), "r"(a[2]), "r"(a[3]), "r"(b0), "r"(b1));
}

// ---------------------------------------------------------------------------
// Transposes
// ---------------------------------------------------------------------------
__global__ void k_transpose1(const float* __restrict__ x) {
    int o = blockIdx.x * 256 + threadIdx.x;
    if (o >= TOT) return;
    int hw = o & 1023;
    int c  = (o >> 10) % CCH;
    int bt = o / (CCH * LHW);
    int b = bt >> 4, t = bt & 15;
    g_xs[o] = x[((b * CCH + c) * 16 + t) * 1024 + hw];
}

__global__ void k_transpose2() {
    int o = blockIdx.x * 256 + threadIdx.x;
    if (o >= TOT) return;
    int t   = o & 15;
    int c   = (o >> 4) % CCH;
    int bhw = o / (CCH * NTT);
    int b = bhw >> 10, hw = bhw & 1023;
    g_yt[o] = g_y[((b * 16 + t) * CCH + c) * 1024 + hw];
}

__global__ void k_transpose3(float* __restrict__ out) {
    int o = blockIdx.x * 256 + threadIdx.x;
    if (o >= TOT) return;
    int hw = o & 1023;
    int t  = (o >> 10) & 15;
    int c  = (o >> 14) % CCH;
    int b  = o / (CCH * NTT * LHW);
    out[o] = g_xs[((b * 1024 + hw) * CCH + c) * 16 + t];
}

// ---------------------------------------------------------------------------
// GroupNorm
// ---------------------------------------------------------------------------
__global__ void k_groupnorm(const float* __restrict__ X, const float* __restrict__ gam,
                            const float* __restrict__ bet, float* __restrict__ out, int L) {
    int n = blockIdx.x >> 5;
    int g = blockIdx.x & 31;
    int len = 6 * L;
    const float* base = X + (size_t)(n * CCH + g * 6) * L;
    float* ob = out + (size_t)(n * CCH + g * 6) * L;
    float s = 0.f, q = 0.f;
    for (int i = threadIdx.x; i < len; i += 128) { float v = base[i]; s += v; q += v * v; }
    __shared__ float rs[128], rq[128];
    rs[threadIdx.x] = s; rq[threadIdx.x] = q;
    __syncthreads();
    for (int st = 64; st > 0; st >>= 1) {
        if (threadIdx.x < st) { rs[threadIdx.x] += rs[threadIdx.x + st]; rq[threadIdx.x] += rq[threadIdx.x + st]; }
        __syncthreads();
    }
    float mean = rs[0] / len;
    float var  = rq[0] / len - mean * mean;
    float inv  = rsqrtf(var + 1e-5f);
    for (int i = threadIdx.x; i < len; i += 128) {
        int c = g * 6 + i / L;
        ob[i] = (base[i] - mean) * inv * gam[c] + bet[c];
    }
}

// ---------------------------------------------------------------------------
// 1x1 conv as tf32 tensor-core GEMM.
// out[n][o][l] = bias[o] + sum_k W[o][k] * X[n][k][l]  (+res)
// Block: 128 thr / 4 warps; tile 64 o x 128 cols; K staged 16 rows.
// Warp w: o rows [o0+16w, +16); cols all 128 (16 n-tiles of 8).
// Xs pad 132, Ws pad 68 -> fragment reads hit banks 4*k2+r (conflict-free).
// ---------------------------------------------------------------------------
#define XP 132
#define WP 68

__global__ __launch_bounds__(128) void k_convT(
    const float* __restrict__ X, const float* __restrict__ W,
    const float* __restrict__ bias, const float* __restrict__ res,
    float* __restrict__ out, int Cin, int Cout, int ls) {
    __shared__ float Xs[16][XP];
    __shared__ float Ws[16][WP];
    const int L = 1 << ls, Lm1 = L - 1;
    const int tid = threadIdx.x;
    const int lane = tid & 31, w = tid >> 5;
    const int r = lane >> 2, k2 = lane & 3;
    const int g0 = blockIdx.x * 128;
    const int o0 = blockIdx.y * 64;

    float4 acc[16];
    #pragma unroll
    for (int nt = 0; nt < 16; nt++) acc[nt] = make_float4(0.f, 0.f, 0.f, 0.f);

    const int xrow = tid >> 5;        // + 4*i
    const int xc4  = (tid & 31) * 4;
    const int wo   = tid & 63;
    const int wkq  = (tid >> 6) * 4;  // + 8*i

    for (int cc = 0; cc < Cin; cc += 16) {
        // stage X[cc..cc+15][g0..g0+127] -> Xs (tf32)
        #pragma unroll
        for (int i = 0; i < 4; i++) {
            int k = xrow + 4 * i;
            int g = g0 + xc4;
            float4 v = *(const float4*)(X + ((size_t)(g >> ls) * Cin + cc + k) * L + (g & Lm1));
            *(float4*)&Xs[k][xc4] = make_float4(tf32r(v.x), tf32r(v.y), tf32r(v.z), tf32r(v.w));
        }
        // stage W[o0..o0+63][cc..cc+15] transposed -> Ws[k][o] (tf32)
        #pragma unroll
        for (int i = 0; i < 2; i++) {
            int k4 = wkq + 8 * i;
            float4 wv = *(const float4*)(W + (size_t)(o0 + wo) * Cin + cc + k4);
            Ws[k4 + 0][wo] = tf32r(wv.x);
            Ws[k4 + 1][wo] = tf32r(wv.y);
            Ws[k4 + 2][wo] = tf32r(wv.z);
            Ws[k4 + 3][wo] = tf32r(wv.w);
        }
        __syncthreads();
        #pragma unroll
        for (int kc = 0; kc < 16; kc += 8) {
            uint32 a[4];
            a[0] = __float_as_uint(Ws[kc + k2]    [16 * w + r]);
            a[1] = __float_as_uint(Ws[kc + k2]    [16 * w + r + 8]);
            a[2] = __float_as_uint(Ws[kc + k2 + 4][16 * w + r]);
            a[3] = __float_as_uint(Ws[kc + k2 + 4][16 * w + r + 8]);
            #pragma unroll
            for (int nt = 0; nt < 16; nt++) {
                uint32 b0 = __float_as_uint(Xs[kc + k2]    [nt * 8 + r]);
                uint32 b1 = __float_as_uint(Xs[kc + k2 + 4][nt * 8 + r]);
                mma8(acc[nt], a, b0, b1);
            }
        }
        __syncthreads();
    }

    // epilogue: C rows oa=o0+16w+r (c.x,c.y) and oa+8 (c.z,c.w); cols nt*8+2k2, +1
    const int oa = o0 + 16 * w + r;
    const int ob = oa + 8;
    const float ba = bias[oa], bb = bias[ob];
    #pragma unroll
    for (int nt = 0; nt < 16; nt++) {
        int g = g0 + nt * 8 + 2 * k2;
        int n = g >> ls, l = g & Lm1;
        size_t pa = ((size_t)n * Cout + oa) * L + l;
        size_t pb = ((size_t)n * Cout + ob) * L + l;
        float2 va = make_float2(acc[nt].x + ba, acc[nt].y + ba);
        float2 vb = make_float2(acc[nt].z + bb, acc[nt].w + bb);
        if (res) {
            float2 qa = *(const float2*)(res + pa);
            float2 qb = *(const float2*)(res + pb);
            va.x += qa.x; va.y += qa.y;
            vb.x += qb.x; vb.y += qb.y;
        }
        *(float2*)(out + pa) = va;
        *(float2*)(out + pb) = vb;
    }
}

// ---------------------------------------------------------------------------
// Attention pass 1: flash-style tf32 MMA. Block = 64 queries, 128 thr / 4 warps.
// ---------------------------------------------------------------------------
#define RQ 72
#define RV 68
#define ATTN1_SMEM ((64*RQ*2 + 64*RV*2) * 4)

__global__ __launch_bounds__(128, 2) void k_attn1(const float* __restrict__ qkv,
                                                  float* __restrict__ out) {
    extern __shared__ float sm[];
    float* Qs = sm;                  // [64][RQ] (d, q)
    float* Ks = sm + 64 * RQ;        // [64][RQ] (d, s); reused as Os (d, q)
    float* Vs = sm + 2 * 64 * RQ;    // [64][RV] (d, s)
    float* Ps = Vs + 64 * RV;        // [64][RV] (q, s)

    const int tid  = threadIdx.x;
    const int lane = tid & 31, w = tid >> 5;
    const int r  = lane >> 2;
    const int k2 = lane & 3;
    const int bh = blockIdx.y;
    const int n = bh / 3, h = bh % 3;
    const int q0 = blockIdx.x * 64;
    const float* Q = qkv + (size_t)(n * 576 + h * 192) * 1024;
    const float* K = Q + 64 * 1024;
    const float* V = Q + 128 * 1024;

    const int dr = tid >> 4, c4 = (tid & 15) * 4;

    #pragma unroll
    for (int i = 0; i < 8; i++) {
        int d = dr + 8 * i;
        float4 v = *(const float4*)(Q + d * 1024 + q0 + c4);
        float4 t = make_float4(tf32r(v.x * 0.125f), tf32r(v.y * 0.125f),
                               tf32r(v.z * 0.125f), tf32r(v.w * 0.125f));
        *(float4*)&Qs[d * RQ + c4] = t;
    }
    __syncthreads();

    uint32 qa[8][4];
    #pragma unroll
    for (int ks = 0; ks < 8; ks++) {
        int d0 = ks * 8 + k2;
        qa[ks][0] = __float_as_uint(Qs[d0 * RQ + 16 * w + r]);
        qa[ks][1] = __float_as_uint(Qs[d0 * RQ + 16 * w + r + 8]);
        qa[ks][2] = __float_as_uint(Qs[(d0 + 4) * RQ + 16 * w + r]);
        qa[ks][3] = __float_as_uint(Qs[(d0 + 4) * RQ + 16 * w + r + 8]);
    }

    float4 o[8];
    #pragma unroll
    for (int nt = 0; nt < 8; nt++) o[nt] = make_float4(0.f, 0.f, 0.f, 0.f);
    float m0 = -1e30f, m1 = -1e30f, s0 = 0.f, s1 = 0.f;

    for (int kt = 0; kt < 16; kt++) {
        __syncthreads();
        const int sb = kt * 64;
        #pragma unroll
        for (int i = 0; i < 8; i++) {
            int d = dr + 8 * i;
            float4 kv = *(const float4*)(K + d * 1024 + sb + c4);
            *(float4*)&Ks[d * RQ + c4] = make_float4(tf32r(kv.x), tf32r(kv.y),
                                                     tf32r(kv.z), tf32r(kv.w));
            float4 vv = *(const float4*)(V + d * 1024 + sb + c4);
            *(float4*)&Vs[d * RV + c4] = make_float4(tf32r(vv.x), tf32r(vv.y),
                                                     tf32r(vv.z), tf32r(vv.w));
        }
        __syncthreads();

        float4 sc[8];
        #pragma unroll
        for (int nt = 0; nt < 8; nt++) sc[nt] = make_float4(0.f, 0.f, 0.f, 0.f);
        #pragma unroll
        for (int ks = 0; ks < 8; ks++) {
            int d0 = ks * 8 + k2;
            const float* kr0 = Ks + d0 * RQ + r;
            const float* kr1 = Ks + (d0 + 4) * RQ + r;
            #pragma unroll
            for (int nt = 0; nt < 8; nt++) {
                uint32 b0 = __float_as_uint(kr0[nt * 8]);
                uint32 b1 = __float_as_uint(kr1[nt * 8]);
                mma8(sc[nt], qa[ks], b0, b1);
            }
        }

        float tm0 = -1e30f, tm1 = -1e30f;
        #pragma unroll
        for (int nt = 0; nt < 8; nt++) {
            tm0 = fmaxf(tm0, fmaxf(sc[nt].x, sc[nt].y));
            tm1 = fmaxf(tm1, fmaxf(sc[nt].z, sc[nt].w));
        }
        tm0 = fmaxf(tm0, __shfl_xor_sync(0xffffffffu, tm0, 1));
        tm0 = fmaxf(tm0, __shfl_xor_sync(0xffffffffu, tm0, 2));
        tm1 = fmaxf(tm1, __shfl_xor_sync(0xffffffffu, tm1, 1));
        tm1 = fmaxf(tm1, __shfl_xor_sync(0xffffffffu, tm1, 2));
        float nm0 = fmaxf(m0, tm0), nm1 = fmaxf(m1, tm1);
        float a0 = __expf(m0 - nm0), a1 = __expf(m1 - nm1);
        float t0 = 0.f, t1 = 0.f;
        float* pr0 = Ps + (16 * w + r) * RV;
        float* pr1 = Ps + (16 * w + r + 8) * RV;
        #pragma unroll
        for (int nt = 0; nt < 8; nt++) {
            float px = __expf(sc[nt].x - nm0), py = __expf(sc[nt].y - nm0);
            float pz = __expf(sc[nt].z - nm1), pw = __expf(sc[nt].w - nm1);
            t0 += px + py; t1 += pz + pw;
            int col = nt * 8 + 2 * k2;
            *(float2*)&pr0[col] = make_float2(tf32r(px), tf32r(py));
            *(float2*)&pr1[col] = make_float2(tf32r(pz), tf32r(pw));
            o[nt].x *= a0; o[nt].y *= a0;
            o[nt].z *= a1; o[nt].w *= a1;
        }
        t0 += __shfl_xor_sync(0xffffffffu, t0, 1);
        t0 += __shfl_xor_sync(0xffffffffu, t0, 2);
        t1 += __shfl_xor_sync(0xffffffffu, t1, 1);
        t1 += __shfl_xor_sync(0xffffffffu, t1, 2);
        s0 = s0 * a0 + t0;
        s1 = s1 * a1 + t1;
        m0 = nm0; m1 = nm1;
        __syncwarp();

        #pragma unroll
        for (int ks = 0; ks < 8; ks++) {
            int scol = ks * 8 + k2;
            uint32 a[4];
            a[0] = __float_as_uint(pr0[scol]);
            a[1] = __float_as_uint(pr1[scol]);
            a[2] = __float_as_uint(pr0[scol + 4]);
            a[3] = __float_as_uint(pr1[scol + 4]);
            #pragma unroll
            for (int nt = 0; nt < 8; nt++) {
                uint32 b0 = __float_as_uint(Vs[(nt * 8 + r) * RV + scol]);
                uint32 b1 = __float_as_uint(Vs[(nt * 8 + r) * RV + scol + 4]);
                mma8(o[nt], a, b0, b1);
            }
        }
    }

    float i0 = 1.f / s0, i1 = 1.f / s1;
    __syncthreads();
    #pragma unroll
    for (int nt = 0; nt < 8; nt++) {
        int d0 = nt * 8 + 2 * k2;
        Ks[d0 * RQ + 16 * w + r]           = o[nt].x * i0;
        Ks[(d0 + 1) * RQ + 16 * w + r]     = o[nt].y * i0;
        Ks[d0 * RQ + 16 * w + r + 8]       = o[nt].z * i1;
        Ks[(d0 + 1) * RQ + 16 * w + r + 8] = o[nt].w * i1;
    }
    __syncthreads();
    const int cb = n * 192 + h * 64;
    #pragma unroll
    for (int i = 0; i < 8; i++) {
        int d = dr + 8 * i;
        *(float4*)(out + (size_t)(cb + d) * 1024 + q0 + c4) = *(const float4*)&Ks[d * RQ + c4];
    }
}

// ---------------------------------------------------------------------------
// Attention pass 2: L=16
// ---------------------------------------------------------------------------
__global__ void k_attn2(const float* __restrict__ qkv, float* __restrict__ out) {
    __shared__ float qs[1024], ks[1024], vs[1024], S[16 * 17];
    int bh = blockIdx.x;
    int n = bh / 3, h = bh % 3;
    const float* B = qkv + (size_t)(n * 576 + h * 192) * 16;
    int tid = threadIdx.x;
    for (int i = tid; i < 1024; i += 256) {
        qs[i] = B[i] * 0.125f;
        ks[i] = B[1024 + i];
        vs[i] = B[2048 + i];
    }
    __syncthreads();
    {
        int q = tid >> 4, s = tid & 15;
        float a = 0.f;
        #pragma unroll
        for (int c = 0; c < 64; c++) a += qs[c * 16 + q] * ks[c * 16 + s];
        S[q * 17 + s] = a;
    }
    __syncthreads();
    if (tid < 16) {
        float* row = S + tid * 17;
        float m = -1e30f;
        #pragma unroll
        for (int s = 0; s < 16; s++) m = fmaxf(m, row[s]);
        float sum = 0.f;
        #pragma unroll
        for (int s = 0; s < 16; s++) { float e = __expf(row[s] - m); row[s] = e; sum += e; }
        float inv = 1.f / sum;
        #pragma unroll
        for (int s = 0; s < 16; s++) row[s] *= inv;
    }
    __syncthreads();
    {
        int q  = tid & 15;
        int cb = (tid >> 4) << 2;
        float a0 = 0.f, a1 = 0.f, a2 = 0.f, a3 = 0.f;
        #pragma unroll
        for (int s = 0; s < 16; s++) {
            float sv = S[q * 17 + s];
            a0 += vs[(cb + 0) * 16 + s] * sv;
            a1 += vs[(cb + 1) * 16 + s] * sv;
            a2 += vs[(cb + 2) * 16 + s] * sv;
            a3 += vs[(cb + 3) * 16 + s] * sv;
        }
        size_t ob = (size_t)(n * 192 + h * 64 + cb) * 16 + q;
        out[ob + 0 * 16] = a0;
        out[ob + 1 * 16] = a1;
        out[ob + 2 * 16] = a2;
        out[ob + 3 * 16] = a3;
    }
}

// ---------------------------------------------------------------------------
extern "C" void kernel_launch(void* const* d_in, const int* in_sizes, int n_in,
                              void* d_out, int out_size) {
    const float* x       = (const float*)d_in[0];
    const float* norm_g  = (const float*)d_in[1];
    const float* norm_b  = (const float*)d_in[2];
    const float* qkv_w   = (const float*)d_in[3];
    const float* qkv_b   = (const float*)d_in[4];
    const float* proj_w  = (const float*)d_in[5];
    const float* proj_b  = (const float*)d_in[6];
    const float* normt_g = (const float*)d_in[7];
    const float* normt_b = (const float*)d_in[8];
    const float* qkvt_w  = (const float*)d_in[9];
    const float* qkvt_b  = (const float*)d_in[10];
    const float* projt_w = (const float*)d_in[11];
    const float* projt_b = (const float*)d_in[12];
    float* out = (float*)d_out;

    float *xs, *nrm, *qkv, *att, *y, *yt;
    cudaGetSymbolAddress((void**)&xs,  g_xs);
    cudaGetSymbolAddress((void**)&nrm, g_nrm);
    cudaGetSymbolAddress((void**)&qkv, g_qkv);
    cudaGetSymbolAddress((void**)&att, g_att);
    cudaGetSymbolAddress((void**)&y,   g_y);
    cudaGetSymbolAddress((void**)&yt,  g_yt);

    cudaFuncSetAttribute(k_attn1, cudaFuncAttributeMaxDynamicSharedMemorySize, ATTN1_SMEM);

    int nb = (TOT + 255) / 256;

    // ---- pass 1 (spatial, L=1024) ----
    k_transpose1<<<nb, 256>>>(x);
    k_groupnorm<<<NBT * 32, 128>>>(xs, norm_g, norm_b, nrm, 1024);
    k_convT<<<dim3(256, 9), 128>>>(nrm, qkv_w, qkv_b, nullptr, qkv, 192, 576, 10);
    k_attn1<<<dim3(16, 96), 128, ATTN1_SMEM>>>(qkv, att);
    k_convT<<<dim3(256, 3), 128>>>(att, proj_w, proj_b, xs, y, 192, 192, 10);

    // ---- pass 2 (temporal, L=16) ----
    k_transpose2<<<nb, 256>>>();
    k_groupnorm<<<NBHW * 32, 128>>>(yt, normt_g, normt_b, nrm, 16);
    k_convT<<<dim3(256, 9), 128>>>(nrm, qkvt_w, qkvt_b, nullptr, qkv, 192, 576, 4);
    k_attn2<<<NBHW * 3, 256>>>(qkv, att);
    k_convT<<<dim3(256, 3), 128>>>(att, projt_w, projt_b, yt, xs, 192, 192, 4);

    k_transpose3<<<nb, 256>>>(out);
}

// round 6
// speedup vs baseline: 6.2385x; 1.1219x over previous
#include <cuda_runtime.h>
#include <math.h>

// Shapes
#define NBT   32
#define CCH   192
#define LHW   1024
#define NTT   16
#define NBHW  2048
#define TOT   (NBT*CCH*LHW)

typedef unsigned long long ull;
typedef unsigned int uint32;

// Scratch
__device__ float g_xs [TOT];           // z (bhw,c,t) in pass2
__device__ float g_nrm[TOT];
__device__ float g_qkv[NBT*3*CCH*LHW];
__device__ float g_att[TOT];
__device__ float g_y  [TOT];
__device__ float g_yt [TOT];

// ---- mma / cp.async helpers ------------------------------------------------
__device__ __forceinline__ void mma8(float4 &c, const uint32* a, uint32 b0, uint32 b1) {
    asm("mma.sync.aligned.m16n8k8.row.col.f32.tf32.tf32.f32 "
        "{%0,%1,%2,%3},{%4,%5,%6,%7},{%8,%9},{%0,%1,%2,%3};"
        : "+f"(c.x), "+f"(c.y), "+f"(c.z), "+f"(c.w)
        : "r"(a[0]), "r"(a[1]), "r"(a[2]), "r"(a[3]), "r"(b0), "r"(b1));
}
__device__ __forceinline__ uint32 sptr(const void* p) {
    return (uint32)__cvta_generic_to_shared(p);
}
__device__ __forceinline__ void cp16(uint32 s, const void* g) {
    asm volatile("cp.async.ca.shared.global [%0], [%1], 16;" :: "r"(s), "l"(g));
}
__device__ __forceinline__ void cp_commit() { asm volatile("cp.async.commit_group;"); }
template<int N> __device__ __forceinline__ void cp_wait() {
    asm volatile("cp.async.wait_group %0;" :: "n"(N));
}

// ---------------------------------------------------------------------------
// GroupNorm pass 1: reads x (b,c,t,hw) directly, writes nrm (bt,c,hw)
// ---------------------------------------------------------------------------
__global__ void k_gn1(const float* __restrict__ x, const float* __restrict__ gam,
                      const float* __restrict__ bet, float* __restrict__ out) {
    int n = blockIdx.x >> 5;         // bt
    int g = blockIdx.x & 31;
    int b = n >> 4, t = n & 15;
    const float* xb = x + (((size_t)(b * CCH + g * 6) * 16 + t) << 10);
    float* ob = out + (size_t)(n * CCH + g * 6) * 1024;
    int tid = threadIdx.x;
    float s = 0.f, q = 0.f;
    for (int i = tid; i < 6144; i += 256) {
        float v = xb[((size_t)(i >> 10) << 14) + (i & 1023)];
        s += v; q += v * v;
    }
    __shared__ float rs[256], rq[256];
    rs[tid] = s; rq[tid] = q;
    __syncthreads();
    for (int st = 128; st > 0; st >>= 1) {
        if (tid < st) { rs[tid] += rs[tid + st]; rq[tid] += rq[tid + st]; }
        __syncthreads();
    }
    float mean = rs[0] / 6144.f;
    float var  = rq[0] / 6144.f - mean * mean;
    float inv  = rsqrtf(var + 1e-5f);
    for (int i = tid; i < 6144; i += 256) {
        int c = g * 6 + (i >> 10);
        float v = xb[((size_t)(i >> 10) << 14) + (i & 1023)];
        ob[i] = (v - mean) * inv * gam[c] + bet[c];
    }
}

// ---------------------------------------------------------------------------
// GroupNorm pass 2: X (bhw,c,t) contiguous per n; one block per n.
// ---------------------------------------------------------------------------
__global__ void k_gn2(const float* __restrict__ X, const float* __restrict__ gam,
                      const float* __restrict__ bet, float* __restrict__ out) {
    int n = blockIdx.x;
    __shared__ float buf[3072];
    __shared__ float mu[32], iv[32];
    int tid = threadIdx.x;
    const float4* xb = (const float4*)(X + (size_t)n * 3072);
    #pragma unroll
    for (int i = tid; i < 768; i += 128) ((float4*)buf)[i] = xb[i];
    __syncthreads();
    int w = tid >> 5, lane = tid & 31;
    for (int g = w; g < 32; g += 4) {
        float v0 = buf[g * 96 + lane], v1 = buf[g * 96 + 32 + lane], v2 = buf[g * 96 + 64 + lane];
        float s = v0 + v1 + v2, q = v0 * v0 + v1 * v1 + v2 * v2;
        #pragma unroll
        for (int off = 16; off; off >>= 1) {
            s += __shfl_xor_sync(0xffffffffu, s, off);
            q += __shfl_xor_sync(0xffffffffu, q, off);
        }
        if (lane == 0) {
            float m = s / 96.f, va = q / 96.f - m * m;
            mu[g] = m; iv[g] = rsqrtf(va + 1e-5f);
        }
    }
    __syncthreads();
    float* ob = out + (size_t)n * 3072;
    for (int i = tid; i < 3072; i += 128) {
        int c = i >> 4, g = c / 6;
        ob[i] = (buf[i] - mu[g]) * iv[g] * gam[c] + bet[c];
    }
}

// ---------------------------------------------------------------------------
// Tiled transposes through smem
// y (bt,c,hw) -> yt (bhw,c,t)
// ---------------------------------------------------------------------------
__global__ void k_transpose2t() {
    __shared__ float sm[64][20];
    int hw0 = blockIdx.x * 64, c = blockIdx.y, b = blockIdx.z;
    int tid = threadIdx.x;
    {
        int t = tid & 15, hwj = (tid >> 4) * 4;
        float4 v = *(const float4*)&g_y[(((size_t)(b * 16 + t) * CCH + c) << 10) + hw0 + hwj];
        sm[hwj + 0][t] = v.x; sm[hwj + 1][t] = v.y;
        sm[hwj + 2][t] = v.z; sm[hwj + 3][t] = v.w;
    }
    __syncthreads();
    {
        int hwl = tid >> 2, t4 = (tid & 3) * 4;
        *(float4*)&g_yt[((size_t)(b * 1024 + hw0 + hwl) * CCH + c) * 16 + t4] =
            *(const float4*)&sm[hwl][t4];
    }
}

// z (bhw,c,t) -> out (b,c,t,hw)
__global__ void k_transpose3t(float* __restrict__ out) {
    __shared__ float sm[16][68];
    int hw0 = blockIdx.x * 64, c = blockIdx.y, b = blockIdx.z;
    int tid = threadIdx.x;
    {
        int hwl = tid >> 2, t4 = (tid & 3) * 4;
        float4 v = *(const float4*)&g_xs[((size_t)(b * 1024 + hw0 + hwl) * CCH + c) * 16 + t4];
        sm[t4 + 0][hwl] = v.x; sm[t4 + 1][hwl] = v.y;
        sm[t4 + 2][hwl] = v.z; sm[t4 + 3][hwl] = v.w;
    }
    __syncthreads();
    {
        int t = tid >> 4, hw4 = (tid & 15) * 4;
        *(float4*)&out[(((size_t)(b * CCH + c) * 16 + t) << 10) + hw0 + hw4] =
            *(const float4*)&sm[t][hw4];
    }
}

// ---------------------------------------------------------------------------
// 1x1 conv as tf32 tensor-core GEMM with cp.async double buffering.
// Block: 128 thr / 4 warps; tile 64 o x 128 cols; K staged 16 at a time.
// Xs pad 132 (B-frags conflict-free), Ws row-major pad 20 (A-frags conflict-free).
// resmode: 0 = none, 1 = same layout, 2 = x layout (b,C,t,hw), Cout=192
// ---------------------------------------------------------------------------
#define XP 132
#define WPD 20

__global__ __launch_bounds__(128, 3) void k_convT(
    const float* __restrict__ X, const float* __restrict__ W,
    const float* __restrict__ bias, const float* __restrict__ res,
    float* __restrict__ out, int Cin, int Cout, int ls, int resmode) {
    __shared__ float Xs[2][16][XP];
    __shared__ float Ws[2][64][WPD];
    const int L = 1 << ls, Lm1 = L - 1;
    const int tid = threadIdx.x;
    const int lane = tid & 31, w = tid >> 5;
    const int r = lane >> 2, k2 = lane & 3;
    const int g0 = blockIdx.x * 128;
    const int o0 = blockIdx.y * 64;

    float4 acc[16];
    #pragma unroll
    for (int nt = 0; nt < 16; nt++) acc[nt] = make_float4(0.f, 0.f, 0.f, 0.f);

    const int xrow = tid >> 5;        // + 4*i
    const int xc4  = (tid & 31) * 4;
    const int wo   = tid & 63;
    const int wkq  = (tid >> 6) * 4;  // + 8*i

    const int nch = Cin >> 4;         // 12

    // prologue: stage chunk 0
    {
        #pragma unroll
        for (int i = 0; i < 4; i++) {
            int k = xrow + 4 * i;
            int g = g0 + xc4;
            cp16(sptr(&Xs[0][k][xc4]), X + ((size_t)(g >> ls) * Cin + k) * L + (g & Lm1));
        }
        #pragma unroll
        for (int i = 0; i < 2; i++) {
            int k4 = wkq + 8 * i;
            cp16(sptr(&Ws[0][wo][k4]), W + (size_t)(o0 + wo) * Cin + k4);
        }
        cp_commit();
    }

    for (int c = 0; c < nch; c++) {
        const int buf = c & 1;
        if (c + 1 < nch) {
            const int cc = (c + 1) << 4;
            #pragma unroll
            for (int i = 0; i < 4; i++) {
                int k = xrow + 4 * i;
                int g = g0 + xc4;
                cp16(sptr(&Xs[buf ^ 1][k][xc4]),
                     X + ((size_t)(g >> ls) * Cin + cc + k) * L + (g & Lm1));
            }
            #pragma unroll
            for (int i = 0; i < 2; i++) {
                int k4 = wkq + 8 * i;
                cp16(sptr(&Ws[buf ^ 1][wo][k4]), W + (size_t)(o0 + wo) * Cin + cc + k4);
            }
            cp_commit();
            cp_wait<1>();
        } else {
            cp_wait<0>();
        }
        __syncthreads();
        #pragma unroll
        for (int kc = 0; kc < 16; kc += 8) {
            uint32 a[4];
            a[0] = __float_as_uint(Ws[buf][16 * w + r]    [kc + k2]);
            a[1] = __float_as_uint(Ws[buf][16 * w + r + 8][kc + k2]);
            a[2] = __float_as_uint(Ws[buf][16 * w + r]    [kc + k2 + 4]);
            a[3] = __float_as_uint(Ws[buf][16 * w + r + 8][kc + k2 + 4]);
            #pragma unroll
            for (int nt = 0; nt < 16; nt++) {
                uint32 b0 = __float_as_uint(Xs[buf][kc + k2]    [nt * 8 + r]);
                uint32 b1 = __float_as_uint(Xs[buf][kc + k2 + 4][nt * 8 + r]);
                mma8(acc[nt], a, b0, b1);
            }
        }
        __syncthreads();
    }

    // epilogue
    const int oa = o0 + 16 * w + r;
    const int ob = oa + 8;
    const float ba = bias[oa], bb = bias[ob];
    #pragma unroll
    for (int nt = 0; nt < 16; nt++) {
        int g = g0 + nt * 8 + 2 * k2;
        int n = g >> ls, l = g & Lm1;
        size_t pa = ((size_t)n * Cout + oa) * L + l;
        size_t pb = ((size_t)n * Cout + ob) * L + l;
        float2 va = make_float2(acc[nt].x + ba, acc[nt].y + ba);
        float2 vb = make_float2(acc[nt].z + bb, acc[nt].w + bb);
        if (resmode == 1) {
            float2 qa = *(const float2*)(res + pa);
            float2 qb = *(const float2*)(res + pb);
            va.x += qa.x; va.y += qa.y; vb.x += qb.x; vb.y += qb.y;
        } else if (resmode == 2) {  // x layout (b,192,t,hw); n = b*16+t, l = hw
            int b = n >> 4, t = n & 15;
            size_t xa = (((size_t)(b * 192 + oa) * 16 + t) << 10) + l;
            size_t xb = (((size_t)(b * 192 + ob) * 16 + t) << 10) + l;
            float2 qa = *(const float2*)(res + xa);
            float2 qb = *(const float2*)(res + xb);
            va.x += qa.x; va.y += qa.y; vb.x += qb.x; vb.y += qb.y;
        }
        *(float2*)(out + pa) = va;
        *(float2*)(out + pb) = vb;
    }
}

// ---------------------------------------------------------------------------
// Attention pass 1: flash tf32 MMA, cp.async double-buffered K/V.
// Block = 64 queries, 128 thr / 4 warps; warp owns 16 q rows.
// ---------------------------------------------------------------------------
#define RQ 72
#define RV 68
#define ATTN1_SMEM ((3*64*RQ + 3*64*RV) * 4)   // Qs + Kb[2] + Vb[2] + Ps = 107520B

__global__ __launch_bounds__(128, 2) void k_attn1(const float* __restrict__ qkv,
                                                  float* __restrict__ out) {
    extern __shared__ float sm[];
    float* Qs  = sm;
    float* Kb0 = sm + 64 * RQ;
    float* Kb1 = sm + 2 * 64 * RQ;
    float* Vb0 = sm + 3 * 64 * RQ;
    float* Vb1 = Vb0 + 64 * RV;
    float* Ps  = Vb0 + 2 * 64 * RV;
    float* KB[2] = {Kb0, Kb1};
    float* VB[2] = {Vb0, Vb1};

    const int tid  = threadIdx.x;
    const int lane = tid & 31, w = tid >> 5;
    const int r  = lane >> 2;
    const int k2 = lane & 3;
    const int bh = blockIdx.y;
    const int n = bh / 3, h = bh % 3;
    const int q0 = blockIdx.x * 64;
    const float* Q = qkv + (size_t)(n * 576 + h * 192) * 1024;
    const float* K = Q + 64 * 1024;
    const float* V = Q + 128 * 1024;

    const int dr = tid >> 4, c4 = (tid & 15) * 4;

    // prologue: stage K/V tile 0
    #pragma unroll
    for (int i = 0; i < 8; i++) {
        int d = dr + 8 * i;
        cp16(sptr(&KB[0][d * RQ + c4]), K + d * 1024 + c4);
        cp16(sptr(&VB[0][d * RV + c4]), V + d * 1024 + c4);
    }
    cp_commit();

    // stage Q (scale folded)
    #pragma unroll
    for (int i = 0; i < 8; i++) {
        int d = dr + 8 * i;
        float4 v = *(const float4*)(Q + d * 1024 + q0 + c4);
        *(float4*)&Qs[d * RQ + c4] = make_float4(v.x * 0.125f, v.y * 0.125f,
                                                 v.z * 0.125f, v.w * 0.125f);
    }
    __syncthreads();

    uint32 qa[8][4];
    #pragma unroll
    for (int ks = 0; ks < 8; ks++) {
        int d0 = ks * 8 + k2;
        qa[ks][0] = __float_as_uint(Qs[d0 * RQ + 16 * w + r]);
        qa[ks][1] = __float_as_uint(Qs[d0 * RQ + 16 * w + r + 8]);
        qa[ks][2] = __float_as_uint(Qs[(d0 + 4) * RQ + 16 * w + r]);
        qa[ks][3] = __float_as_uint(Qs[(d0 + 4) * RQ + 16 * w + r + 8]);
    }

    float4 o[8];
    #pragma unroll
    for (int nt = 0; nt < 8; nt++) o[nt] = make_float4(0.f, 0.f, 0.f, 0.f);
    float m0 = -1e30f, m1 = -1e30f, s0 = 0.f, s1 = 0.f;

    for (int kt = 0; kt < 16; kt++) {
        const int buf = kt & 1;
        if (kt < 15) {
            const int sb = (kt + 1) * 64;
            #pragma unroll
            for (int i = 0; i < 8; i++) {
                int d = dr + 8 * i;
                cp16(sptr(&KB[buf ^ 1][d * RQ + c4]), K + d * 1024 + sb + c4);
                cp16(sptr(&VB[buf ^ 1][d * RV + c4]), V + d * 1024 + sb + c4);
            }
            cp_commit();
            cp_wait<1>();
        } else {
            cp_wait<0>();
        }
        __syncthreads();
        const float* Ks = KB[buf];
        const float* Vs = VB[buf];

        // S = Q K^T
        float4 sc[8];
        #pragma unroll
        for (int nt = 0; nt < 8; nt++) sc[nt] = make_float4(0.f, 0.f, 0.f, 0.f);
        #pragma unroll
        for (int ks = 0; ks < 8; ks++) {
            int d0 = ks * 8 + k2;
            const float* kr0 = Ks + d0 * RQ + r;
            const float* kr1 = Ks + (d0 + 4) * RQ + r;
            #pragma unroll
            for (int nt = 0; nt < 8; nt++) {
                uint32 b0 = __float_as_uint(kr0[nt * 8]);
                uint32 b1 = __float_as_uint(kr1[nt * 8]);
                mma8(sc[nt], qa[ks], b0, b1);
            }
        }

        // online softmax
        float tm0 = -1e30f, tm1 = -1e30f;
        #pragma unroll
        for (int nt = 0; nt < 8; nt++) {
            tm0 = fmaxf(tm0, fmaxf(sc[nt].x, sc[nt].y));
            tm1 = fmaxf(tm1, fmaxf(sc[nt].z, sc[nt].w));
        }
        tm0 = fmaxf(tm0, __shfl_xor_sync(0xffffffffu, tm0, 1));
        tm0 = fmaxf(tm0, __shfl_xor_sync(0xffffffffu, tm0, 2));
        tm1 = fmaxf(tm1, __shfl_xor_sync(0xffffffffu, tm1, 1));
        tm1 = fmaxf(tm1, __shfl_xor_sync(0xffffffffu, tm1, 2));
        float nm0 = fmaxf(m0, tm0), nm1 = fmaxf(m1, tm1);
        float a0 = __expf(m0 - nm0), a1 = __expf(m1 - nm1);
        float t0 = 0.f, t1 = 0.f;
        float* pr0 = Ps + (16 * w + r) * RV;
        float* pr1 = Ps + (16 * w + r + 8) * RV;
        #pragma unroll
        for (int nt = 0; nt < 8; nt++) {
            float px = __expf(sc[nt].x - nm0), py = __expf(sc[nt].y - nm0);
            float pz = __expf(sc[nt].z - nm1), pw = __expf(sc[nt].w - nm1);
            t0 += px + py; t1 += pz + pw;
            int col = nt * 8 + 2 * k2;
            *(float2*)&pr0[col] = make_float2(px, py);
            *(float2*)&pr1[col] = make_float2(pz, pw);
            o[nt].x *= a0; o[nt].y *= a0;
            o[nt].z *= a1; o[nt].w *= a1;
        }
        t0 += __shfl_xor_sync(0xffffffffu, t0, 1);
        t0 += __shfl_xor_sync(0xffffffffu, t0, 2);
        t1 += __shfl_xor_sync(0xffffffffu, t1, 1);
        t1 += __shfl_xor_sync(0xffffffffu, t1, 2);
        s0 = s0 * a0 + t0;
        s1 = s1 * a1 + t1;
        m0 = nm0; m1 = nm1;
        __syncwarp();

        // O += P V
        #pragma unroll
        for (int ks = 0; ks < 8; ks++) {
            int scol = ks * 8 + k2;
            uint32 a[4];
            a[0] = __float_as_uint(pr0[scol]);
            a[1] = __float_as_uint(pr1[scol]);
            a[2] = __float_as_uint(pr0[scol + 4]);
            a[3] = __float_as_uint(pr1[scol + 4]);
            #pragma unroll
            for (int nt = 0; nt < 8; nt++) {
                uint32 b0 = __float_as_uint(Vs[(nt * 8 + r) * RV + scol]);
                uint32 b1 = __float_as_uint(Vs[(nt * 8 + r) * RV + scol + 4]);
                mma8(o[nt], a, b0, b1);
            }
        }
        __syncthreads();
    }

    // normalize + coalesced write via smem (reuse KB[0])
    float i0 = 1.f / s0, i1 = 1.f / s1;
    float* Os = KB[0];
    #pragma unroll
    for (int nt = 0; nt < 8; nt++) {
        int d0 = nt * 8 + 2 * k2;
        Os[d0 * RQ + 16 * w + r]           = o[nt].x * i0;
        Os[(d0 + 1) * RQ + 16 * w + r]     = o[nt].y * i0;
        Os[d0 * RQ + 16 * w + r + 8]       = o[nt].z * i1;
        Os[(d0 + 1) * RQ + 16 * w + r + 8] = o[nt].w * i1;
    }
    __syncthreads();
    const int cb = n * 192 + h * 64;
    #pragma unroll
    for (int i = 0; i < 8; i++) {
        int d = dr + 8 * i;
        *(float4*)(out + (size_t)(cb + d) * 1024 + q0 + c4) = *(const float4*)&Os[d * RQ + c4];
    }
}

// ---------------------------------------------------------------------------
// Attention pass 2: L=16
// ---------------------------------------------------------------------------
__global__ void k_attn2(const float* __restrict__ qkv, float* __restrict__ out) {
    __shared__ float qs[1024], ks[1024], vs[1024], S[16 * 17];
    int bh = blockIdx.x;
    int n = bh / 3, h = bh % 3;
    const float* B = qkv + (size_t)(n * 576 + h * 192) * 16;
    int tid = threadIdx.x;
    for (int i = tid; i < 1024; i += 256) {
        qs[i] = B[i] * 0.125f;
        ks[i] = B[1024 + i];
        vs[i] = B[2048 + i];
    }
    __syncthreads();
    {
        int q = tid >> 4, s = tid & 15;
        float a = 0.f;
        #pragma unroll
        for (int c = 0; c < 64; c++) a += qs[c * 16 + q] * ks[c * 16 + s];
        S[q * 17 + s] = a;
    }
    __syncthreads();
    if (tid < 16) {
        float* row = S + tid * 17;
        float m = -1e30f;
        #pragma unroll
        for (int s = 0; s < 16; s++) m = fmaxf(m, row[s]);
        float sum = 0.f;
        #pragma unroll
        for (int s = 0; s < 16; s++) { float e = __expf(row[s] - m); row[s] = e; sum += e; }
        float inv = 1.f / sum;
        #pragma unroll
        for (int s = 0; s < 16; s++) row[s] *= inv;
    }
    __syncthreads();
    {
        int q  = tid & 15;
        int cb = (tid >> 4) << 2;
        float a0 = 0.f, a1 = 0.f, a2 = 0.f, a3 = 0.f;
        #pragma unroll
        for (int s = 0; s < 16; s++) {
            float sv = S[q * 17 + s];
            a0 += vs[(cb + 0) * 16 + s] * sv;
            a1 += vs[(cb + 1) * 16 + s] * sv;
            a2 += vs[(cb + 2) * 16 + s] * sv;
            a3 += vs[(cb + 3) * 16 + s] * sv;
        }
        size_t ob = (size_t)(n * 192 + h * 64 + cb) * 16 + q;
        out[ob + 0 * 16] = a0;
        out[ob + 1 * 16] = a1;
        out[ob + 2 * 16] = a2;
        out[ob + 3 * 16] = a3;
    }
}

// ---------------------------------------------------------------------------
extern "C" void kernel_launch(void* const* d_in, const int* in_sizes, int n_in,
                              void* d_out, int out_size) {
    const float* x       = (const float*)d_in[0];
    const float* norm_g  = (const float*)d_in[1];
    const float* norm_b  = (const float*)d_in[2];
    const float* qkv_w   = (const float*)d_in[3];
    const float* qkv_b   = (const float*)d_in[4];
    const float* proj_w  = (const float*)d_in[5];
    const float* proj_b  = (const float*)d_in[6];
    const float* normt_g = (const float*)d_in[7];
    const float* normt_b = (const float*)d_in[8];
    const float* qkvt_w  = (const float*)d_in[9];
    const float* qkvt_b  = (const float*)d_in[10];
    const float* projt_w = (const float*)d_in[11];
    const float* projt_b = (const float*)d_in[12];
    float* out = (float*)d_out;

    float *xs, *nrm, *qkv, *att, *y, *yt;
    cudaGetSymbolAddress((void**)&xs,  g_xs);
    cudaGetSymbolAddress((void**)&nrm, g_nrm);
    cudaGetSymbolAddress((void**)&qkv, g_qkv);
    cudaGetSymbolAddress((void**)&att, g_att);
    cudaGetSymbolAddress((void**)&y,   g_y);
    cudaGetSymbolAddress((void**)&yt,  g_yt);

    cudaFuncSetAttribute(k_attn1, cudaFuncAttributeMaxDynamicSharedMemorySize, ATTN1_SMEM);

    // ---- pass 1 (spatial, L=1024) ----
    k_gn1<<<NBT * 32, 256>>>(x, norm_g, norm_b, nrm);
    k_convT<<<dim3(256, 9), 128>>>(nrm, qkv_w, qkv_b, nullptr, qkv, 192, 576, 10, 0);
    k_attn1<<<dim3(16, 96), 128, ATTN1_SMEM>>>(qkv, att);
    k_convT<<<dim3(256, 3), 128>>>(att, proj_w, proj_b, x, y, 192, 192, 10, 2);

    // ---- pass 2 (temporal, L=16) ----
    k_transpose2t<<<dim3(16, 192, 2), 256>>>();
    k_gn2<<<NBHW, 128>>>(yt, normt_g, normt_b, nrm);
    k_convT<<<dim3(256, 9), 128>>>(nrm, qkvt_w, qkvt_b, nullptr, qkv, 192, 576, 4, 0);
    k_attn2<<<NBHW * 3, 256>>>(qkv, att);
    k_convT<<<dim3(256, 3), 128>>>(att, projt_w, projt_b, yt, xs, 192, 192, 4, 1);
    k_transpose3t<<<dim3(16, 192, 2), 256>>>(out);
}

// round 7
// speedup vs baseline: 8.0277x; 1.2868x over previous
#include <cuda_runtime.h>
#include <math.h>

// Shapes
#define NBT   32
#define CCH   192
#define LHW   1024
#define NTT   16
#define NBHW  2048
#define TOT   (NBT*CCH*LHW)

typedef unsigned long long ull;
typedef unsigned int uint32;

// Scratch
__device__ float g_xs [TOT];           // z (bhw,c,t) in pass2
__device__ float g_nrm[TOT];
__device__ float g_qkv[NBT*3*CCH*LHW];
__device__ float g_att[TOT];
__device__ float g_y  [TOT];
__device__ float g_yt [TOT];

// ---- mma / cp.async helpers ------------------------------------------------
__device__ __forceinline__ void mma8(float4 &c, const uint32* a, uint32 b0, uint32 b1) {
    asm("mma.sync.aligned.m16n8k8.row.col.f32.tf32.tf32.f32 "
        "{%0,%1,%2,%3},{%4,%5,%6,%7},{%8,%9},{%0,%1,%2,%3};"
        : "+f"(c.x), "+f"(c.y), "+f"(c.z), "+f"(c.w)
        : "r"(a[0]), "r"(a[1]), "r"(a[2]), "r"(a[3]), "r"(b0), "r"(b1));
}
__device__ __forceinline__ uint32 sptr(const void* p) {
    return (uint32)__cvta_generic_to_shared(p);
}
__device__ __forceinline__ void cp16(uint32 s, const void* g) {
    asm volatile("cp.async.ca.shared.global [%0], [%1], 16;" :: "r"(s), "l"(g));
}
__device__ __forceinline__ void cp_commit() { asm volatile("cp.async.commit_group;"); }
template<int N> __device__ __forceinline__ void cp_wait() {
    asm volatile("cp.async.wait_group %0;" :: "n"(N));
}

// ---------------------------------------------------------------------------
// GroupNorm pass 1: reads x (b,c,t,hw) directly, writes nrm (bt,c,hw)
// ---------------------------------------------------------------------------
__global__ void k_gn1(const float* __restrict__ x, const float* __restrict__ gam,
                      const float* __restrict__ bet, float* __restrict__ out) {
    int n = blockIdx.x >> 5;         // bt
    int g = blockIdx.x & 31;
    int b = n >> 4, t = n & 15;
    const float* xb = x + (((size_t)(b * CCH + g * 6) * 16 + t) << 10);
    float* ob = out + (size_t)(n * CCH + g * 6) * 1024;
    int tid = threadIdx.x;
    float s = 0.f, q = 0.f;
    for (int i = tid; i < 6144; i += 256) {
        float v = xb[((size_t)(i >> 10) << 14) + (i & 1023)];
        s += v; q += v * v;
    }
    __shared__ float rs[256], rq[256];
    rs[tid] = s; rq[tid] = q;
    __syncthreads();
    for (int st = 128; st > 0; st >>= 1) {
        if (tid < st) { rs[tid] += rs[tid + st]; rq[tid] += rq[tid + st]; }
        __syncthreads();
    }
    float mean = rs[0] / 6144.f;
    float var  = rq[0] / 6144.f - mean * mean;
    float inv  = rsqrtf(var + 1e-5f);
    for (int i = tid; i < 6144; i += 256) {
        int c = g * 6 + (i >> 10);
        float v = xb[((size_t)(i >> 10) << 14) + (i & 1023)];
        ob[i] = (v - mean) * inv * gam[c] + bet[c];
    }
}

// ---------------------------------------------------------------------------
// GroupNorm pass 2: X (bhw,c,t), one block per n.
// ---------------------------------------------------------------------------
__global__ void k_gn2(const float* __restrict__ X, const float* __restrict__ gam,
                      const float* __restrict__ bet, float* __restrict__ out) {
    int n = blockIdx.x;
    __shared__ float buf[3072];
    __shared__ float mu[32], iv[32];
    int tid = threadIdx.x;
    const float4* xb = (const float4*)(X + (size_t)n * 3072);
    #pragma unroll
    for (int i = tid; i < 768; i += 128) ((float4*)buf)[i] = xb[i];
    __syncthreads();
    int w = tid >> 5, lane = tid & 31;
    for (int g = w; g < 32; g += 4) {
        float v0 = buf[g * 96 + lane], v1 = buf[g * 96 + 32 + lane], v2 = buf[g * 96 + 64 + lane];
        float s = v0 + v1 + v2, q = v0 * v0 + v1 * v1 + v2 * v2;
        #pragma unroll
        for (int off = 16; off; off >>= 1) {
            s += __shfl_xor_sync(0xffffffffu, s, off);
            q += __shfl_xor_sync(0xffffffffu, q, off);
        }
        if (lane == 0) {
            float m = s / 96.f, va = q / 96.f - m * m;
            mu[g] = m; iv[g] = rsqrtf(va + 1e-5f);
        }
    }
    __syncthreads();
    float* ob = out + (size_t)n * 3072;
    for (int i = tid; i < 3072; i += 128) {
        int c = i >> 4, g = c / 6;
        ob[i] = (buf[i] - mu[g]) * iv[g] * gam[c] + bet[c];
    }
}

// ---------------------------------------------------------------------------
// Tiled transposes
// ---------------------------------------------------------------------------
__global__ void k_transpose2t() {   // y (bt,c,hw) -> yt (bhw,c,t)
    __shared__ float sm[64][20];
    int hw0 = blockIdx.x * 64, c = blockIdx.y, b = blockIdx.z;
    int tid = threadIdx.x;
    {
        int t = tid & 15, hwj = (tid >> 4) * 4;
        float4 v = *(const float4*)&g_y[(((size_t)(b * 16 + t) * CCH + c) << 10) + hw0 + hwj];
        sm[hwj + 0][t] = v.x; sm[hwj + 1][t] = v.y;
        sm[hwj + 2][t] = v.z; sm[hwj + 3][t] = v.w;
    }
    __syncthreads();
    {
        int hwl = tid >> 2, t4 = (tid & 3) * 4;
        *(float4*)&g_yt[((size_t)(b * 1024 + hw0 + hwl) * CCH + c) * 16 + t4] =
            *(const float4*)&sm[hwl][t4];
    }
}

__global__ void k_transpose3t(float* __restrict__ out) {  // z (bhw,c,t) -> (b,c,t,hw)
    __shared__ float sm[16][68];
    int hw0 = blockIdx.x * 64, c = blockIdx.y, b = blockIdx.z;
    int tid = threadIdx.x;
    {
        int hwl = tid >> 2, t4 = (tid & 3) * 4;
        float4 v = *(const float4*)&g_xs[((size_t)(b * 1024 + hw0 + hwl) * CCH + c) * 16 + t4];
        sm[t4 + 0][hwl] = v.x; sm[t4 + 1][hwl] = v.y;
        sm[t4 + 2][hwl] = v.z; sm[t4 + 3][hwl] = v.w;
    }
    __syncthreads();
    {
        int t = tid >> 4, hw4 = (tid & 15) * 4;
        *(float4*)&out[(((size_t)(b * CCH + c) * 16 + t) << 10) + hw0 + hw4] =
            *(const float4*)&sm[t][hw4];
    }
}

// ---------------------------------------------------------------------------
// 1x1 conv, tf32 MMA, cp.async double buffered.
// Block 128 thr / 4 warps; tile 64 o x 128 cols; warp tile 32 o x 64 cols.
// Xs stride 136 (mod32=8 -> B loads conflict-free), Ws stride 20 (A conflict-free).
// resmode: 0 none, 1 same layout, 2 x layout (b,C,t,hw)
// ---------------------------------------------------------------------------
#define XP 136
#define WPD 20

__global__ __launch_bounds__(128, 3) void k_convT(
    const float* __restrict__ X, const float* __restrict__ W,
    const float* __restrict__ bias, const float* __restrict__ res,
    float* __restrict__ out, int Cin, int Cout, int ls, int resmode) {
    __shared__ float Xs[2][16][XP];
    __shared__ float Ws[2][64][WPD];
    const int L = 1 << ls, Lm1 = L - 1;
    const int tid = threadIdx.x;
    const int lane = tid & 31, w = tid >> 5;
    const int r = lane >> 2, k2 = lane & 3;
    const int g0 = blockIdx.x * 128;
    const int o0 = blockIdx.y * 64;
    const int ob0 = 32 * (w >> 1);        // warp o base (0 or 32)
    const int coff = (w & 1) * 64;        // warp col base

    float4 acc[2][8];
    #pragma unroll
    for (int ms = 0; ms < 2; ms++)
        #pragma unroll
        for (int nt = 0; nt < 8; nt++) acc[ms][nt] = make_float4(0.f, 0.f, 0.f, 0.f);

    const int xk  = tid >> 5;         // + 4*i
    const int xc4 = (tid & 31) * 4;
    const int wo  = tid & 63;
    const int wk4 = (tid >> 6) * 4;   // + 8*i

    const int nch = Cin >> 4;

    {   // prologue: chunk 0
        #pragma unroll
        for (int i = 0; i < 4; i++) {
            int k = xk + 4 * i;
            int g = g0 + xc4;
            cp16(sptr(&Xs[0][k][xc4]), X + ((size_t)(g >> ls) * Cin + k) * L + (g & Lm1));
        }
        #pragma unroll
        for (int i = 0; i < 2; i++) {
            int k4 = wk4 + 8 * i;
            cp16(sptr(&Ws[0][wo][k4]), W + (size_t)(o0 + wo) * Cin + k4);
        }
        cp_commit();
    }

    for (int c = 0; c < nch; c++) {
        const int buf = c & 1;
        if (c + 1 < nch) {
            const int cc = (c + 1) << 4;
            #pragma unroll
            for (int i = 0; i < 4; i++) {
                int k = xk + 4 * i;
                int g = g0 + xc4;
                cp16(sptr(&Xs[buf ^ 1][k][xc4]),
                     X + ((size_t)(g >> ls) * Cin + cc + k) * L + (g & Lm1));
            }
            #pragma unroll
            for (int i = 0; i < 2; i++) {
                int k4 = wk4 + 8 * i;
                cp16(sptr(&Ws[buf ^ 1][wo][k4]), W + (size_t)(o0 + wo) * Cin + cc + k4);
            }
            cp_commit();
            cp_wait<1>();
        } else {
            cp_wait<0>();
        }
        __syncthreads();
        #pragma unroll
        for (int kc = 0; kc < 16; kc += 8) {
            uint32 a0[4], a1[4];
            a0[0] = __float_as_uint(Ws[buf][ob0 + r]     [kc + k2]);
            a0[1] = __float_as_uint(Ws[buf][ob0 + r + 8] [kc + k2]);
            a0[2] = __float_as_uint(Ws[buf][ob0 + r]     [kc + k2 + 4]);
            a0[3] = __float_as_uint(Ws[buf][ob0 + r + 8] [kc + k2 + 4]);
            a1[0] = __float_as_uint(Ws[buf][ob0 + 16 + r]    [kc + k2]);
            a1[1] = __float_as_uint(Ws[buf][ob0 + 24 + r]    [kc + k2]);
            a1[2] = __float_as_uint(Ws[buf][ob0 + 16 + r]    [kc + k2 + 4]);
            a1[3] = __float_as_uint(Ws[buf][ob0 + 24 + r]    [kc + k2 + 4]);
            #pragma unroll
            for (int nt = 0; nt < 8; nt++) {
                uint32 b0 = __float_as_uint(Xs[buf][kc + k2]    [coff + nt * 8 + r]);
                uint32 b1 = __float_as_uint(Xs[buf][kc + k2 + 4][coff + nt * 8 + r]);
                mma8(acc[0][nt], a0, b0, b1);
                mma8(acc[1][nt], a1, b0, b1);
            }
        }
        __syncthreads();
    }

    // epilogue
    #pragma unroll
    for (int ms = 0; ms < 2; ms++) {
        const int oa = o0 + ob0 + 16 * ms + r;
        const int obr = oa + 8;
        const float ba = bias[oa], bb = bias[obr];
        #pragma unroll
        for (int nt = 0; nt < 8; nt++) {
            int g = g0 + coff + nt * 8 + 2 * k2;
            int n = g >> ls, l = g & Lm1;
            size_t pa = ((size_t)n * Cout + oa) * L + l;
            size_t pb = ((size_t)n * Cout + obr) * L + l;
            float2 va = make_float2(acc[ms][nt].x + ba, acc[ms][nt].y + ba);
            float2 vb = make_float2(acc[ms][nt].z + bb, acc[ms][nt].w + bb);
            if (resmode == 1) {
                float2 qa = *(const float2*)(res + pa);
                float2 qb = *(const float2*)(res + pb);
                va.x += qa.x; va.y += qa.y; vb.x += qb.x; vb.y += qb.y;
            } else if (resmode == 2) {
                int b = n >> 4, t = n & 15;
                size_t xa = (((size_t)(b * 192 + oa) * 16 + t) << 10) + l;
                size_t xb = (((size_t)(b * 192 + obr) * 16 + t) << 10) + l;
                float2 qa = *(const float2*)(res + xa);
                float2 qb = *(const float2*)(res + xb);
                va.x += qa.x; va.y += qa.y; vb.x += qb.x; vb.y += qb.y;
            }
            *(float2*)(out + pa) = va;
            *(float2*)(out + pb) = vb;
        }
    }
}

// ---------------------------------------------------------------------------
// Attention pass 1: flash tf32 MMA; K double-buffered, V single-buffered,
// Q staging unioned with P. 71 KB smem -> 3 CTAs/SM.
// ---------------------------------------------------------------------------
#define RQ 72
#define RV 68
#define U_FLOATS  (64*RQ)                 // 4608 (Q staging, then P[64][RV])
#define ATTN1_SMEM ((U_FLOATS + 2*64*RQ + 64*RV) * 4)   // 72704 B

__global__ __launch_bounds__(128, 3) void k_attn1(const float* __restrict__ qkv,
                                                  float* __restrict__ out) {
    extern __shared__ float sm[];
    float* U  = sm;                        // Q staging then P
    float* K0 = sm + U_FLOATS;
    float* K1 = K0 + 64 * RQ;
    float* Vs = K1 + 64 * RQ;

    const int tid  = threadIdx.x;
    const int lane = tid & 31, w = tid >> 5;
    const int r  = lane >> 2;
    const int k2 = lane & 3;
    const int bh = blockIdx.y;
    const int n = bh / 3, h = bh % 3;
    const int q0 = blockIdx.x * 64;
    const float* Q = qkv + (size_t)(n * 576 + h * 192) * 1024;
    const float* K = Q + 64 * 1024;
    const float* V = Q + 128 * 1024;

    const int dr = tid >> 4, c4 = (tid & 15) * 4;

    // prologue: stage K tile 0
    #pragma unroll
    for (int i = 0; i < 8; i++) {
        int d = dr + 8 * i;
        cp16(sptr(&K0[d * RQ + c4]), K + d * 1024 + c4);
    }
    cp_commit();

    // stage Q into U (scale folded)
    #pragma unroll
    for (int i = 0; i < 8; i++) {
        int d = dr + 8 * i;
        float4 v = *(const float4*)(Q + d * 1024 + q0 + c4);
        *(float4*)&U[d * RQ + c4] = make_float4(v.x * 0.125f, v.y * 0.125f,
                                                v.z * 0.125f, v.w * 0.125f);
    }
    __syncthreads();

    uint32 qa[8][4];
    #pragma unroll
    for (int ks = 0; ks < 8; ks++) {
        int d0 = ks * 8 + k2;
        qa[ks][0] = __float_as_uint(U[d0 * RQ + 16 * w + r]);
        qa[ks][1] = __float_as_uint(U[d0 * RQ + 16 * w + r + 8]);
        qa[ks][2] = __float_as_uint(U[(d0 + 4) * RQ + 16 * w + r]);
        qa[ks][3] = __float_as_uint(U[(d0 + 4) * RQ + 16 * w + r + 8]);
    }

    float4 o[8];
    #pragma unroll
    for (int nt = 0; nt < 8; nt++) o[nt] = make_float4(0.f, 0.f, 0.f, 0.f);
    float m0 = -1e30f, m1 = -1e30f, s0 = 0.f, s1 = 0.f;

    float* pr0 = U + (16 * w + r) * RV;
    float* pr1 = U + (16 * w + r + 8) * RV;

    for (int kt = 0; kt < 16; kt++) {
        const int buf = kt & 1;
        // stage V(kt) (group A)
        {
            const int sb = kt * 64;
            #pragma unroll
            for (int i = 0; i < 8; i++) {
                int d = dr + 8 * i;
                cp16(sptr(&Vs[d * RV + c4]), V + d * 1024 + sb + c4);
            }
            cp_commit();
        }
        // stage K(kt+1) (group B, possibly empty)
        if (kt < 15) {
            const int sb = (kt + 1) * 64;
            float* Kn = buf ? K0 : K1;
            #pragma unroll
            for (int i = 0; i < 8; i++) {
                int d = dr + 8 * i;
                cp16(sptr(&Kn[d * RQ + c4]), K + d * 1024 + sb + c4);
            }
        }
        cp_commit();
        cp_wait<2>();            // K(kt) complete
        __syncthreads();
        const float* Ks = buf ? K1 : K0;

        // S = Q K^T
        float4 sc[8];
        #pragma unroll
        for (int nt = 0; nt < 8; nt++) sc[nt] = make_float4(0.f, 0.f, 0.f, 0.f);
        #pragma unroll
        for (int ks = 0; ks < 8; ks++) {
            int d0 = ks * 8 + k2;
            const float* kr0 = Ks + d0 * RQ + r;
            const float* kr1 = Ks + (d0 + 4) * RQ + r;
            #pragma unroll
            for (int nt = 0; nt < 8; nt++) {
                uint32 b0 = __float_as_uint(kr0[nt * 8]);
                uint32 b1 = __float_as_uint(kr1[nt * 8]);
                mma8(sc[nt], qa[ks], b0, b1);
            }
        }

        // online softmax (writes P into U)
        float tm0 = -1e30f, tm1 = -1e30f;
        #pragma unroll
        for (int nt = 0; nt < 8; nt++) {
            tm0 = fmaxf(tm0, fmaxf(sc[nt].x, sc[nt].y));
            tm1 = fmaxf(tm1, fmaxf(sc[nt].z, sc[nt].w));
        }
        tm0 = fmaxf(tm0, __shfl_xor_sync(0xffffffffu, tm0, 1));
        tm0 = fmaxf(tm0, __shfl_xor_sync(0xffffffffu, tm0, 2));
        tm1 = fmaxf(tm1, __shfl_xor_sync(0xffffffffu, tm1, 1));
        tm1 = fmaxf(tm1, __shfl_xor_sync(0xffffffffu, tm1, 2));
        float nm0 = fmaxf(m0, tm0), nm1 = fmaxf(m1, tm1);
        float a0 = __expf(m0 - nm0), a1 = __expf(m1 - nm1);
        float t0 = 0.f, t1 = 0.f;
        #pragma unroll
        for (int nt = 0; nt < 8; nt++) {
            float px = __expf(sc[nt].x - nm0), py = __expf(sc[nt].y - nm0);
            float pz = __expf(sc[nt].z - nm1), pw = __expf(sc[nt].w - nm1);
            t0 += px + py; t1 += pz + pw;
            int col = nt * 8 + 2 * k2;
            *(float2*)&pr0[col] = make_float2(px, py);
            *(float2*)&pr1[col] = make_float2(pz, pw);
            o[nt].x *= a0; o[nt].y *= a0;
            o[nt].z *= a1; o[nt].w *= a1;
        }
        t0 += __shfl_xor_sync(0xffffffffu, t0, 1);
        t0 += __shfl_xor_sync(0xffffffffu, t0, 2);
        t1 += __shfl_xor_sync(0xffffffffu, t1, 1);
        t1 += __shfl_xor_sync(0xffffffffu, t1, 2);
        s0 = s0 * a0 + t0;
        s1 = s1 * a1 + t1;
        m0 = nm0; m1 = nm1;

        cp_wait<1>();            // V(kt) complete (only K(kt+1) may pend)
        __syncthreads();

        // O += P V
        #pragma unroll
        for (int ks = 0; ks < 8; ks++) {
            int scol = ks * 8 + k2;
            uint32 a[4];
            a[0] = __float_as_uint(pr0[scol]);
            a[1] = __float_as_uint(pr1[scol]);
            a[2] = __float_as_uint(pr0[scol + 4]);
            a[3] = __float_as_uint(pr1[scol + 4]);
            #pragma unroll
            for (int nt = 0; nt < 8; nt++) {
                uint32 b0 = __float_as_uint(Vs[(nt * 8 + r) * RV + scol]);
                uint32 b1 = __float_as_uint(Vs[(nt * 8 + r) * RV + scol + 4]);
                mma8(o[nt], a, b0, b1);
            }
        }
        __syncthreads();         // protect V (single buffer) and K (reuse)
    }

    // normalize + coalesced write via K0
    float i0 = 1.f / s0, i1 = 1.f / s1;
    float* Os = K0;
    #pragma unroll
    for (int nt = 0; nt < 8; nt++) {
        int d0 = nt * 8 + 2 * k2;
        Os[d0 * RQ + 16 * w + r]           = o[nt].x * i0;
        Os[(d0 + 1) * RQ + 16 * w + r]     = o[nt].y * i0;
        Os[d0 * RQ + 16 * w + r + 8]       = o[nt].z * i1;
        Os[(d0 + 1) * RQ + 16 * w + r + 8] = o[nt].w * i1;
    }
    __syncthreads();
    const int cb = n * 192 + h * 64;
    #pragma unroll
    for (int i = 0; i < 8; i++) {
        int d = dr + 8 * i;
        *(float4*)(out + (size_t)(cb + d) * 1024 + q0 + c4) = *(const float4*)&Os[d * RQ + c4];
    }
}

// ---------------------------------------------------------------------------
// Attention pass 2: L=16
// ---------------------------------------------------------------------------
__global__ void k_attn2(const float* __restrict__ qkv, float* __restrict__ out) {
    __shared__ float qs[1024], ks[1024], vs[1024], S[16 * 17];
    int bh = blockIdx.x;
    int n = bh / 3, h = bh % 3;
    const float* B = qkv + (size_t)(n * 576 + h * 192) * 16;
    int tid = threadIdx.x;
    for (int i = tid; i < 1024; i += 256) {
        qs[i] = B[i] * 0.125f;
        ks[i] = B[1024 + i];
        vs[i] = B[2048 + i];
    }
    __syncthreads();
    {
        int q = tid >> 4, s = tid & 15;
        float a = 0.f;
        #pragma unroll
        for (int c = 0; c < 64; c++) a += qs[c * 16 + q] * ks[c * 16 + s];
        S[q * 17 + s] = a;
    }
    __syncthreads();
    if (tid < 16) {
        float* row = S + tid * 17;
        float m = -1e30f;
        #pragma unroll
        for (int s = 0; s < 16; s++) m = fmaxf(m, row[s]);
        float sum = 0.f;
        #pragma unroll
        for (int s = 0; s < 16; s++) { float e = __expf(row[s] - m); row[s] = e; sum += e; }
        float inv = 1.f / sum;
        #pragma unroll
        for (int s = 0; s < 16; s++) row[s] *= inv;
    }
    __syncthreads();
    {
        int q  = tid & 15;
        int cb = (tid >> 4) << 2;
        float a0 = 0.f, a1 = 0.f, a2 = 0.f, a3 = 0.f;
        #pragma unroll
        for (int s = 0; s < 16; s++) {
            float sv = S[q * 17 + s];
            a0 += vs[(cb + 0) * 16 + s] * sv;
            a1 += vs[(cb + 1) * 16 + s] * sv;
            a2 += vs[(cb + 2) * 16 + s] * sv;
            a3 += vs[(cb + 3) * 16 + s] * sv;
        }
        size_t ob = (size_t)(n * 192 + h * 64 + cb) * 16 + q;
        out[ob + 0 * 16] = a0;
        out[ob + 1 * 16] = a1;
        out[ob + 2 * 16] = a2;
        out[ob + 3 * 16] = a3;
    }
}

// ---------------------------------------------------------------------------
extern "C" void kernel_launch(void* const* d_in, const int* in_sizes, int n_in,
                              void* d_out, int out_size) {
    const float* x       = (const float*)d_in[0];
    const float* norm_g  = (const float*)d_in[1];
    const float* norm_b  = (const float*)d_in[2];
    const float* qkv_w   = (const float*)d_in[3];
    const float* qkv_b   = (const float*)d_in[4];
    const float* proj_w  = (const float*)d_in[5];
    const float* proj_b  = (const float*)d_in[6];
    const float* normt_g = (const float*)d_in[7];
    const float* normt_b = (const float*)d_in[8];
    const float* qkvt_w  = (const float*)d_in[9];
    const float* qkvt_b  = (const float*)d_in[10];
    const float* projt_w = (const float*)d_in[11];
    const float* projt_b = (const float*)d_in[12];
    float* out = (float*)d_out;

    float *xs, *nrm, *qkv, *att, *y, *yt;
    cudaGetSymbolAddress((void**)&xs,  g_xs);
    cudaGetSymbolAddress((void**)&nrm, g_nrm);
    cudaGetSymbolAddress((void**)&qkv, g_qkv);
    cudaGetSymbolAddress((void**)&att, g_att);
    cudaGetSymbolAddress((void**)&y,   g_y);
    cudaGetSymbolAddress((void**)&yt,  g_yt);

    cudaFuncSetAttribute(k_attn1, cudaFuncAttributeMaxDynamicSharedMemorySize, ATTN1_SMEM);

    // ---- pass 1 (spatial, L=1024) ----
    k_gn1<<<NBT * 32, 256>>>(x, norm_g, norm_b, nrm);
    k_convT<<<dim3(256, 9), 128>>>(nrm, qkv_w, qkv_b, nullptr, qkv, 192, 576, 10, 0);
    k_attn1<<<dim3(16, 96), 128, ATTN1_SMEM>>>(qkv, att);
    k_convT<<<dim3(256, 3), 128>>>(att, proj_w, proj_b, x, y, 192, 192, 10, 2);

    // ---- pass 2 (temporal, L=16) ----
    k_transpose2t<<<dim3(16, 192, 2), 256>>>();
    k_gn2<<<NBHW, 128>>>(yt, normt_g, normt_b, nrm);
    k_convT<<<dim3(256, 9), 128>>>(nrm, qkvt_w, qkvt_b, nullptr, qkv, 192, 576, 4, 0);
    k_attn2<<<NBHW * 3, 256>>>(qkv, att);
    k_convT<<<dim3(256, 3), 128>>>(att, projt_w, projt_b, yt, xs, 192, 192, 4, 1);
    k_transpose3t<<<dim3(16, 192, 2), 256>>>(out);
}

// round 10
// speedup vs baseline: 9.2338x; 1.1502x over previous
#include <cuda_runtime.h>
#include <cuda_fp16.h>
#include <math.h>

#define NBT 32
#define CCH 192
#define TOT (NBT*CCH*1024)
typedef unsigned int uint32;

// fp32 scratch
__device__ float g_xs [TOT];          // z (bhw,c,t) in pass2
__device__ float g_y  [TOT];
__device__ float g_yt [TOT];
__device__ float g_stat[NBT*32*2];
// fp16 scratch
__device__ __half g_nrm16[32768*192];
__device__ __half g_qk16 [32768*384];
__device__ __half g_v16T [32768*192];
__device__ __half g_att16[32768*192];
__device__ __half g_w16  [294912];

// ---- helpers ----------------------------------------------------------------
__device__ __forceinline__ void mmah(float4 &c, const uint32* a, uint32 b0, uint32 b1) {
    asm("mma.sync.aligned.m16n8k16.row.col.f32.f16.f16.f32 "
        "{%0,%1,%2,%3},{%4,%5,%6,%7},{%8,%9},{%0,%1,%2,%3};"
        : "+f"(c.x), "+f"(c.y), "+f"(c.z), "+f"(c.w)
        : "r"(a[0]), "r"(a[1]), "r"(a[2]), "r"(a[3]), "r"(b0), "r"(b1));
}
__device__ __forceinline__ uint32 sptr(const void* p) {
    return (uint32)__cvta_generic_to_shared(p);
}
__device__ __forceinline__ void cp16(uint32 s, const void* g) {
    asm volatile("cp.async.ca.shared.global [%0], [%1], 16;" :: "r"(s), "l"(g));
}
__device__ __forceinline__ void cp_commit() { asm volatile("cp.async.commit_group;"); }
template<int N> __device__ __forceinline__ void cp_wait() {
    asm volatile("cp.async.wait_group %0;" :: "n"(N));
}

// ---------------------------------------------------------------------------
// Weight fp16 prep (294912 elems exactly = 288 * 1024)
// ---------------------------------------------------------------------------
__global__ void k_wprep(const float* __restrict__ qw, const float* __restrict__ pw,
                        const float* __restrict__ qtw, const float* __restrict__ ptw) {
    int i = blockIdx.x * 1024 + threadIdx.x;
    float v;
    if      (i < 110592) v = qw[i];
    else if (i < 147456) v = pw[i - 110592];
    else if (i < 258048) v = qtw[i - 147456];
    else                 v = ptw[i - 258048];
    g_w16[i] = __float2half(v);
}

// ---------------------------------------------------------------------------
// GroupNorm pass 1 stats: grid (32 bt x 32 g)
// ---------------------------------------------------------------------------
__global__ void k_gn1s(const float* __restrict__ x) {
    int n = blockIdx.x >> 5, g = blockIdx.x & 31;
    int b = n >> 4, t = n & 15;
    const float* xb = x + (((size_t)(b * CCH + g * 6) * 16 + t) << 10);
    int tid = threadIdx.x;
    float s = 0.f, q = 0.f;
    for (int i = tid; i < 6144; i += 256) {
        float v = xb[((size_t)(i >> 10) << 14) + (i & 1023)];
        s += v; q += v * v;
    }
    __shared__ float rs[256], rq[256];
    rs[tid] = s; rq[tid] = q;
    __syncthreads();
    for (int st = 128; st > 0; st >>= 1) {
        if (tid < st) { rs[tid] += rs[tid + st]; rq[tid] += rq[tid + st]; }
        __syncthreads();
    }
    if (tid == 0) {
        float mean = rs[0] / 6144.f;
        float var  = rq[0] / 6144.f - mean * mean;
        g_stat[blockIdx.x * 2]     = mean;
        g_stat[blockIdx.x * 2 + 1] = rsqrtf(var + 1e-5f);
    }
}

// apply: one thread per token, writes channel-last half
__global__ void k_gn1a(const float* __restrict__ x, const float* __restrict__ gam,
                       const float* __restrict__ bet) {
    int token = blockIdx.x * 256 + threadIdx.x;
    int bt = token >> 10, hw = token & 1023;
    int b = bt >> 4, t = bt & 15;
    int sb = bt * 32;
    __half* o = g_nrm16 + (size_t)token * 192;
    for (int g = 0; g < 32; g++) {
        float mu = g_stat[(sb + g) * 2], iv = g_stat[(sb + g) * 2 + 1];
        const float* xc = x + (((size_t)(b * CCH + g * 6) * 16 + t) << 10) + hw;
        #pragma unroll
        for (int j = 0; j < 6; j += 2) {
            int c = g * 6 + j;
            float v0 = xc[(size_t)j << 14], v1 = xc[(size_t)(j + 1) << 14];
            __half2 hh = __floats2half2_rn((v0 - mu) * iv * gam[c] + bet[c],
                                           (v1 - mu) * iv * gam[c + 1] + bet[c + 1]);
            *(__half2*)(o + c) = hh;
        }
    }
}

// ---------------------------------------------------------------------------
// GroupNorm pass 2: X (bhw,c,t) fp32, one block per n; out half channel-last
// ---------------------------------------------------------------------------
__global__ void k_gn2h(const float* __restrict__ X, const float* __restrict__ gam,
                       const float* __restrict__ bet, __half* __restrict__ out16) {
    int n = blockIdx.x;
    __shared__ float buf[3072];
    __shared__ float mu[32], iv[32];
    int tid = threadIdx.x;
    const float4* xb = (const float4*)(X + (size_t)n * 3072);
    for (int i = tid; i < 768; i += 128) ((float4*)buf)[i] = xb[i];
    __syncthreads();
    int w = tid >> 5, lane = tid & 31;
    for (int g = w; g < 32; g += 4) {
        float v0 = buf[g * 96 + lane], v1 = buf[g * 96 + 32 + lane], v2 = buf[g * 96 + 64 + lane];
        float s = v0 + v1 + v2, q = v0 * v0 + v1 * v1 + v2 * v2;
        #pragma unroll
        for (int off = 16; off; off >>= 1) {
            s += __shfl_xor_sync(0xffffffffu, s, off);
            q += __shfl_xor_sync(0xffffffffu, q, off);
        }
        if (lane == 0) {
            float m = s / 96.f, va = q / 96.f - m * m;
            mu[g] = m; iv[g] = rsqrtf(va + 1e-5f);
        }
    }
    __syncthreads();
    __half* ob = out16 + (size_t)n * 3072;
    for (int j = tid; j < 3072; j += 128) {
        int t = j / 192, c = j - t * 192;
        int g = c / 6;
        ob[j] = __float2half((buf[c * 16 + t] - mu[g]) * iv[g] * gam[c] + bet[c]);
    }
}

// ---------------------------------------------------------------------------
// Tiled fp32 transposes
// ---------------------------------------------------------------------------
__global__ void k_transpose2t() {   // y (bt,c,hw) -> yt (bhw,c,t)
    __shared__ float sm[64][20];
    int hw0 = blockIdx.x * 64, c = blockIdx.y, b = blockIdx.z;
    int tid = threadIdx.x;
    {
        int t = tid & 15, hwj = (tid >> 4) * 4;
        float4 v = *(const float4*)&g_y[(((size_t)(b * 16 + t) * CCH + c) << 10) + hw0 + hwj];
        sm[hwj + 0][t] = v.x; sm[hwj + 1][t] = v.y;
        sm[hwj + 2][t] = v.z; sm[hwj + 3][t] = v.w;
    }
    __syncthreads();
    {
        int hwl = tid >> 2, t4 = (tid & 3) * 4;
        *(float4*)&g_yt[((size_t)(b * 1024 + hw0 + hwl) * CCH + c) * 16 + t4] =
            *(const float4*)&sm[hwl][t4];
    }
}

__global__ void k_transpose3t(float* __restrict__ out) {  // z (bhw,c,t) -> (b,c,t,hw)
    __shared__ float sm[16][68];
    int hw0 = blockIdx.x * 64, c = blockIdx.y, b = blockIdx.z;
    int tid = threadIdx.x;
    {
        int hwl = tid >> 2, t4 = (tid & 3) * 4;
        float4 v = *(const float4*)&g_xs[((size_t)(b * 1024 + hw0 + hwl) * CCH + c) * 16 + t4];
        sm[t4 + 0][hwl] = v.x; sm[t4 + 1][hwl] = v.y;
        sm[t4 + 2][hwl] = v.z; sm[t4 + 3][hwl] = v.w;
    }
    __syncthreads();
    {
        int t = tid >> 4, hw4 = (tid & 15) * 4;
        *(float4*)&out[(((size_t)(b * CCH + c) * 16 + t) << 10) + hw0 + hw4] =
            *(const float4*)&sm[t][hw4];
    }
}

// ---------------------------------------------------------------------------
// 1x1 conv, fp16 MMA (m16n8k16), cp.async double buffered, K-chunks of 32.
// X channel-last [token][192] half, W [o][192] half.
// mode 0 (qkv): out channel o = 192h + 64p + c:
//   p<2 -> qk16[token][h*128 + 64p + c];  p=2 -> v16T[img][h*64+c][tok]
// mode 1: fp32 + res same layout; mode 2: fp32 + res x-layout
// ---------------------------------------------------------------------------
#define CHS 40

__global__ __launch_bounds__(128, 4) void k_convh(
    const __half* __restrict__ X, const __half* __restrict__ W,
    const float* __restrict__ bias, const float* __restrict__ res,
    float* __restrict__ outf, __half* __restrict__ outqk, __half* __restrict__ outv,
    int Cout, int ls, int mode) {
    __shared__ __align__(16) __half Xs[2][128][CHS];
    __shared__ __align__(16) __half Ws[2][64][CHS];
    const int tid = threadIdx.x, lane = tid & 31, w = tid >> 5;
    const int r = lane >> 2, tg = lane & 3;
    const int g0 = blockIdx.x * 128, o0 = blockIdx.y * 64;
    const int ob0 = 32 * (w >> 1), coff = (w & 1) * 64;
    const int L = 1 << ls, Lm1 = L - 1;

    float4 acc[2][8];
    #pragma unroll
    for (int ms = 0; ms < 2; ms++)
        #pragma unroll
        for (int nt = 0; nt < 8; nt++) acc[ms][nt] = make_float4(0.f, 0.f, 0.f, 0.f);

    const __half* xsrc = X + (size_t)(g0 + tid) * 192;
    const int wo = tid & 63, wp = (tid >> 6) * 16;
    const __half* wsrc = W + (size_t)(o0 + wo) * 192 + wp;

    // prologue chunk 0
    #pragma unroll
    for (int j = 0; j < 4; j++) cp16(sptr(&Xs[0][tid][j * 8]), xsrc + j * 8);
    #pragma unroll
    for (int j = 0; j < 2; j++) cp16(sptr(&Ws[0][wo][wp + j * 8]), wsrc + j * 8);
    cp_commit();

    for (int c = 0; c < 6; c++) {
        const int buf = c & 1;
        if (c < 5) {
            const int cc = (c + 1) * 32;
            #pragma unroll
            for (int j = 0; j < 4; j++)
                cp16(sptr(&Xs[buf ^ 1][tid][j * 8]), xsrc + cc + j * 8);
            #pragma unroll
            for (int j = 0; j < 2; j++)
                cp16(sptr(&Ws[buf ^ 1][wo][wp + j * 8]), wsrc + cc + j * 8);
            cp_commit();
            cp_wait<1>();
        } else {
            cp_wait<0>();
        }
        __syncthreads();
        #pragma unroll
        for (int ks = 0; ks < 2; ks++) {
            const int kb = ks * 16 + 2 * tg;
            uint32 a0[4], a1[4];
            a0[0] = *(const uint32*)&Ws[buf][ob0 + r]     [kb];
            a0[1] = *(const uint32*)&Ws[buf][ob0 + r + 8] [kb];
            a0[2] = *(const uint32*)&Ws[buf][ob0 + r]     [kb + 8];
            a0[3] = *(const uint32*)&Ws[buf][ob0 + r + 8] [kb + 8];
            a1[0] = *(const uint32*)&Ws[buf][ob0 + 16 + r][kb];
            a1[1] = *(const uint32*)&Ws[buf][ob0 + 24 + r][kb];
            a1[2] = *(const uint32*)&Ws[buf][ob0 + 16 + r][kb + 8];
            a1[3] = *(const uint32*)&Ws[buf][ob0 + 24 + r][kb + 8];
            #pragma unroll
            for (int nt = 0; nt < 8; nt++) {
                uint32 b0 = *(const uint32*)&Xs[buf][coff + nt * 8 + r][kb];
                uint32 b1 = *(const uint32*)&Xs[buf][coff + nt * 8 + r][kb + 8];
                mmah(acc[0][nt], a0, b0, b1);
                mmah(acc[1][nt], a1, b0, b1);
            }
        }
        __syncthreads();
    }

    // epilogue
    #pragma unroll
    for (int ms = 0; ms < 2; ms++) {
        const int oa = o0 + ob0 + 16 * ms + r;
        const int obr = oa + 8;
        const float ba = bias[oa], bb = bias[obr];
        // head decomposition (valid for mode 0): oa = 192*ha + 64*pa + ca
        const int ha = oa / 192;
        const int rem = oa - ha * 192;
        const int pa = rem >> 6;
        const int ca = rem & 63;
        #pragma unroll
        for (int nt = 0; nt < 8; nt++) {
            int g = g0 + coff + nt * 8 + 2 * tg;
            float vax = acc[ms][nt].x + ba, vay = acc[ms][nt].y + ba;
            float vbx = acc[ms][nt].z + bb, vby = acc[ms][nt].w + bb;
            if (mode == 0) {
                if (pa < 2) {  // Q or K -> qk16 channel-last [token][384]
                    int idx = ha * 128 + pa * 64 + ca;
                    outqk[(size_t)g * 384 + idx]           = __float2half(vax);
                    outqk[(size_t)(g + 1) * 384 + idx]     = __float2half(vay);
                    outqk[(size_t)g * 384 + idx + 8]       = __float2half(vbx);
                    outqk[(size_t)(g + 1) * 384 + idx + 8] = __float2half(vby);
                } else {       // V -> d-major [img][h*64+c][tok]
                    int img = g >> ls, tok = g & Lm1;
                    int cv = ha * 64 + ca;
                    *(__half2*)(outv + ((size_t)img * 192 + cv) * L + tok) =
                        __floats2half2_rn(vax, vay);
                    *(__half2*)(outv + ((size_t)img * 192 + cv + 8) * L + tok) =
                        __floats2half2_rn(vbx, vby);
                }
            } else {
                int n = g >> ls, l = g & Lm1;
                size_t pAa = ((size_t)n * Cout + oa) * L + l;
                size_t pBb = ((size_t)n * Cout + obr) * L + l;
                float2 va = make_float2(vax, vay);
                float2 vb = make_float2(vbx, vby);
                if (mode == 1) {
                    float2 qa = *(const float2*)(res + pAa);
                    float2 qb = *(const float2*)(res + pBb);
                    va.x += qa.x; va.y += qa.y; vb.x += qb.x; vb.y += qb.y;
                } else {
                    int b = n >> 4, t = n & 15;
                    size_t xa = (((size_t)(b * 192 + oa) * 16 + t) << 10) + l;
                    size_t xb = (((size_t)(b * 192 + obr) * 16 + t) << 10) + l;
                    float2 qa = *(const float2*)(res + xa);
                    float2 qb = *(const float2*)(res + xb);
                    va.x += qa.x; va.y += qa.y; vb.x += qb.x; vb.y += qb.y;
                }
                *(float2*)(outf + pAa) = va;
                *(float2*)(outf + pBb) = vb;
            }
        }
    }
}

// ---------------------------------------------------------------------------
// Attention pass 1: flash fp16 MMA. qk16 [token][h*128 + {Q:0..63, K:64..127}],
// V d-major [img][h*64+c][tok].
// ---------------------------------------------------------------------------
#define HS 72

__global__ __launch_bounds__(128, 4) void k_attn1h(const __half* __restrict__ qk,
                                                   const __half* __restrict__ vT,
                                                   __half* __restrict__ outh) {
    __shared__ __align__(16) __half smh[4 * 64 * HS];
    __half* U  = smh;
    __half* K0 = smh + 64 * HS;
    __half* K1 = smh + 2 * 64 * HS;
    __half* Vt = smh + 3 * 64 * HS;

    const int tid = threadIdx.x, lane = tid & 31, w = tid >> 5;
    const int r = lane >> 2, tg = lane & 3;
    const int bh = blockIdx.y, n = bh / 3, h = bh % 3;
    const int q0 = blockIdx.x * 64;
    const __half* Qg = qk + ((size_t)(n * 1024) + q0) * 384 + h * 128;
    const __half* Kg = qk + (size_t)(n * 1024) * 384 + h * 128 + 64;
    const __half* Vg = vT + (size_t)(n * 192 + h * 64) * 1024;

    const int stok = tid >> 1, seg = (tid & 1) * 32;

    // prologue: K tile 0 and Q
    #pragma unroll
    for (int i = 0; i < 4; i++)
        cp16(sptr(&K0[stok * HS + seg + i * 8]), Kg + (size_t)stok * 384 + seg + i * 8);
    #pragma unroll
    for (int i = 0; i < 4; i++)
        cp16(sptr(&U[stok * HS + seg + i * 8]), Qg + (size_t)stok * 384 + seg + i * 8);
    cp_commit();
    cp_wait<0>();
    __syncthreads();

    // Q fragments persistent (U gets reused for P afterwards)
    uint32 qa[4][4];
    #pragma unroll
    for (int ks = 0; ks < 4; ks++) {
        const int kb = ks * 16 + 2 * tg;
        qa[ks][0] = *(const uint32*)&U[(16 * w + r) * HS + kb];
        qa[ks][1] = *(const uint32*)&U[(16 * w + r + 8) * HS + kb];
        qa[ks][2] = *(const uint32*)&U[(16 * w + r) * HS + kb + 8];
        qa[ks][3] = *(const uint32*)&U[(16 * w + r + 8) * HS + kb + 8];
    }

    float4 o[8];
    #pragma unroll
    for (int nt = 0; nt < 8; nt++) o[nt] = make_float4(0.f, 0.f, 0.f, 0.f);
    float m0 = -1e30f, m1 = -1e30f, s0 = 0.f, s1 = 0.f;
    __half* pr0h = U + (16 * w + r) * HS;
    __half* pr1h = U + (16 * w + r + 8) * HS;
    const float SC = 0.125f;   // ch^-0.5 combined score scale

    for (int kt = 0; kt < 16; kt++) {
        const int buf = kt & 1;
        // stage V(kt): rows d, 64 local tokens
        {
            const int sb = kt * 64;
            #pragma unroll
            for (int i = 0; i < 4; i++)
                cp16(sptr(&Vt[stok * HS + seg + i * 8]),
                     Vg + (size_t)stok * 1024 + sb + seg + i * 8);
            cp_commit();
        }
        // stage K(kt+1)
        if (kt < 15) {
            const int sb = (kt + 1) * 64;
            __half* Kn = buf ? K0 : K1;
            #pragma unroll
            for (int i = 0; i < 4; i++)
                cp16(sptr(&Kn[stok * HS + seg + i * 8]),
                     Kg + (size_t)(sb + stok) * 384 + seg + i * 8);
        }
        cp_commit();
        cp_wait<2>();
        __syncthreads();
        const __half* Ks = buf ? K1 : K0;

        // S = Q K^T (raw, scale applied in softmax)
        float4 sc[8];
        #pragma unroll
        for (int nt = 0; nt < 8; nt++) sc[nt] = make_float4(0.f, 0.f, 0.f, 0.f);
        #pragma unroll
        for (int ks = 0; ks < 4; ks++) {
            const int kb = ks * 16 + 2 * tg;
            #pragma unroll
            for (int nt = 0; nt < 8; nt++) {
                uint32 b0 = *(const uint32*)&Ks[(nt * 8 + r) * HS + kb];
                uint32 b1 = *(const uint32*)&Ks[(nt * 8 + r) * HS + kb + 8];
                mmah(sc[nt], qa[ks], b0, b1);
            }
        }

        // online softmax
        float tm0 = -1e30f, tm1 = -1e30f;
        #pragma unroll
        for (int nt = 0; nt < 8; nt++) {
            tm0 = fmaxf(tm0, fmaxf(sc[nt].x, sc[nt].y));
            tm1 = fmaxf(tm1, fmaxf(sc[nt].z, sc[nt].w));
        }
        tm0 = fmaxf(tm0, __shfl_xor_sync(0xffffffffu, tm0, 1));
        tm0 = fmaxf(tm0, __shfl_xor_sync(0xffffffffu, tm0, 2));
        tm1 = fmaxf(tm1, __shfl_xor_sync(0xffffffffu, tm1, 1));
        tm1 = fmaxf(tm1, __shfl_xor_sync(0xffffffffu, tm1, 2));
        tm0 *= SC; tm1 *= SC;
        float nm0 = fmaxf(m0, tm0), nm1 = fmaxf(m1, tm1);
        float a0 = __expf(m0 - nm0), a1 = __expf(m1 - nm1);
        float t0 = 0.f, t1 = 0.f;
        #pragma unroll
        for (int nt = 0; nt < 8; nt++) {
            float px = __expf(fmaf(sc[nt].x, SC, -nm0));
            float py = __expf(fmaf(sc[nt].y, SC, -nm0));
            float pz = __expf(fmaf(sc[nt].z, SC, -nm1));
            float pw = __expf(fmaf(sc[nt].w, SC, -nm1));
            t0 += px + py; t1 += pz + pw;
            const int col = nt * 8 + 2 * tg;
            *(__half2*)(pr0h + col) = __floats2half2_rn(px, py);
            *(__half2*)(pr1h + col) = __floats2half2_rn(pz, pw);
            o[nt].x *= a0; o[nt].y *= a0;
            o[nt].z *= a1; o[nt].w *= a1;
        }
        t0 += __shfl_xor_sync(0xffffffffu, t0, 1);
        t0 += __shfl_xor_sync(0xffffffffu, t0, 2);
        t1 += __shfl_xor_sync(0xffffffffu, t1, 1);
        t1 += __shfl_xor_sync(0xffffffffu, t1, 2);
        s0 = s0 * a0 + t0;
        s1 = s1 * a1 + t1;
        m0 = nm0; m1 = nm1;
        __syncwarp();

        cp_wait<1>();     // V(kt) complete
        __syncthreads();

        // O += P V
        #pragma unroll
        for (int ks = 0; ks < 4; ks++) {
            const int kb = ks * 16 + 2 * tg;
            uint32 a[4];
            a[0] = *(const uint32*)(pr0h + kb);
            a[1] = *(const uint32*)(pr1h + kb);
            a[2] = *(const uint32*)(pr0h + kb + 8);
            a[3] = *(const uint32*)(pr1h + kb + 8);
            #pragma unroll
            for (int nt = 0; nt < 8; nt++) {
                uint32 b0 = *(const uint32*)&Vt[(nt * 8 + r) * HS + kb];
                uint32 b1 = *(const uint32*)&Vt[(nt * 8 + r) * HS + kb + 8];
                mmah(o[nt], a, b0, b1);
            }
        }
        __syncthreads();
    }

    // normalize, stage to smem (K0), coalesced half write (channel-last)
    float i0 = 1.f / s0, i1 = 1.f / s1;
    __half* Os = K0;
    #pragma unroll
    for (int nt = 0; nt < 8; nt++) {
        const int col = nt * 8 + 2 * tg;
        *(__half2*)(Os + (16 * w + r) * HS + col)     = __floats2half2_rn(o[nt].x * i0, o[nt].y * i0);
        *(__half2*)(Os + (16 * w + r + 8) * HS + col) = __floats2half2_rn(o[nt].z * i1, o[nt].w * i1);
    }
    __syncthreads();
    __half* dst = outh + ((size_t)(n * 1024) + q0 + stok) * 192 + h * 64 + seg;
    #pragma unroll
    for (int i = 0; i < 4; i++)
        *(uint4*)(dst + i * 8) = *(const uint4*)(Os + stok * HS + seg + i * 8);
}

// ---------------------------------------------------------------------------
// Attention pass 2: L=16, scalar fp32 from half inputs
// ---------------------------------------------------------------------------
__global__ void k_attn2h(const __half* __restrict__ qkh, const __half* __restrict__ vTh,
                         __half* __restrict__ outh) {
    __shared__ float qs[16][68], ks[16][68], vs[1024], S[16 * 17];
    int bh = blockIdx.x, n = bh / 3, h = bh % 3;
    int tid = threadIdx.x;
    const __half* Qb = qkh + (size_t)(n * 16) * 384 + h * 128;
    const __half* Vb = vTh + (size_t)(n * 192 + h * 64) * 16;
    for (int i = tid; i < 1024; i += 256) {
        int q = i >> 6, c = i & 63;
        qs[q][c] = __half2float(Qb[(size_t)q * 384 + c]) * 0.125f;
        ks[q][c] = __half2float(Qb[(size_t)q * 384 + 64 + c]);
        vs[i] = __half2float(Vb[i]);
    }
    __syncthreads();
    {
        int q = tid >> 4, s = tid & 15;
        float a = 0.f;
        #pragma unroll
        for (int c = 0; c < 64; c++) a += qs[q][c] * ks[s][c];
        S[q * 17 + s] = a;
    }
    __syncthreads();
    if (tid < 16) {
        float* row = S + tid * 17;
        float m = -1e30f;
        #pragma unroll
        for (int s = 0; s < 16; s++) m = fmaxf(m, row[s]);
        float sum = 0.f;
        #pragma unroll
        for (int s = 0; s < 16; s++) { float e = __expf(row[s] - m); row[s] = e; sum += e; }
        float inv = 1.f / sum;
        #pragma unroll
        for (int s = 0; s < 16; s++) row[s] *= inv;
    }
    __syncthreads();
    {
        int q = tid & 15;
        int cb = (tid >> 4) << 2;
        float a0 = 0.f, a1 = 0.f, a2 = 0.f, a3 = 0.f;
        #pragma unroll
        for (int s = 0; s < 16; s++) {
            float sv = S[q * 17 + s];
            a0 += vs[(cb + 0) * 16 + s] * sv;
            a1 += vs[(cb + 1) * 16 + s] * sv;
            a2 += vs[(cb + 2) * 16 + s] * sv;
            a3 += vs[(cb + 3) * 16 + s] * sv;
        }
        __half* ob = outh + ((size_t)(n * 16) + q) * 192 + h * 64 + cb;
        ob[0] = __float2half(a0);
        ob[1] = __float2half(a1);
        ob[2] = __float2half(a2);
        ob[3] = __float2half(a3);
    }
}

// ---------------------------------------------------------------------------
extern "C" void kernel_launch(void* const* d_in, const int* in_sizes, int n_in,
                              void* d_out, int out_size) {
    const float* x       = (const float*)d_in[0];
    const float* norm_g  = (const float*)d_in[1];
    const float* norm_b  = (const float*)d_in[2];
    const float* qkv_w   = (const float*)d_in[3];
    const float* qkv_b   = (const float*)d_in[4];
    const float* proj_w  = (const float*)d_in[5];
    const float* proj_b  = (const float*)d_in[6];
    const float* normt_g = (const float*)d_in[7];
    const float* normt_b = (const float*)d_in[8];
    const float* qkvt_w  = (const float*)d_in[9];
    const float* qkvt_b  = (const float*)d_in[10];
    const float* projt_w = (const float*)d_in[11];
    const float* projt_b = (const float*)d_in[12];
    float* out = (float*)d_out;

    float *xs, *y, *yt;
    __half *nrm16, *qk16, *v16T, *att16, *w16;
    cudaGetSymbolAddress((void**)&xs,    g_xs);
    cudaGetSymbolAddress((void**)&y,     g_y);
    cudaGetSymbolAddress((void**)&yt,    g_yt);
    cudaGetSymbolAddress((void**)&nrm16, g_nrm16);
    cudaGetSymbolAddress((void**)&qk16,  g_qk16);
    cudaGetSymbolAddress((void**)&v16T,  g_v16T);
    cudaGetSymbolAddress((void**)&att16, g_att16);
    cudaGetSymbolAddress((void**)&w16,   g_w16);

    const __half* w_qkv  = w16;
    const __half* w_proj = w16 + 110592;
    const __half* w_qkvt = w16 + 147456;
    const __half* w_projt= w16 + 258048;

    k_wprep<<<288, 1024>>>(qkv_w, proj_w, qkvt_w, projt_w);

    // ---- pass 1 (spatial, L=1024) ----
    k_gn1s<<<NBT * 32, 256>>>(x);
    k_gn1a<<<128, 256>>>(x, norm_g, norm_b);
    k_convh<<<dim3(256, 9), 128>>>(nrm16, w_qkv, qkv_b, nullptr,
                                   nullptr, qk16, v16T, 576, 10, 0);
    k_attn1h<<<dim3(16, 96), 128>>>(qk16, v16T, att16);
    k_convh<<<dim3(256, 3), 128>>>(att16, w_proj, proj_b, x,
                                   y, nullptr, nullptr, 192, 10, 2);

    // ---- pass 2 (temporal, L=16) ----
    k_transpose2t<<<dim3(16, 192, 2), 256>>>();
    k_gn2h<<<2048, 128>>>(yt, normt_g, normt_b, nrm16);
    k_convh<<<dim3(256, 9), 128>>>(nrm16, w_qkvt, qkvt_b, nullptr,
                                   nullptr, qk16, v16T, 576, 4, 0);
    k_attn2h<<<6144, 256>>>(qk16, v16T, att16);
    k_convh<<<dim3(256, 3), 128>>>(att16, w_projt, projt_b, yt,
                                   xs, nullptr, nullptr, 192, 4, 1);
    k_transpose3t<<<dim3(16, 192, 2), 256>>>(out);
}

// round 11
// speedup vs baseline: 9.4268x; 1.0209x over previous
#include <cuda_runtime.h>
#include <cuda_fp16.h>
#include <math.h>

#define NBT 32
#define CCH 192
#define TOT (NBT*CCH*1024)
typedef unsigned int uint32;

// fp32 scratch
__device__ float g_xs [TOT];          // z (bhw,c,t) in pass2
__device__ float g_y  [TOT];
__device__ float g_yt [TOT];
__device__ float g_stat[NBT*32*2];
// fp16 scratch
__device__ __half g_nrm16[32768*192];
__device__ __half g_qk16 [32768*384];
__device__ __half g_v16T [32768*192];
__device__ __half g_att16[32768*192];
__device__ __half g_w16  [294912];

// ---- helpers ----------------------------------------------------------------
__device__ __forceinline__ void mmah(float4 &c, const uint32* a, uint32 b0, uint32 b1) {
    asm("mma.sync.aligned.m16n8k16.row.col.f32.f16.f16.f32 "
        "{%0,%1,%2,%3},{%4,%5,%6,%7},{%8,%9},{%0,%1,%2,%3};"
        : "+f"(c.x), "+f"(c.y), "+f"(c.z), "+f"(c.w)
        : "r"(a[0]), "r"(a[1]), "r"(a[2]), "r"(a[3]), "r"(b0), "r"(b1));
}
__device__ __forceinline__ uint32 sptr(const void* p) {
    return (uint32)__cvta_generic_to_shared(p);
}
__device__ __forceinline__ void cp16(uint32 s, const void* g) {
    asm volatile("cp.async.ca.shared.global [%0], [%1], 16;" :: "r"(s), "l"(g));
}
__device__ __forceinline__ void cp_commit() { asm volatile("cp.async.commit_group;"); }
template<int N> __device__ __forceinline__ void cp_wait() {
    asm volatile("cp.async.wait_group %0;" :: "n"(N));
}

// ---------------------------------------------------------------------------
// Weight fp16 prep (294912 elems exactly = 288 * 1024)
// ---------------------------------------------------------------------------
__global__ void k_wprep(const float* __restrict__ qw, const float* __restrict__ pw,
                        const float* __restrict__ qtw, const float* __restrict__ ptw) {
    int i = blockIdx.x * 1024 + threadIdx.x;
    float v;
    if      (i < 110592) v = qw[i];
    else if (i < 147456) v = pw[i - 110592];
    else if (i < 258048) v = qtw[i - 147456];
    else                 v = ptw[i - 258048];
    g_w16[i] = __float2half(v);
}

// ---------------------------------------------------------------------------
// GroupNorm pass 1 stats: grid (32 bt x 32 g)
// ---------------------------------------------------------------------------
__global__ void k_gn1s(const float* __restrict__ x) {
    int n = blockIdx.x >> 5, g = blockIdx.x & 31;
    int b = n >> 4, t = n & 15;
    const float* xb = x + (((size_t)(b * CCH + g * 6) * 16 + t) << 10);
    int tid = threadIdx.x;
    float s = 0.f, q = 0.f;
    for (int i = tid; i < 6144; i += 256) {
        float v = xb[((size_t)(i >> 10) << 14) + (i & 1023)];
        s += v; q += v * v;
    }
    __shared__ float rs[256], rq[256];
    rs[tid] = s; rq[tid] = q;
    __syncthreads();
    for (int st = 128; st > 0; st >>= 1) {
        if (tid < st) { rs[tid] += rs[tid + st]; rq[tid] += rq[tid + st]; }
        __syncthreads();
    }
    if (tid == 0) {
        float mean = rs[0] / 6144.f;
        float var  = rq[0] / 6144.f - mean * mean;
        g_stat[blockIdx.x * 2]     = mean;
        g_stat[blockIdx.x * 2 + 1] = rsqrtf(var + 1e-5f);
    }
}

// apply: one thread per token, writes channel-last half
__global__ void k_gn1a(const float* __restrict__ x, const float* __restrict__ gam,
                       const float* __restrict__ bet) {
    int token = blockIdx.x * 256 + threadIdx.x;
    int bt = token >> 10, hw = token & 1023;
    int b = bt >> 4, t = bt & 15;
    int sb = bt * 32;
    __half* o = g_nrm16 + (size_t)token * 192;
    for (int g = 0; g < 32; g++) {
        float mu = g_stat[(sb + g) * 2], iv = g_stat[(sb + g) * 2 + 1];
        const float* xc = x + (((size_t)(b * CCH + g * 6) * 16 + t) << 10) + hw;
        #pragma unroll
        for (int j = 0; j < 6; j += 2) {
            int c = g * 6 + j;
            float v0 = xc[(size_t)j << 14], v1 = xc[(size_t)(j + 1) << 14];
            __half2 hh = __floats2half2_rn((v0 - mu) * iv * gam[c] + bet[c],
                                           (v1 - mu) * iv * gam[c + 1] + bet[c + 1]);
            *(__half2*)(o + c) = hh;
        }
    }
}

// ---------------------------------------------------------------------------
// GroupNorm pass 2: X (bhw,c,t) fp32, one block per n; out half channel-last
// ---------------------------------------------------------------------------
__global__ void k_gn2h(const float* __restrict__ X, const float* __restrict__ gam,
                       const float* __restrict__ bet, __half* __restrict__ out16) {
    int n = blockIdx.x;
    __shared__ float buf[3072];
    __shared__ float mu[32], iv[32];
    int tid = threadIdx.x;
    const float4* xb = (const float4*)(X + (size_t)n * 3072);
    for (int i = tid; i < 768; i += 128) ((float4*)buf)[i] = xb[i];
    __syncthreads();
    int w = tid >> 5, lane = tid & 31;
    for (int g = w; g < 32; g += 4) {
        float v0 = buf[g * 96 + lane], v1 = buf[g * 96 + 32 + lane], v2 = buf[g * 96 + 64 + lane];
        float s = v0 + v1 + v2, q = v0 * v0 + v1 * v1 + v2 * v2;
        #pragma unroll
        for (int off = 16; off; off >>= 1) {
            s += __shfl_xor_sync(0xffffffffu, s, off);
            q += __shfl_xor_sync(0xffffffffu, q, off);
        }
        if (lane == 0) {
            float m = s / 96.f, va = q / 96.f - m * m;
            mu[g] = m; iv[g] = rsqrtf(va + 1e-5f);
        }
    }
    __syncthreads();
    __half* ob = out16 + (size_t)n * 3072;
    for (int j = tid; j < 3072; j += 128) {
        int t = j / 192, c = j - t * 192;
        int g = c / 6;
        ob[j] = __float2half((buf[c * 16 + t] - mu[g]) * iv[g] * gam[c] + bet[c]);
    }
}

// ---------------------------------------------------------------------------
// Tiled fp32 transposes
// ---------------------------------------------------------------------------
__global__ void k_transpose2t() {   // y (bt,c,hw) -> yt (bhw,c,t)
    __shared__ float sm[64][20];
    int hw0 = blockIdx.x * 64, c = blockIdx.y, b = blockIdx.z;
    int tid = threadIdx.x;
    {
        int t = tid & 15, hwj = (tid >> 4) * 4;
        float4 v = *(const float4*)&g_y[(((size_t)(b * 16 + t) * CCH + c) << 10) + hw0 + hwj];
        sm[hwj + 0][t] = v.x; sm[hwj + 1][t] = v.y;
        sm[hwj + 2][t] = v.z; sm[hwj + 3][t] = v.w;
    }
    __syncthreads();
    {
        int hwl = tid >> 2, t4 = (tid & 3) * 4;
        *(float4*)&g_yt[((size_t)(b * 1024 + hw0 + hwl) * CCH + c) * 16 + t4] =
            *(const float4*)&sm[hwl][t4];
    }
}

__global__ void k_transpose3t(float* __restrict__ out) {  // z (bhw,c,t) -> (b,c,t,hw)
    __shared__ float sm[16][68];
    int hw0 = blockIdx.x * 64, c = blockIdx.y, b = blockIdx.z;
    int tid = threadIdx.x;
    {
        int hwl = tid >> 2, t4 = (tid & 3) * 4;
        float4 v = *(const float4*)&g_xs[((size_t)(b * 1024 + hw0 + hwl) * CCH + c) * 16 + t4];
        sm[t4 + 0][hwl] = v.x; sm[t4 + 1][hwl] = v.y;
        sm[t4 + 2][hwl] = v.z; sm[t4 + 3][hwl] = v.w;
    }
    __syncthreads();
    {
        int t = tid >> 4, hw4 = (tid & 15) * 4;
        *(float4*)&out[(((size_t)(b * CCH + c) * 16 + t) << 10) + hw0 + hw4] =
            *(const float4*)&sm[t][hw4];
    }
}

// ---------------------------------------------------------------------------
// 1x1 conv, fp16 MMA (m16n8k16), cp.async double buffered, K-chunks of 32.
// X channel-last [token][192] half, W [o][192] half.
// mode 0 (qkv): out channel o = 192h + 64p + c:
//   p<2 -> qk16[token][h*128 + 64p + c];  p=2 -> v16T[img][h*64+c][tok]
//   Epilogue staged through smem for coalesced gmem writes.
// mode 1: fp32 + res same layout; mode 2: fp32 + res x-layout
// ---------------------------------------------------------------------------
// Unified smem: Xs(buf,tok,k)=SM[buf*5120+tok*40+k], Ws(buf,o,k)=SM[10240+buf*2560+o*40+k]
#define XS(b,t,k) SM[(b)*5120 + (t)*40 + (k)]
#define WS(b,o,k) SM[10240 + (b)*2560 + (o)*40 + (k)]

__global__ __launch_bounds__(128, 4) void k_convh(
    const __half* __restrict__ X, const __half* __restrict__ W,
    const float* __restrict__ bias, const float* __restrict__ res,
    float* __restrict__ outf, __half* __restrict__ outqk, __half* __restrict__ outv,
    int Cout, int ls, int mode) {
    __shared__ __align__(16) __half SM[15360];
    const int tid = threadIdx.x, lane = tid & 31, w = tid >> 5;
    const int r = lane >> 2, tg = lane & 3;
    const int g0 = blockIdx.x * 128, o0 = blockIdx.y * 64;
    const int ob0 = 32 * (w >> 1), coff = (w & 1) * 64;
    const int L = 1 << ls, Lm1 = L - 1;

    float4 acc[2][8];
    #pragma unroll
    for (int ms = 0; ms < 2; ms++)
        #pragma unroll
        for (int nt = 0; nt < 8; nt++) acc[ms][nt] = make_float4(0.f, 0.f, 0.f, 0.f);

    const __half* xsrc = X + (size_t)(g0 + tid) * 192;
    const int wo = tid & 63, wp = (tid >> 6) * 16;
    const __half* wsrc = W + (size_t)(o0 + wo) * 192 + wp;

    // prologue chunk 0
    #pragma unroll
    for (int j = 0; j < 4; j++) cp16(sptr(&XS(0, tid, j * 8)), xsrc + j * 8);
    #pragma unroll
    for (int j = 0; j < 2; j++) cp16(sptr(&WS(0, wo, wp + j * 8)), wsrc + j * 8);
    cp_commit();

    for (int c = 0; c < 6; c++) {
        const int buf = c & 1;
        if (c < 5) {
            const int cc = (c + 1) * 32;
            #pragma unroll
            for (int j = 0; j < 4; j++)
                cp16(sptr(&XS(buf ^ 1, tid, j * 8)), xsrc + cc + j * 8);
            #pragma unroll
            for (int j = 0; j < 2; j++)
                cp16(sptr(&WS(buf ^ 1, wo, wp + j * 8)), wsrc + cc + j * 8);
            cp_commit();
            cp_wait<1>();
        } else {
            cp_wait<0>();
        }
        __syncthreads();
        #pragma unroll
        for (int ks = 0; ks < 2; ks++) {
            const int kb = ks * 16 + 2 * tg;
            uint32 a0[4], a1[4];
            a0[0] = *(const uint32*)&WS(buf, ob0 + r,      kb);
            a0[1] = *(const uint32*)&WS(buf, ob0 + r + 8,  kb);
            a0[2] = *(const uint32*)&WS(buf, ob0 + r,      kb + 8);
            a0[3] = *(const uint32*)&WS(buf, ob0 + r + 8,  kb + 8);
            a1[0] = *(const uint32*)&WS(buf, ob0 + 16 + r, kb);
            a1[1] = *(const uint32*)&WS(buf, ob0 + 24 + r, kb);
            a1[2] = *(const uint32*)&WS(buf, ob0 + 16 + r, kb + 8);
            a1[3] = *(const uint32*)&WS(buf, ob0 + 24 + r, kb + 8);
            #pragma unroll
            for (int nt = 0; nt < 8; nt++) {
                uint32 b0 = *(const uint32*)&XS(buf, coff + nt * 8 + r, kb);
                uint32 b1 = *(const uint32*)&XS(buf, coff + nt * 8 + r, kb + 8);
                mmah(acc[0][nt], a0, b0, b1);
                mmah(acc[1][nt], a1, b0, b1);
            }
        }
        __syncthreads();
    }

    // ---- epilogue ----
    if (mode == 0) {
        // block covers 64 contiguous channels: o0 = 192*ha + 64*pa
        const int ha = o0 / 192;
        const int pa = (o0 - ha * 192) >> 6;
        if (pa < 2) {
            // Q/K: stage [tok 128][72] halves, then coalesced uint4 per token
            #pragma unroll
            for (int ms = 0; ms < 2; ms++) {
                const int c0 = ob0 + 16 * ms + r;         // local ch
                const float ba = bias[o0 + c0], bb = bias[o0 + c0 + 8];
                #pragma unroll
                for (int nt = 0; nt < 8; nt++) {
                    const int tok = coff + nt * 8 + 2 * tg;
                    SM[tok * 72 + c0]           = __float2half(acc[ms][nt].x + ba);
                    SM[(tok + 1) * 72 + c0]     = __float2half(acc[ms][nt].y + ba);
                    SM[tok * 72 + c0 + 8]       = __float2half(acc[ms][nt].z + bb);
                    SM[(tok + 1) * 72 + c0 + 8] = __float2half(acc[ms][nt].w + bb);
                }
            }
            __syncthreads();
            const int base = ha * 128 + pa * 64;
            #pragma unroll
            for (int i = 0; i < 8; i++) {
                int j = tid + 128 * i;
                int tok = j >> 3, seg = j & 7;
                *(uint4*)(outqk + (size_t)(g0 + tok) * 384 + base + seg * 8) =
                    *(const uint4*)(SM + tok * 72 + seg * 8);
            }
        } else {
            // V: stage [ch 64][136] halves (conflict-free half2), coalesced rows out
            #pragma unroll
            for (int ms = 0; ms < 2; ms++) {
                const int c0 = ob0 + 16 * ms + r;
                const float ba = bias[o0 + c0], bb = bias[o0 + c0 + 8];
                #pragma unroll
                for (int nt = 0; nt < 8; nt++) {
                    const int tok = coff + nt * 8 + 2 * tg;
                    *(__half2*)(SM + c0 * 136 + tok) =
                        __floats2half2_rn(acc[ms][nt].x + ba, acc[ms][nt].y + ba);
                    *(__half2*)(SM + (c0 + 8) * 136 + tok) =
                        __floats2half2_rn(acc[ms][nt].z + bb, acc[ms][nt].w + bb);
                }
            }
            __syncthreads();
            const int cvb = ha * 64;
            #pragma unroll
            for (int i = 0; i < 8; i++) {
                int j = tid + 128 * i;
                int ch = j >> 4, seg = j & 15;
                int gt = g0 + seg * 8;
                int img = gt >> ls, tok = gt & Lm1;
                *(uint4*)(outv + ((size_t)img * 192 + cvb + ch) * L + tok) =
                    *(const uint4*)(SM + ch * 136 + seg * 8);
            }
        }
    } else {
        #pragma unroll
        for (int ms = 0; ms < 2; ms++) {
            const int oa = o0 + ob0 + 16 * ms + r;
            const int obr = oa + 8;
            const float ba = bias[oa], bb = bias[obr];
            #pragma unroll
            for (int nt = 0; nt < 8; nt++) {
                int g = g0 + coff + nt * 8 + 2 * tg;
                float vax = acc[ms][nt].x + ba, vay = acc[ms][nt].y + ba;
                float vbx = acc[ms][nt].z + bb, vby = acc[ms][nt].w + bb;
                int n = g >> ls, l = g & Lm1;
                size_t pAa = ((size_t)n * Cout + oa) * L + l;
                size_t pBb = ((size_t)n * Cout + obr) * L + l;
                float2 va = make_float2(vax, vay);
                float2 vb = make_float2(vbx, vby);
                if (mode == 1) {
                    float2 qa = *(const float2*)(res + pAa);
                    float2 qb = *(const float2*)(res + pBb);
                    va.x += qa.x; va.y += qa.y; vb.x += qb.x; vb.y += qb.y;
                } else {
                    int b = n >> 4, t = n & 15;
                    size_t xa = (((size_t)(b * 192 + oa) * 16 + t) << 10) + l;
                    size_t xb = (((size_t)(b * 192 + obr) * 16 + t) << 10) + l;
                    float2 qa = *(const float2*)(res + xa);
                    float2 qb = *(const float2*)(res + xb);
                    va.x += qa.x; va.y += qa.y; vb.x += qb.x; vb.y += qb.y;
                }
                *(float2*)(outf + pAa) = va;
                *(float2*)(outf + pBb) = vb;
            }
        }
    }
}

// ---------------------------------------------------------------------------
// Attention pass 1: flash fp16 MMA. qk16 [token][h*128 + {Q:0..63, K:64..127}],
// V d-major [img][h*64+c][tok].
// ---------------------------------------------------------------------------
#define HS 72

__global__ __launch_bounds__(128, 4) void k_attn1h(const __half* __restrict__ qk,
                                                   const __half* __restrict__ vT,
                                                   __half* __restrict__ outh) {
    __shared__ __align__(16) __half smh[4 * 64 * HS];
    __half* U  = smh;
    __half* K0 = smh + 64 * HS;
    __half* K1 = smh + 2 * 64 * HS;
    __half* Vt = smh + 3 * 64 * HS;

    const int tid = threadIdx.x, lane = tid & 31, w = tid >> 5;
    const int r = lane >> 2, tg = lane & 3;
    const int bh = blockIdx.y, n = bh / 3, h = bh % 3;
    const int q0 = blockIdx.x * 64;
    const __half* Qg = qk + ((size_t)(n * 1024) + q0) * 384 + h * 128;
    const __half* Kg = qk + (size_t)(n * 1024) * 384 + h * 128 + 64;
    const __half* Vg = vT + (size_t)(n * 192 + h * 64) * 1024;

    const int stok = tid >> 1, seg = (tid & 1) * 32;

    // prologue: K tile 0 and Q
    #pragma unroll
    for (int i = 0; i < 4; i++)
        cp16(sptr(&K0[stok * HS + seg + i * 8]), Kg + (size_t)stok * 384 + seg + i * 8);
    #pragma unroll
    for (int i = 0; i < 4; i++)
        cp16(sptr(&U[stok * HS + seg + i * 8]), Qg + (size_t)stok * 384 + seg + i * 8);
    cp_commit();
    cp_wait<0>();
    __syncthreads();

    // Q fragments persistent (U gets reused for P afterwards)
    uint32 qa[4][4];
    #pragma unroll
    for (int ks = 0; ks < 4; ks++) {
        const int kb = ks * 16 + 2 * tg;
        qa[ks][0] = *(const uint32*)&U[(16 * w + r) * HS + kb];
        qa[ks][1] = *(const uint32*)&U[(16 * w + r + 8) * HS + kb];
        qa[ks][2] = *(const uint32*)&U[(16 * w + r) * HS + kb + 8];
        qa[ks][3] = *(const uint32*)&U[(16 * w + r + 8) * HS + kb + 8];
    }

    float4 o[8];
    #pragma unroll
    for (int nt = 0; nt < 8; nt++) o[nt] = make_float4(0.f, 0.f, 0.f, 0.f);
    float m0 = -1e30f, m1 = -1e30f, s0 = 0.f, s1 = 0.f;
    __half* pr0h = U + (16 * w + r) * HS;
    __half* pr1h = U + (16 * w + r + 8) * HS;
    const float SC = 0.125f;   // ch^-0.5 combined score scale

    for (int kt = 0; kt < 16; kt++) {
        const int buf = kt & 1;
        // stage V(kt): rows d, 64 local tokens
        {
            const int sb = kt * 64;
            #pragma unroll
            for (int i = 0; i < 4; i++)
                cp16(sptr(&Vt[stok * HS + seg + i * 8]),
                     Vg + (size_t)stok * 1024 + sb + seg + i * 8);
            cp_commit();
        }
        // stage K(kt+1)
        if (kt < 15) {
            const int sb = (kt + 1) * 64;
            __half* Kn = buf ? K0 : K1;
            #pragma unroll
            for (int i = 0; i < 4; i++)
                cp16(sptr(&Kn[stok * HS + seg + i * 8]),
                     Kg + (size_t)(sb + stok) * 384 + seg + i * 8);
        }
        cp_commit();
        cp_wait<2>();
        __syncthreads();
        const __half* Ks = buf ? K1 : K0;

        // S = Q K^T (raw, scale applied in softmax)
        float4 sc[8];
        #pragma unroll
        for (int nt = 0; nt < 8; nt++) sc[nt] = make_float4(0.f, 0.f, 0.f, 0.f);
        #pragma unroll
        for (int ks = 0; ks < 4; ks++) {
            const int kb = ks * 16 + 2 * tg;
            #pragma unroll
            for (int nt = 0; nt < 8; nt++) {
                uint32 b0 = *(const uint32*)&Ks[(nt * 8 + r) * HS + kb];
                uint32 b1 = *(const uint32*)&Ks[(nt * 8 + r) * HS + kb + 8];
                mmah(sc[nt], qa[ks], b0, b1);
            }
        }

        // online softmax
        float tm0 = -1e30f, tm1 = -1e30f;
        #pragma unroll
        for (int nt = 0; nt < 8; nt++) {
            tm0 = fmaxf(tm0, fmaxf(sc[nt].x, sc[nt].y));
            tm1 = fmaxf(tm1, fmaxf(sc[nt].z, sc[nt].w));
        }
        tm0 = fmaxf(tm0, __shfl_xor_sync(0xffffffffu, tm0, 1));
        tm0 = fmaxf(tm0, __shfl_xor_sync(0xffffffffu, tm0, 2));
        tm1 = fmaxf(tm1, __shfl_xor_sync(0xffffffffu, tm1, 1));
        tm1 = fmaxf(tm1, __shfl_xor_sync(0xffffffffu, tm1, 2));
        tm0 *= SC; tm1 *= SC;
        float nm0 = fmaxf(m0, tm0), nm1 = fmaxf(m1, tm1);
        float a0 = __expf(m0 - nm0), a1 = __expf(m1 - nm1);
        float t0 = 0.f, t1 = 0.f;
        #pragma unroll
        for (int nt = 0; nt < 8; nt++) {
            float px = __expf(fmaf(sc[nt].x, SC, -nm0));
            float py = __expf(fmaf(sc[nt].y, SC, -nm0));
            float pz = __expf(fmaf(sc[nt].z, SC, -nm1));
            float pw = __expf(fmaf(sc[nt].w, SC, -nm1));
            t0 += px + py; t1 += pz + pw;
            const int col = nt * 8 + 2 * tg;
            *(__half2*)(pr0h + col) = __floats2half2_rn(px, py);
            *(__half2*)(pr1h + col) = __floats2half2_rn(pz, pw);
            o[nt].x *= a0; o[nt].y *= a0;
            o[nt].z *= a1; o[nt].w *= a1;
        }
        t0 += __shfl_xor_sync(0xffffffffu, t0, 1);
        t0 += __shfl_xor_sync(0xffffffffu, t0, 2);
        t1 += __shfl_xor_sync(0xffffffffu, t1, 1);
        t1 += __shfl_xor_sync(0xffffffffu, t1, 2);
        s0 = s0 * a0 + t0;
        s1 = s1 * a1 + t1;
        m0 = nm0; m1 = nm1;
        __syncwarp();

        cp_wait<1>();     // V(kt) complete
        __syncthreads();

        // O += P V
        #pragma unroll
        for (int ks = 0; ks < 4; ks++) {
            const int kb = ks * 16 + 2 * tg;
            uint32 a[4];
            a[0] = *(const uint32*)(pr0h + kb);
            a[1] = *(const uint32*)(pr1h + kb);
            a[2] = *(const uint32*)(pr0h + kb + 8);
            a[3] = *(const uint32*)(pr1h + kb + 8);
            #pragma unroll
            for (int nt = 0; nt < 8; nt++) {
                uint32 b0 = *(const uint32*)&Vt[(nt * 8 + r) * HS + kb];
                uint32 b1 = *(const uint32*)&Vt[(nt * 8 + r) * HS + kb + 8];
                mmah(o[nt], a, b0, b1);
            }
        }
        __syncthreads();
    }

    // normalize, stage to smem (K0), coalesced half write (channel-last)
    float i0 = 1.f / s0, i1 = 1.f / s1;
    __half* Os = K0;
    #pragma unroll
    for (int nt = 0; nt < 8; nt++) {
        const int col = nt * 8 + 2 * tg;
        *(__half2*)(Os + (16 * w + r) * HS + col)     = __floats2half2_rn(o[nt].x * i0, o[nt].y * i0);
        *(__half2*)(Os + (16 * w + r + 8) * HS + col) = __floats2half2_rn(o[nt].z * i1, o[nt].w * i1);
    }
    __syncthreads();
    __half* dst = outh + ((size_t)(n * 1024) + q0 + stok) * 192 + h * 64 + seg;
    #pragma unroll
    for (int i = 0; i < 4; i++)
        *(uint4*)(dst + i * 8) = *(const uint4*)(Os + stok * HS + seg + i * 8);
}

// ---------------------------------------------------------------------------
// Attention pass 2: L=16, scalar fp32 from half inputs
// ---------------------------------------------------------------------------
__global__ void k_attn2h(const __half* __restrict__ qkh, const __half* __restrict__ vTh,
                         __half* __restrict__ outh) {
    __shared__ float qs[16][68], ks[16][68], vs[1024], S[16 * 17];
    int bh = blockIdx.x, n = bh / 3, h = bh % 3;
    int tid = threadIdx.x;
    const __half* Qb = qkh + (size_t)(n * 16) * 384 + h * 128;
    const __half* Vb = vTh + (size_t)(n * 192 + h * 64) * 16;
    for (int i = tid; i < 1024; i += 256) {
        int q = i >> 6, c = i & 63;
        qs[q][c] = __half2float(Qb[(size_t)q * 384 + c]) * 0.125f;
        ks[q][c] = __half2float(Qb[(size_t)q * 384 + 64 + c]);
        vs[i] = __half2float(Vb[i]);
    }
    __syncthreads();
    {
        int q = tid >> 4, s = tid & 15;
        float a = 0.f;
        #pragma unroll
        for (int c = 0; c < 64; c++) a += qs[q][c] * ks[s][c];
        S[q * 17 + s] = a;
    }
    __syncthreads();
    if (tid < 16) {
        float* row = S + tid * 17;
        float m = -1e30f;
        #pragma unroll
        for (int s = 0; s < 16; s++) m = fmaxf(m, row[s]);
        float sum = 0.f;
        #pragma unroll
        for (int s = 0; s < 16; s++) { float e = __expf(row[s] - m); row[s] = e; sum += e; }
        float inv = 1.f / sum;
        #pragma unroll
        for (int s = 0; s < 16; s++) row[s] *= inv;
    }
    __syncthreads();
    {
        int q = tid & 15;
        int cb = (tid >> 4) << 2;
        float a0 = 0.f, a1 = 0.f, a2 = 0.f, a3 = 0.f;
        #pragma unroll
        for (int s = 0; s < 16; s++) {
            float sv = S[q * 17 + s];
            a0 += vs[(cb + 0) * 16 + s] * sv;
            a1 += vs[(cb + 1) * 16 + s] * sv;
            a2 += vs[(cb + 2) * 16 + s] * sv;
            a3 += vs[(cb + 3) * 16 + s] * sv;
        }
        __half* ob = outh + ((size_t)(n * 16) + q) * 192 + h * 64 + cb;
        ob[0] = __float2half(a0);
        ob[1] = __float2half(a1);
        ob[2] = __float2half(a2);
        ob[3] = __float2half(a3);
    }
}

// ---------------------------------------------------------------------------
extern "C" void kernel_launch(void* const* d_in, const int* in_sizes, int n_in,
                              void* d_out, int out_size) {
    const float* x       = (const float*)d_in[0];
    const float* norm_g  = (const float*)d_in[1];
    const float* norm_b  = (const float*)d_in[2];
    const float* qkv_w   = (const float*)d_in[3];
    const float* qkv_b   = (const float*)d_in[4];
    const float* proj_w  = (const float*)d_in[5];
    const float* proj_b  = (const float*)d_in[6];
    const float* normt_g = (const float*)d_in[7];
    const float* normt_b = (const float*)d_in[8];
    const float* qkvt_w  = (const float*)d_in[9];
    const float* qkvt_b  = (const float*)d_in[10];
    const float* projt_w = (const float*)d_in[11];
    const float* projt_b = (const float*)d_in[12];
    float* out = (float*)d_out;

    float *xs, *y, *yt;
    __half *nrm16, *qk16, *v16T, *att16, *w16;
    cudaGetSymbolAddress((void**)&xs,    g_xs);
    cudaGetSymbolAddress((void**)&y,     g_y);
    cudaGetSymbolAddress((void**)&yt,    g_yt);
    cudaGetSymbolAddress((void**)&nrm16, g_nrm16);
    cudaGetSymbolAddress((void**)&qk16,  g_qk16);
    cudaGetSymbolAddress((void**)&v16T,  g_v16T);
    cudaGetSymbolAddress((void**)&att16, g_att16);
    cudaGetSymbolAddress((void**)&w16,   g_w16);

    const __half* w_qkv  = w16;
    const __half* w_proj = w16 + 110592;
    const __half* w_qkvt = w16 + 147456;
    const __half* w_projt= w16 + 258048;

    k_wprep<<<288, 1024>>>(qkv_w, proj_w, qkvt_w, projt_w);

    // ---- pass 1 (spatial, L=1024) ----
    k_gn1s<<<NBT * 32, 256>>>(x);
    k_gn1a<<<128, 256>>>(x, norm_g, norm_b);
    k_convh<<<dim3(256, 9), 128>>>(nrm16, w_qkv, qkv_b, nullptr,
                                   nullptr, qk16, v16T, 576, 10, 0);
    k_attn1h<<<dim3(16, 96), 128>>>(qk16, v16T, att16);
    k_convh<<<dim3(256, 3), 128>>>(att16, w_proj, proj_b, x,
                                   y, nullptr, nullptr, 192, 10, 2);

    // ---- pass 2 (temporal, L=16) ----
    k_transpose2t<<<dim3(16, 192, 2), 256>>>();
    k_gn2h<<<2048, 128>>>(yt, normt_g, normt_b, nrm16);
    k_convh<<<dim3(256, 9), 128>>>(nrm16, w_qkvt, qkvt_b, nullptr,
                                   nullptr, qk16, v16T, 576, 4, 0);
    k_attn2h<<<6144, 256>>>(qk16, v16T, att16);
    k_convh<<<dim3(256, 3), 128>>>(att16, w_projt, projt_b, yt,
                                   xs, nullptr, nullptr, 192, 4, 1);
    k_transpose3t<<<dim3(16, 192, 2), 256>>>(out);
}

// round 12
// speedup vs baseline: 9.9090x; 1.0512x over previous
#include <cuda_runtime.h>
#include <cuda_fp16.h>
#include <math.h>

#define NBT 32
#define CCH 192
#define TOT (NBT*CCH*1024)
typedef unsigned int uint32;

// fp32 scratch
__device__ float g_xs [TOT];          // z (bhw,c,t) in pass2
__device__ float g_y  [TOT];
__device__ float g_yt [TOT];
__device__ float g_stat[NBT*32*2];
// fp16 scratch
__device__ __half g_nrm16[32768*192];
__device__ __half g_qk16 [32768*384];
__device__ __half g_v16T [32768*192];
__device__ __half g_att16[32768*192];
__device__ __half g_w16  [294912];

// ---- helpers ----------------------------------------------------------------
__device__ __forceinline__ void mmah(float4 &c, const uint32* a, uint32 b0, uint32 b1) {
    asm("mma.sync.aligned.m16n8k16.row.col.f32.f16.f16.f32 "
        "{%0,%1,%2,%3},{%4,%5,%6,%7},{%8,%9},{%0,%1,%2,%3};"
        : "+f"(c.x), "+f"(c.y), "+f"(c.z), "+f"(c.w)
        : "r"(a[0]), "r"(a[1]), "r"(a[2]), "r"(a[3]), "r"(b0), "r"(b1));
}
__device__ __forceinline__ uint32 sptr(const void* p) {
    return (uint32)__cvta_generic_to_shared(p);
}
__device__ __forceinline__ void ldsm4(uint32* r, uint32 addr) {
    asm volatile("ldmatrix.sync.aligned.m8n8.x4.shared.b16 {%0,%1,%2,%3}, [%4];"
        : "=r"(r[0]), "=r"(r[1]), "=r"(r[2]), "=r"(r[3]) : "r"(addr));
}
__device__ __forceinline__ void cp16(uint32 s, const void* g) {
    asm volatile("cp.async.ca.shared.global [%0], [%1], 16;" :: "r"(s), "l"(g));
}
__device__ __forceinline__ void cp_commit() { asm volatile("cp.async.commit_group;"); }
template<int N> __device__ __forceinline__ void cp_wait() {
    asm volatile("cp.async.wait_group %0;" :: "n"(N));
}

// ---------------------------------------------------------------------------
// Weight fp16 prep
// ---------------------------------------------------------------------------
__global__ void k_wprep(const float* __restrict__ qw, const float* __restrict__ pw,
                        const float* __restrict__ qtw, const float* __restrict__ ptw) {
    int i = blockIdx.x * 1024 + threadIdx.x;
    float v;
    if      (i < 110592) v = qw[i];
    else if (i < 147456) v = pw[i - 110592];
    else if (i < 258048) v = qtw[i - 147456];
    else                 v = ptw[i - 258048];
    g_w16[i] = __float2half(v);
}

// ---------------------------------------------------------------------------
// GroupNorm pass 1 stats
// ---------------------------------------------------------------------------
__global__ void k_gn1s(const float* __restrict__ x) {
    int n = blockIdx.x >> 5, g = blockIdx.x & 31;
    int b = n >> 4, t = n & 15;
    const float* xb = x + (((size_t)(b * CCH + g * 6) * 16 + t) << 10);
    int tid = threadIdx.x;
    float s = 0.f, q = 0.f;
    for (int i = tid; i < 6144; i += 256) {
        float v = xb[((size_t)(i >> 10) << 14) + (i & 1023)];
        s += v; q += v * v;
    }
    __shared__ float rs[256], rq[256];
    rs[tid] = s; rq[tid] = q;
    __syncthreads();
    for (int st = 128; st > 0; st >>= 1) {
        if (tid < st) { rs[tid] += rs[tid + st]; rq[tid] += rq[tid + st]; }
        __syncthreads();
    }
    if (tid == 0) {
        float mean = rs[0] / 6144.f;
        float var  = rq[0] / 6144.f - mean * mean;
        g_stat[blockIdx.x * 2]     = mean;
        g_stat[blockIdx.x * 2 + 1] = rsqrtf(var + 1e-5f);
    }
}

// apply: one thread per token, writes channel-last half
__global__ void k_gn1a(const float* __restrict__ x, const float* __restrict__ gam,
                       const float* __restrict__ bet) {
    int token = blockIdx.x * 256 + threadIdx.x;
    int bt = token >> 10, hw = token & 1023;
    int b = bt >> 4, t = bt & 15;
    int sb = bt * 32;
    __half* o = g_nrm16 + (size_t)token * 192;
    for (int g = 0; g < 32; g++) {
        float mu = g_stat[(sb + g) * 2], iv = g_stat[(sb + g) * 2 + 1];
        const float* xc = x + (((size_t)(b * CCH + g * 6) * 16 + t) << 10) + hw;
        #pragma unroll
        for (int j = 0; j < 6; j += 2) {
            int c = g * 6 + j;
            float v0 = xc[(size_t)j << 14], v1 = xc[(size_t)(j + 1) << 14];
            __half2 hh = __floats2half2_rn((v0 - mu) * iv * gam[c] + bet[c],
                                           (v1 - mu) * iv * gam[c + 1] + bet[c + 1]);
            *(__half2*)(o + c) = hh;
        }
    }
}

// ---------------------------------------------------------------------------
// GroupNorm pass 2
// ---------------------------------------------------------------------------
__global__ void k_gn2h(const float* __restrict__ X, const float* __restrict__ gam,
                       const float* __restrict__ bet, __half* __restrict__ out16) {
    int n = blockIdx.x;
    __shared__ float buf[3072];
    __shared__ float mu[32], iv[32];
    int tid = threadIdx.x;
    const float4* xb = (const float4*)(X + (size_t)n * 3072);
    for (int i = tid; i < 768; i += 128) ((float4*)buf)[i] = xb[i];
    __syncthreads();
    int w = tid >> 5, lane = tid & 31;
    for (int g = w; g < 32; g += 4) {
        float v0 = buf[g * 96 + lane], v1 = buf[g * 96 + 32 + lane], v2 = buf[g * 96 + 64 + lane];
        float s = v0 + v1 + v2, q = v0 * v0 + v1 * v1 + v2 * v2;
        #pragma unroll
        for (int off = 16; off; off >>= 1) {
            s += __shfl_xor_sync(0xffffffffu, s, off);
            q += __shfl_xor_sync(0xffffffffu, q, off);
        }
        if (lane == 0) {
            float m = s / 96.f, va = q / 96.f - m * m;
            mu[g] = m; iv[g] = rsqrtf(va + 1e-5f);
        }
    }
    __syncthreads();
    __half* ob = out16 + (size_t)n * 3072;
    for (int j = tid; j < 3072; j += 128) {
        int t = j / 192, c = j - t * 192;
        int g = c / 6;
        ob[j] = __float2half((buf[c * 16 + t] - mu[g]) * iv[g] * gam[c] + bet[c]);
    }
}

// ---------------------------------------------------------------------------
// Tiled fp32 transposes
// ---------------------------------------------------------------------------
__global__ void k_transpose2t() {   // y (bt,c,hw) -> yt (bhw,c,t)
    __shared__ float sm[64][20];
    int hw0 = blockIdx.x * 64, c = blockIdx.y, b = blockIdx.z;
    int tid = threadIdx.x;
    {
        int t = tid & 15, hwj = (tid >> 4) * 4;
        float4 v = *(const float4*)&g_y[(((size_t)(b * 16 + t) * CCH + c) << 10) + hw0 + hwj];
        sm[hwj + 0][t] = v.x; sm[hwj + 1][t] = v.y;
        sm[hwj + 2][t] = v.z; sm[hwj + 3][t] = v.w;
    }
    __syncthreads();
    {
        int hwl = tid >> 2, t4 = (tid & 3) * 4;
        *(float4*)&g_yt[((size_t)(b * 1024 + hw0 + hwl) * CCH + c) * 16 + t4] =
            *(const float4*)&sm[hwl][t4];
    }
}

__global__ void k_transpose3t(float* __restrict__ out) {  // z (bhw,c,t) -> (b,c,t,hw)
    __shared__ float sm[16][68];
    int hw0 = blockIdx.x * 64, c = blockIdx.y, b = blockIdx.z;
    int tid = threadIdx.x;
    {
        int hwl = tid >> 2, t4 = (tid & 3) * 4;
        float4 v = *(const float4*)&g_xs[((size_t)(b * 1024 + hw0 + hwl) * CCH + c) * 16 + t4];
        sm[t4 + 0][hwl] = v.x; sm[t4 + 1][hwl] = v.y;
        sm[t4 + 2][hwl] = v.z; sm[t4 + 3][hwl] = v.w;
    }
    __syncthreads();
    {
        int t = tid >> 4, hw4 = (tid & 15) * 4;
        *(float4*)&out[(((size_t)(b * CCH + c) * 16 + t) << 10) + hw0 + hw4] =
            *(const float4*)&sm[t][hw4];
    }
}

// ---------------------------------------------------------------------------
// 1x1 conv, fp16 MMA + ldmatrix fragments, cp.async double buffered.
// ---------------------------------------------------------------------------
#define XS(b,t,k) SM[(b)*5120 + (t)*40 + (k)]
#define WS(b,o,k) SM[10240 + (b)*2560 + (o)*40 + (k)]

__global__ __launch_bounds__(128, 4) void k_convh(
    const __half* __restrict__ X, const __half* __restrict__ W,
    const float* __restrict__ bias, const float* __restrict__ res,
    float* __restrict__ outf, __half* __restrict__ outqk, __half* __restrict__ outv,
    int Cout, int ls, int mode) {
    __shared__ __align__(16) __half SM[15360];
    const int tid = threadIdx.x, lane = tid & 31, w = tid >> 5;
    const int r = lane >> 2, tg = lane & 3;
    const int g0 = blockIdx.x * 128, o0 = blockIdx.y * 64;
    const int ob0 = 32 * (w >> 1), coff = (w & 1) * 64;
    const int L = 1 << ls, Lm1 = L - 1;
    // ldmatrix lane-address components
    const int aRow = (lane & 7) + 8 * ((lane >> 3) & 1);
    const int aCol = 8 * (lane >> 4);
    const int bRow = (lane & 7) + 8 * (lane >> 4);
    const int bCol = 8 * ((lane >> 3) & 1);

    float4 acc[2][8];
    #pragma unroll
    for (int ms = 0; ms < 2; ms++)
        #pragma unroll
        for (int nt = 0; nt < 8; nt++) acc[ms][nt] = make_float4(0.f, 0.f, 0.f, 0.f);

    const __half* xsrc = X + (size_t)(g0 + tid) * 192;
    const int wo = tid & 63, wp = (tid >> 6) * 16;
    const __half* wsrc = W + (size_t)(o0 + wo) * 192 + wp;

    // prologue chunk 0
    #pragma unroll
    for (int j = 0; j < 4; j++) cp16(sptr(&XS(0, tid, j * 8)), xsrc + j * 8);
    #pragma unroll
    for (int j = 0; j < 2; j++) cp16(sptr(&WS(0, wo, wp + j * 8)), wsrc + j * 8);
    cp_commit();

    for (int c = 0; c < 6; c++) {
        const int buf = c & 1;
        if (c < 5) {
            const int cc = (c + 1) * 32;
            #pragma unroll
            for (int j = 0; j < 4; j++)
                cp16(sptr(&XS(buf ^ 1, tid, j * 8)), xsrc + cc + j * 8);
            #pragma unroll
            for (int j = 0; j < 2; j++)
                cp16(sptr(&WS(buf ^ 1, wo, wp + j * 8)), wsrc + cc + j * 8);
            cp_commit();
            cp_wait<1>();
        } else {
            cp_wait<0>();
        }
        __syncthreads();
        #pragma unroll
        for (int ks = 0; ks < 2; ks++) {
            uint32 a0[4], a1[4];
            ldsm4(a0, sptr(&WS(buf, ob0 + aRow,      ks * 16 + aCol)));
            ldsm4(a1, sptr(&WS(buf, ob0 + 16 + aRow, ks * 16 + aCol)));
            #pragma unroll
            for (int pr = 0; pr < 4; pr++) {
                uint32 b[4];
                ldsm4(b, sptr(&XS(buf, coff + pr * 16 + bRow, ks * 16 + bCol)));
                mmah(acc[0][2 * pr],     a0, b[0], b[1]);
                mmah(acc[0][2 * pr + 1], a0, b[2], b[3]);
                mmah(acc[1][2 * pr],     a1, b[0], b[1]);
                mmah(acc[1][2 * pr + 1], a1, b[2], b[3]);
            }
        }
        __syncthreads();
    }

    // ---- epilogue ----
    if (mode == 0) {
        const int ha = o0 / 192;
        const int pa = (o0 - ha * 192) >> 6;
        if (pa < 2) {
            #pragma unroll
            for (int ms = 0; ms < 2; ms++) {
                const int c0 = ob0 + 16 * ms + r;
                const float ba = bias[o0 + c0], bb = bias[o0 + c0 + 8];
                #pragma unroll
                for (int nt = 0; nt < 8; nt++) {
                    const int tok = coff + nt * 8 + 2 * tg;
                    SM[tok * 72 + c0]           = __float2half(acc[ms][nt].x + ba);
                    SM[(tok + 1) * 72 + c0]     = __float2half(acc[ms][nt].y + ba);
                    SM[tok * 72 + c0 + 8]       = __float2half(acc[ms][nt].z + bb);
                    SM[(tok + 1) * 72 + c0 + 8] = __float2half(acc[ms][nt].w + bb);
                }
            }
            __syncthreads();
            const int base = ha * 128 + pa * 64;
            #pragma unroll
            for (int i = 0; i < 8; i++) {
                int j = tid + 128 * i;
                int tok = j >> 3, seg = j & 7;
                *(uint4*)(outqk + (size_t)(g0 + tok) * 384 + base + seg * 8) =
                    *(const uint4*)(SM + tok * 72 + seg * 8);
            }
        } else {
            #pragma unroll
            for (int ms = 0; ms < 2; ms++) {
                const int c0 = ob0 + 16 * ms + r;
                const float ba = bias[o0 + c0], bb = bias[o0 + c0 + 8];
                #pragma unroll
                for (int nt = 0; nt < 8; nt++) {
                    const int tok = coff + nt * 8 + 2 * tg;
                    *(__half2*)(SM + c0 * 136 + tok) =
                        __floats2half2_rn(acc[ms][nt].x + ba, acc[ms][nt].y + ba);
                    *(__half2*)(SM + (c0 + 8) * 136 + tok) =
                        __floats2half2_rn(acc[ms][nt].z + bb, acc[ms][nt].w + bb);
                }
            }
            __syncthreads();
            const int cvb = ha * 64;
            #pragma unroll
            for (int i = 0; i < 8; i++) {
                int j = tid + 128 * i;
                int ch = j >> 4, seg = j & 15;
                int gt = g0 + seg * 8;
                int img = gt >> ls, tok = gt & Lm1;
                *(uint4*)(outv + ((size_t)img * 192 + cvb + ch) * L + tok) =
                    *(const uint4*)(SM + ch * 136 + seg * 8);
            }
        }
    } else {
        #pragma unroll
        for (int ms = 0; ms < 2; ms++) {
            const int oa = o0 + ob0 + 16 * ms + r;
            const int obr = oa + 8;
            const float ba = bias[oa], bb = bias[obr];
            #pragma unroll
            for (int nt = 0; nt < 8; nt++) {
                int g = g0 + coff + nt * 8 + 2 * tg;
                float vax = acc[ms][nt].x + ba, vay = acc[ms][nt].y + ba;
                float vbx = acc[ms][nt].z + bb, vby = acc[ms][nt].w + bb;
                int n = g >> ls, l = g & Lm1;
                size_t pAa = ((size_t)n * Cout + oa) * L + l;
                size_t pBb = ((size_t)n * Cout + obr) * L + l;
                float2 va = make_float2(vax, vay);
                float2 vb = make_float2(vbx, vby);
                if (mode == 1) {
                    float2 qa = *(const float2*)(res + pAa);
                    float2 qb = *(const float2*)(res + pBb);
                    va.x += qa.x; va.y += qa.y; vb.x += qb.x; vb.y += qb.y;
                } else {
                    int b = n >> 4, t = n & 15;
                    size_t xa = (((size_t)(b * 192 + oa) * 16 + t) << 10) + l;
                    size_t xb = (((size_t)(b * 192 + obr) * 16 + t) << 10) + l;
                    float2 qa = *(const float2*)(res + xa);
                    float2 qb = *(const float2*)(res + xb);
                    va.x += qa.x; va.y += qa.y; vb.x += qb.x; vb.y += qb.y;
                }
                *(float2*)(outf + pAa) = va;
                *(float2*)(outf + pBb) = vb;
            }
        }
    }
}

// ---------------------------------------------------------------------------
// Attention pass 1: flash fp16 MMA + ldmatrix fragments.
// ---------------------------------------------------------------------------
#define HS 72

__global__ __launch_bounds__(128, 4) void k_attn1h(const __half* __restrict__ qk,
                                                   const __half* __restrict__ vT,
                                                   __half* __restrict__ outh) {
    __shared__ __align__(16) __half smh[4 * 64 * HS];
    __half* U  = smh;
    __half* K0 = smh + 64 * HS;
    __half* K1 = smh + 2 * 64 * HS;
    __half* Vt = smh + 3 * 64 * HS;

    const int tid = threadIdx.x, lane = tid & 31, w = tid >> 5;
    const int r = lane >> 2, tg = lane & 3;
    const int bh = blockIdx.y, n = bh / 3, h = bh % 3;
    const int q0 = blockIdx.x * 64;
    const __half* Qg = qk + ((size_t)(n * 1024) + q0) * 384 + h * 128;
    const __half* Kg = qk + (size_t)(n * 1024) * 384 + h * 128 + 64;
    const __half* Vg = vT + (size_t)(n * 192 + h * 64) * 1024;
    // ldmatrix lane-address components
    const int aRow = (lane & 7) + 8 * ((lane >> 3) & 1);
    const int aCol = 8 * (lane >> 4);
    const int bRow = (lane & 7) + 8 * (lane >> 4);
    const int bCol = 8 * ((lane >> 3) & 1);

    const int stok = tid >> 1, seg = (tid & 1) * 32;

    // prologue: K tile 0 and Q
    #pragma unroll
    for (int i = 0; i < 4; i++)
        cp16(sptr(&K0[stok * HS + seg + i * 8]), Kg + (size_t)stok * 384 + seg + i * 8);
    #pragma unroll
    for (int i = 0; i < 4; i++)
        cp16(sptr(&U[stok * HS + seg + i * 8]), Qg + (size_t)stok * 384 + seg + i * 8);
    cp_commit();
    cp_wait<0>();
    __syncthreads();

    // Q fragments persistent (U gets reused for P afterwards)
    uint32 qa[4][4];
    #pragma unroll
    for (int ks = 0; ks < 4; ks++)
        ldsm4(qa[ks], sptr(&U[(16 * w + aRow) * HS + ks * 16 + aCol]));

    float4 o[8];
    #pragma unroll
    for (int nt = 0; nt < 8; nt++) o[nt] = make_float4(0.f, 0.f, 0.f, 0.f);
    float m0 = -1e30f, m1 = -1e30f, s0 = 0.f, s1 = 0.f;
    __half* pr0h = U + (16 * w + r) * HS;
    __half* pr1h = U + (16 * w + r + 8) * HS;
    const float SC = 0.125f;   // ch^-0.5 combined score scale

    for (int kt = 0; kt < 16; kt++) {
        const int buf = kt & 1;
        // stage V(kt)
        {
            const int sb = kt * 64;
            #pragma unroll
            for (int i = 0; i < 4; i++)
                cp16(sptr(&Vt[stok * HS + seg + i * 8]),
                     Vg + (size_t)stok * 1024 + sb + seg + i * 8);
            cp_commit();
        }
        // stage K(kt+1)
        if (kt < 15) {
            const int sb = (kt + 1) * 64;
            __half* Kn = buf ? K0 : K1;
            #pragma unroll
            for (int i = 0; i < 4; i++)
                cp16(sptr(&Kn[stok * HS + seg + i * 8]),
                     Kg + (size_t)(sb + stok) * 384 + seg + i * 8);
        }
        cp_commit();
        cp_wait<2>();
        __syncthreads();
        const __half* Ks = buf ? K1 : K0;

        // S = Q K^T
        float4 sc[8];
        #pragma unroll
        for (int nt = 0; nt < 8; nt++) sc[nt] = make_float4(0.f, 0.f, 0.f, 0.f);
        #pragma unroll
        for (int ks = 0; ks < 4; ks++) {
            #pragma unroll
            for (int pr = 0; pr < 4; pr++) {
                uint32 b[4];
                ldsm4(b, sptr(&Ks[(pr * 16 + bRow) * HS + ks * 16 + bCol]));
                mmah(sc[2 * pr],     qa[ks], b[0], b[1]);
                mmah(sc[2 * pr + 1], qa[ks], b[2], b[3]);
            }
        }

        // online softmax
        float tm0 = -1e30f, tm1 = -1e30f;
        #pragma unroll
        for (int nt = 0; nt < 8; nt++) {
            tm0 = fmaxf(tm0, fmaxf(sc[nt].x, sc[nt].y));
            tm1 = fmaxf(tm1, fmaxf(sc[nt].z, sc[nt].w));
        }
        tm0 = fmaxf(tm0, __shfl_xor_sync(0xffffffffu, tm0, 1));
        tm0 = fmaxf(tm0, __shfl_xor_sync(0xffffffffu, tm0, 2));
        tm1 = fmaxf(tm1, __shfl_xor_sync(0xffffffffu, tm1, 1));
        tm1 = fmaxf(tm1, __shfl_xor_sync(0xffffffffu, tm1, 2));
        tm0 *= SC; tm1 *= SC;
        float nm0 = fmaxf(m0, tm0), nm1 = fmaxf(m1, tm1);
        float a0 = __expf(m0 - nm0), a1 = __expf(m1 - nm1);
        float t0 = 0.f, t1 = 0.f;
        #pragma unroll
        for (int nt = 0; nt < 8; nt++) {
            float px = __expf(fmaf(sc[nt].x, SC, -nm0));
            float py = __expf(fmaf(sc[nt].y, SC, -nm0));
            float pz = __expf(fmaf(sc[nt].z, SC, -nm1));
            float pw = __expf(fmaf(sc[nt].w, SC, -nm1));
            t0 += px + py; t1 += pz + pw;
            const int col = nt * 8 + 2 * tg;
            *(__half2*)(pr0h + col) = __floats2half2_rn(px, py);
            *(__half2*)(pr1h + col) = __floats2half2_rn(pz, pw);
            o[nt].x *= a0; o[nt].y *= a0;
            o[nt].z *= a1; o[nt].w *= a1;
        }
        t0 += __shfl_xor_sync(0xffffffffu, t0, 1);
        t0 += __shfl_xor_sync(0xffffffffu, t0, 2);
        t1 += __shfl_xor_sync(0xffffffffu, t1, 1);
        t1 += __shfl_xor_sync(0xffffffffu, t1, 2);
        s0 = s0 * a0 + t0;
        s1 = s1 * a1 + t1;
        m0 = nm0; m1 = nm1;
        __syncwarp();

        cp_wait<1>();     // V(kt) complete
        __syncthreads();

        // O += P V
        #pragma unroll
        for (int ks = 0; ks < 4; ks++) {
            uint32 a[4];
            ldsm4(a, sptr(&U[(16 * w + aRow) * HS + ks * 16 + aCol]));
            #pragma unroll
            for (int pr = 0; pr < 4; pr++) {
                uint32 b[4];
                ldsm4(b, sptr(&Vt[(pr * 16 + bRow) * HS + ks * 16 + bCol]));
                mmah(o[2 * pr],     a, b[0], b[1]);
                mmah(o[2 * pr + 1], a, b[2], b[3]);
            }
        }
        __syncthreads();
    }

    // normalize, stage to smem (K0), coalesced half write (channel-last)
    float i0 = 1.f / s0, i1 = 1.f / s1;
    __half* Os = K0;
    #pragma unroll
    for (int nt = 0; nt < 8; nt++) {
        const int col = nt * 8 + 2 * tg;
        *(__half2*)(Os + (16 * w + r) * HS + col)     = __floats2half2_rn(o[nt].x * i0, o[nt].y * i0);
        *(__half2*)(Os + (16 * w + r + 8) * HS + col) = __floats2half2_rn(o[nt].z * i1, o[nt].w * i1);
    }
    __syncthreads();
    __half* dst = outh + ((size_t)(n * 1024) + q0 + stok) * 192 + h * 64 + seg;
    #pragma unroll
    for (int i = 0; i < 4; i++)
        *(uint4*)(dst + i * 8) = *(const uint4*)(Os + stok * HS + seg + i * 8);
}

// ---------------------------------------------------------------------------
// Attention pass 2: L=16, scalar fp32 from half inputs
// ---------------------------------------------------------------------------
__global__ void k_attn2h(const __half* __restrict__ qkh, const __half* __restrict__ vTh,
                         __half* __restrict__ outh) {
    __shared__ float qs[16][68], ks[16][68], vs[1024], S[16 * 17];
    int bh = blockIdx.x, n = bh / 3, h = bh % 3;
    int tid = threadIdx.x;
    const __half* Qb = qkh + (size_t)(n * 16) * 384 + h * 128;
    const __half* Vb = vTh + (size_t)(n * 192 + h * 64) * 16;
    for (int i = tid; i < 1024; i += 256) {
        int q = i >> 6, c = i & 63;
        qs[q][c] = __half2float(Qb[(size_t)q * 384 + c]) * 0.125f;
        ks[q][c] = __half2float(Qb[(size_t)q * 384 + 64 + c]);
        vs[i] = __half2float(Vb[i]);
    }
    __syncthreads();
    {
        int q = tid >> 4, s = tid & 15;
        float a = 0.f;
        #pragma unroll
        for (int c = 0; c < 64; c++) a += qs[q][c] * ks[s][c];
        S[q * 17 + s] = a;
    }
    __syncthreads();
    if (tid < 16) {
        float* row = S + tid * 17;
        float m = -1e30f;
        #pragma unroll
        for (int s = 0; s < 16; s++) m = fmaxf(m, row[s]);
        float sum = 0.f;
        #pragma unroll
        for (int s = 0; s < 16; s++) { float e = __expf(row[s] - m); row[s] = e; sum += e; }
        float inv = 1.f / sum;
        #pragma unroll
        for (int s = 0; s < 16; s++) row[s] *= inv;
    }
    __syncthreads();
    {
        int q = tid & 15;
        int cb = (tid >> 4) << 2;
        float a0 = 0.f, a1 = 0.f, a2 = 0.f, a3 = 0.f;
        #pragma unroll
        for (int s = 0; s < 16; s++) {
            float sv = S[q * 17 + s];
            a0 += vs[(cb + 0) * 16 + s] * sv;
            a1 += vs[(cb + 1) * 16 + s] * sv;
            a2 += vs[(cb + 2) * 16 + s] * sv;
            a3 += vs[(cb + 3) * 16 + s] * sv;
        }
        __half* ob = outh + ((size_t)(n * 16) + q) * 192 + h * 64 + cb;
        ob[0] = __float2half(a0);
        ob[1] = __float2half(a1);
        ob[2] = __float2half(a2);
        ob[3] = __float2half(a3);
    }
}

// ---------------------------------------------------------------------------
extern "C" void kernel_launch(void* const* d_in, const int* in_sizes, int n_in,
                              void* d_out, int out_size) {
    const float* x       = (const float*)d_in[0];
    const float* norm_g  = (const float*)d_in[1];
    const float* norm_b  = (const float*)d_in[2];
    const float* qkv_w   = (const float*)d_in[3];
    const float* qkv_b   = (const float*)d_in[4];
    const float* proj_w  = (const float*)d_in[5];
    const float* proj_b  = (const float*)d_in[6];
    const float* normt_g = (const float*)d_in[7];
    const float* normt_b = (const float*)d_in[8];
    const float* qkvt_w  = (const float*)d_in[9];
    const float* qkvt_b  = (const float*)d_in[10];
    const float* projt_w = (const float*)d_in[11];
    const float* projt_b = (const float*)d_in[12];
    float* out = (float*)d_out;

    float *xs, *y, *yt;
    __half *nrm16, *qk16, *v16T, *att16, *w16;
    cudaGetSymbolAddress((void**)&xs,    g_xs);
    cudaGetSymbolAddress((void**)&y,     g_y);
    cudaGetSymbolAddress((void**)&yt,    g_yt);
    cudaGetSymbolAddress((void**)&nrm16, g_nrm16);
    cudaGetSymbolAddress((void**)&qk16,  g_qk16);
    cudaGetSymbolAddress((void**)&v16T,  g_v16T);
    cudaGetSymbolAddress((void**)&att16, g_att16);
    cudaGetSymbolAddress((void**)&w16,   g_w16);

    const __half* w_qkv  = w16;
    const __half* w_proj = w16 + 110592;
    const __half* w_qkvt = w16 + 147456;
    const __half* w_projt= w16 + 258048;

    k_wprep<<<288, 1024>>>(qkv_w, proj_w, qkvt_w, projt_w);

    // ---- pass 1 (spatial, L=1024) ----
    k_gn1s<<<NBT * 32, 256>>>(x);
    k_gn1a<<<128, 256>>>(x, norm_g, norm_b);
    k_convh<<<dim3(256, 9), 128>>>(nrm16, w_qkv, qkv_b, nullptr,
                                   nullptr, qk16, v16T, 576, 10, 0);
    k_attn1h<<<dim3(16, 96), 128>>>(qk16, v16T, att16);
    k_convh<<<dim3(256, 3), 128>>>(att16, w_proj, proj_b, x,
                                   y, nullptr, nullptr, 192, 10, 2);

    // ---- pass 2 (temporal, L=16) ----
    k_transpose2t<<<dim3(16, 192, 2), 256>>>();
    k_gn2h<<<2048, 128>>>(yt, normt_g, normt_b, nrm16);
    k_convh<<<dim3(256, 9), 128>>>(nrm16, w_qkvt, qkvt_b, nullptr,
                                   nullptr, qk16, v16T, 576, 4, 0);
    k_attn2h<<<6144, 256>>>(qk16, v16T, att16);
    k_convh<<<dim3(256, 3), 128>>>(att16, w_projt, projt_b, yt,
                                   xs, nullptr, nullptr, 192, 4, 1);
    k_transpose3t<<<dim3(16, 192, 2), 256>>>(out);
}

// round 13
// speedup vs baseline: 10.3321x; 1.0427x over previous
#include <cuda_runtime.h>
#include <cuda_fp16.h>
#include <math.h>

#define NBT 32
#define CCH 192
#define TOT (NBT*CCH*1024)
typedef unsigned int uint32;

// fp32 scratch
__device__ float g_xs [TOT];          // z (bhw,c,t) in pass2
__device__ float g_y  [TOT];
__device__ float g_yt [TOT];
__device__ float g_stat[NBT*32*2];
// fp16 scratch
__device__ __half g_nrm16[32768*192];
__device__ __half g_qk16 [32768*384];
__device__ __half g_v16T [32768*192];
__device__ __half g_att16[32768*192];
__device__ __half g_w16  [294912];

// ---- helpers ----------------------------------------------------------------
__device__ __forceinline__ void mmah(float4 &c, const uint32* a, uint32 b0, uint32 b1) {
    asm("mma.sync.aligned.m16n8k16.row.col.f32.f16.f16.f32 "
        "{%0,%1,%2,%3},{%4,%5,%6,%7},{%8,%9},{%0,%1,%2,%3};"
        : "+f"(c.x), "+f"(c.y), "+f"(c.z), "+f"(c.w)
        : "r"(a[0]), "r"(a[1]), "r"(a[2]), "r"(a[3]), "r"(b0), "r"(b1));
}
__device__ __forceinline__ uint32 sptr(const void* p) {
    return (uint32)__cvta_generic_to_shared(p);
}
__device__ __forceinline__ void ldsm4(uint32* r, uint32 addr) {
    asm volatile("ldmatrix.sync.aligned.m8n8.x4.shared.b16 {%0,%1,%2,%3}, [%4];"
        : "=r"(r[0]), "=r"(r[1]), "=r"(r[2]), "=r"(r[3]) : "r"(addr));
}
__device__ __forceinline__ void cp16(uint32 s, const void* g) {
    asm volatile("cp.async.ca.shared.global [%0], [%1], 16;" :: "r"(s), "l"(g));
}
__device__ __forceinline__ void cp_commit() { asm volatile("cp.async.commit_group;"); }
template<int N> __device__ __forceinline__ void cp_wait() {
    asm volatile("cp.async.wait_group %0;" :: "n"(N));
}

// ---------------------------------------------------------------------------
// Weight fp16 prep
// ---------------------------------------------------------------------------
__global__ void k_wprep(const float* __restrict__ qw, const float* __restrict__ pw,
                        const float* __restrict__ qtw, const float* __restrict__ ptw) {
    int i = blockIdx.x * 1024 + threadIdx.x;
    float v;
    if      (i < 110592) v = qw[i];
    else if (i < 147456) v = pw[i - 110592];
    else if (i < 258048) v = qtw[i - 147456];
    else                 v = ptw[i - 258048];
    g_w16[i] = __float2half(v);
}

// ---------------------------------------------------------------------------
// GroupNorm pass 1 stats
// ---------------------------------------------------------------------------
__global__ void k_gn1s(const float* __restrict__ x) {
    int n = blockIdx.x >> 5, g = blockIdx.x & 31;
    int b = n >> 4, t = n & 15;
    const float* xb = x + (((size_t)(b * CCH + g * 6) * 16 + t) << 10);
    int tid = threadIdx.x;
    float s = 0.f, q = 0.f;
    for (int i = tid; i < 6144; i += 256) {
        float v = xb[((size_t)(i >> 10) << 14) + (i & 1023)];
        s += v; q += v * v;
    }
    __shared__ float rs[256], rq[256];
    rs[tid] = s; rq[tid] = q;
    __syncthreads();
    for (int st = 128; st > 0; st >>= 1) {
        if (tid < st) { rs[tid] += rs[tid + st]; rq[tid] += rq[tid + st]; }
        __syncthreads();
    }
    if (tid == 0) {
        float mean = rs[0] / 6144.f;
        float var  = rq[0] / 6144.f - mean * mean;
        g_stat[blockIdx.x * 2]     = mean;
        g_stat[blockIdx.x * 2 + 1] = rsqrtf(var + 1e-5f);
    }
}

// ---------------------------------------------------------------------------
// GroupNorm pass 1 apply, tiled: block = (64 hw, one bt). Coalesced both sides.
// ---------------------------------------------------------------------------
__global__ __launch_bounds__(256) void k_gn1at(const float* __restrict__ x,
                                               const float* __restrict__ gam,
                                               const float* __restrict__ bet) {
    __shared__ __half sbuf[64 * 200];
    const int hw0 = blockIdx.x * 64, bt = blockIdx.y;
    const int b = bt >> 4, t = bt & 15;
    const int tid = threadIdx.x;
    #pragma unroll
    for (int rep = 0; rep < 3; rep++) {
        const int c = rep * 64 + (tid >> 2);
        const int hwq = (tid & 3) * 16;
        const int g = c / 6;
        const float mu = g_stat[(bt * 32 + g) * 2];
        const float iv = g_stat[(bt * 32 + g) * 2 + 1];
        const float ga = gam[c] * iv;
        const float be = bet[c] - mu * ga;
        const float* src = x + (((size_t)(b * CCH + c) * 16 + t) << 10) + hw0 + hwq;
        #pragma unroll
        for (int j = 0; j < 16; j += 4) {
            float4 v = *(const float4*)(src + j);
            sbuf[(hwq + j + 0) * 200 + c] = __float2half(v.x * ga + be);
            sbuf[(hwq + j + 1) * 200 + c] = __float2half(v.y * ga + be);
            sbuf[(hwq + j + 2) * 200 + c] = __float2half(v.z * ga + be);
            sbuf[(hwq + j + 3) * 200 + c] = __float2half(v.w * ga + be);
        }
    }
    __syncthreads();
    #pragma unroll
    for (int i = tid; i < 1536; i += 256) {
        int tok = i / 24, seg = i - tok * 24;
        *(uint4*)(g_nrm16 + ((size_t)(bt * 1024 + hw0 + tok)) * 192 + seg * 8) =
            *(const uint4*)(sbuf + tok * 200 + seg * 8);
    }
}

// ---------------------------------------------------------------------------
// GroupNorm pass 2
// ---------------------------------------------------------------------------
__global__ void k_gn2h(const float* __restrict__ X, const float* __restrict__ gam,
                       const float* __restrict__ bet, __half* __restrict__ out16) {
    int n = blockIdx.x;
    __shared__ float buf[3072];
    __shared__ float mu[32], iv[32];
    int tid = threadIdx.x;
    const float4* xb = (const float4*)(X + (size_t)n * 3072);
    for (int i = tid; i < 768; i += 128) ((float4*)buf)[i] = xb[i];
    __syncthreads();
    int w = tid >> 5, lane = tid & 31;
    for (int g = w; g < 32; g += 4) {
        float v0 = buf[g * 96 + lane], v1 = buf[g * 96 + 32 + lane], v2 = buf[g * 96 + 64 + lane];
        float s = v0 + v1 + v2, q = v0 * v0 + v1 * v1 + v2 * v2;
        #pragma unroll
        for (int off = 16; off; off >>= 1) {
            s += __shfl_xor_sync(0xffffffffu, s, off);
            q += __shfl_xor_sync(0xffffffffu, q, off);
        }
        if (lane == 0) {
            float m = s / 96.f, va = q / 96.f - m * m;
            mu[g] = m; iv[g] = rsqrtf(va + 1e-5f);
        }
    }
    __syncthreads();
    __half* ob = out16 + (size_t)n * 3072;
    for (int j = tid; j < 3072; j += 128) {
        int t = j / 192, c = j - t * 192;
        int g = c / 6;
        ob[j] = __float2half((buf[c * 16 + t] - mu[g]) * iv[g] * gam[c] + bet[c]);
    }
}

// ---------------------------------------------------------------------------
// c-blocked transposes: 4 channels per block, full-line access both sides.
// smem layout: sb[c*1296 + hw*20 + t] (c-stride 1296 => LDS.128 bank-split)
// ---------------------------------------------------------------------------
__global__ __launch_bounds__(256) void k_transpose2c() {  // y (bt,c,hw) -> yt (bhw,c,t)
    __shared__ float sb[5168];
    const int hw0 = blockIdx.x * 64, c0 = blockIdx.y * 4, b = blockIdx.z;
    const int tid = threadIdx.x, w = tid >> 5, lane = tid & 31;
    #pragma unroll
    for (int it = 0; it < 8; it++) {
        int p = it * 8 + w;          // 0..63
        int c = p >> 4, t = p & 15;
        float2 v = *(const float2*)&g_y[(((size_t)(b * 16 + t) * CCH + c0 + c) << 10)
                                        + hw0 + lane * 2];
        sb[c * 1296 + (lane * 2) * 20 + t]     = v.x;
        sb[c * 1296 + (lane * 2 + 1) * 20 + t] = v.y;
    }
    __syncthreads();
    #pragma unroll
    for (int i2 = 0; i2 < 4; i2++) {
        int u = tid + 256 * i2;      // 0..1023
        int hw = u >> 4, q = u & 15;
        int c = q >> 2, t4 = (q & 3) * 4;
        *(float4*)&g_yt[((size_t)(b * 1024 + hw0 + hw) * CCH + c0 + c) * 16 + t4] =
            *(const float4*)&sb[c * 1296 + hw * 20 + t4];
    }
}

__global__ __launch_bounds__(256) void k_transpose3c(float* __restrict__ out) {
    // z (bhw,c,t) -> out (b,c,t,hw)
    __shared__ float sb[5168];
    const int hw0 = blockIdx.x * 64, c0 = blockIdx.y * 4, b = blockIdx.z;
    const int tid = threadIdx.x, w = tid >> 5, lane = tid & 31;
    #pragma unroll
    for (int i2 = 0; i2 < 4; i2++) {
        int u = tid + 256 * i2;
        int hw = u >> 4, q = u & 15;
        int c = q >> 2, t4 = (q & 3) * 4;
        *(float4*)&sb[c * 1296 + hw * 20 + t4] =
            *(const float4*)&g_xs[((size_t)(b * 1024 + hw0 + hw) * CCH + c0 + c) * 16 + t4];
    }
    __syncthreads();
    #pragma unroll
    for (int it = 0; it < 8; it++) {
        int p = it * 8 + w;
        int c = p >> 4, t = p & 15;
        float2 v = make_float2(sb[c * 1296 + (lane * 2) * 20 + t],
                               sb[c * 1296 + (lane * 2 + 1) * 20 + t]);
        *(float2*)&out[(((size_t)(b * CCH + c0 + c) * 16 + t) << 10) + hw0 + lane * 2] = v;
    }
}

// ---------------------------------------------------------------------------
// 1x1 conv, fp16 MMA + ldmatrix fragments, cp.async double buffered.
// ---------------------------------------------------------------------------
#define XS(b,t,k) SM[(b)*5120 + (t)*40 + (k)]
#define WS(b,o,k) SM[10240 + (b)*2560 + (o)*40 + (k)]

__global__ __launch_bounds__(128, 4) void k_convh(
    const __half* __restrict__ X, const __half* __restrict__ W,
    const float* __restrict__ bias, const float* __restrict__ res,
    float* __restrict__ outf, __half* __restrict__ outqk, __half* __restrict__ outv,
    int Cout, int ls, int mode) {
    __shared__ __align__(16) __half SM[15360];
    const int tid = threadIdx.x, lane = tid & 31, w = tid >> 5;
    const int r = lane >> 2, tg = lane & 3;
    const int g0 = blockIdx.x * 128, o0 = blockIdx.y * 64;
    const int ob0 = 32 * (w >> 1), coff = (w & 1) * 64;
    const int L = 1 << ls, Lm1 = L - 1;
    const int aRow = (lane & 7) + 8 * ((lane >> 3) & 1);
    const int aCol = 8 * (lane >> 4);
    const int bRow = (lane & 7) + 8 * (lane >> 4);
    const int bCol = 8 * ((lane >> 3) & 1);

    float4 acc[2][8];
    #pragma unroll
    for (int ms = 0; ms < 2; ms++)
        #pragma unroll
        for (int nt = 0; nt < 8; nt++) acc[ms][nt] = make_float4(0.f, 0.f, 0.f, 0.f);

    const __half* xsrc = X + (size_t)(g0 + tid) * 192;
    const int wo = tid & 63, wp = (tid >> 6) * 16;
    const __half* wsrc = W + (size_t)(o0 + wo) * 192 + wp;

    #pragma unroll
    for (int j = 0; j < 4; j++) cp16(sptr(&XS(0, tid, j * 8)), xsrc + j * 8);
    #pragma unroll
    for (int j = 0; j < 2; j++) cp16(sptr(&WS(0, wo, wp + j * 8)), wsrc + j * 8);
    cp_commit();

    for (int c = 0; c < 6; c++) {
        const int buf = c & 1;
        if (c < 5) {
            const int cc = (c + 1) * 32;
            #pragma unroll
            for (int j = 0; j < 4; j++)
                cp16(sptr(&XS(buf ^ 1, tid, j * 8)), xsrc + cc + j * 8);
            #pragma unroll
            for (int j = 0; j < 2; j++)
                cp16(sptr(&WS(buf ^ 1, wo, wp + j * 8)), wsrc + cc + j * 8);
            cp_commit();
            cp_wait<1>();
        } else {
            cp_wait<0>();
        }
        __syncthreads();
        #pragma unroll
        for (int ks = 0; ks < 2; ks++) {
            uint32 a0[4], a1[4];
            ldsm4(a0, sptr(&WS(buf, ob0 + aRow,      ks * 16 + aCol)));
            ldsm4(a1, sptr(&WS(buf, ob0 + 16 + aRow, ks * 16 + aCol)));
            #pragma unroll
            for (int pr = 0; pr < 4; pr++) {
                uint32 b[4];
                ldsm4(b, sptr(&XS(buf, coff + pr * 16 + bRow, ks * 16 + bCol)));
                mmah(acc[0][2 * pr],     a0, b[0], b[1]);
                mmah(acc[0][2 * pr + 1], a0, b[2], b[3]);
                mmah(acc[1][2 * pr],     a1, b[0], b[1]);
                mmah(acc[1][2 * pr + 1], a1, b[2], b[3]);
            }
        }
        __syncthreads();
    }

    // ---- epilogue ----
    if (mode == 0) {
        const int ha = o0 / 192;
        const int pa = (o0 - ha * 192) >> 6;
        if (pa < 2) {
            #pragma unroll
            for (int ms = 0; ms < 2; ms++) {
                const int c0 = ob0 + 16 * ms + r;
                const float ba = bias[o0 + c0], bb = bias[o0 + c0 + 8];
                #pragma unroll
                for (int nt = 0; nt < 8; nt++) {
                    const int tok = coff + nt * 8 + 2 * tg;
                    SM[tok * 72 + c0]           = __float2half(acc[ms][nt].x + ba);
                    SM[(tok + 1) * 72 + c0]     = __float2half(acc[ms][nt].y + ba);
                    SM[tok * 72 + c0 + 8]       = __float2half(acc[ms][nt].z + bb);
                    SM[(tok + 1) * 72 + c0 + 8] = __float2half(acc[ms][nt].w + bb);
                }
            }
            __syncthreads();
            const int base = ha * 128 + pa * 64;
            #pragma unroll
            for (int i = 0; i < 8; i++) {
                int j = tid + 128 * i;
                int tok = j >> 3, seg = j & 7;
                *(uint4*)(outqk + (size_t)(g0 + tok) * 384 + base + seg * 8) =
                    *(const uint4*)(SM + tok * 72 + seg * 8);
            }
        } else {
            #pragma unroll
            for (int ms = 0; ms < 2; ms++) {
                const int c0 = ob0 + 16 * ms + r;
                const float ba = bias[o0 + c0], bb = bias[o0 + c0 + 8];
                #pragma unroll
                for (int nt = 0; nt < 8; nt++) {
                    const int tok = coff + nt * 8 + 2 * tg;
                    *(__half2*)(SM + c0 * 136 + tok) =
                        __floats2half2_rn(acc[ms][nt].x + ba, acc[ms][nt].y + ba);
                    *(__half2*)(SM + (c0 + 8) * 136 + tok) =
                        __floats2half2_rn(acc[ms][nt].z + bb, acc[ms][nt].w + bb);
                }
            }
            __syncthreads();
            const int cvb = ha * 64;
            #pragma unroll
            for (int i = 0; i < 8; i++) {
                int j = tid + 128 * i;
                int ch = j >> 4, seg = j & 15;
                int gt = g0 + seg * 8;
                int img = gt >> ls, tok = gt & Lm1;
                *(uint4*)(outv + ((size_t)img * 192 + cvb + ch) * L + tok) =
                    *(const uint4*)(SM + ch * 136 + seg * 8);
            }
        }
    } else {
        #pragma unroll
        for (int ms = 0; ms < 2; ms++) {
            const int oa = o0 + ob0 + 16 * ms + r;
            const int obr = oa + 8;
            const float ba = bias[oa], bb = bias[obr];
            #pragma unroll
            for (int nt = 0; nt < 8; nt++) {
                int g = g0 + coff + nt * 8 + 2 * tg;
                float vax = acc[ms][nt].x + ba, vay = acc[ms][nt].y + ba;
                float vbx = acc[ms][nt].z + bb, vby = acc[ms][nt].w + bb;
                int n = g >> ls, l = g & Lm1;
                size_t pAa = ((size_t)n * Cout + oa) * L + l;
                size_t pBb = ((size_t)n * Cout + obr) * L + l;
                float2 va = make_float2(vax, vay);
                float2 vb = make_float2(vbx, vby);
                if (mode == 1) {
                    float2 qa = *(const float2*)(res + pAa);
                    float2 qb = *(const float2*)(res + pBb);
                    va.x += qa.x; va.y += qa.y; vb.x += qb.x; vb.y += qb.y;
                } else {
                    int b = n >> 4, t = n & 15;
                    size_t xa = (((size_t)(b * 192 + oa) * 16 + t) << 10) + l;
                    size_t xb = (((size_t)(b * 192 + obr) * 16 + t) << 10) + l;
                    float2 qa = *(const float2*)(res + xa);
                    float2 qb = *(const float2*)(res + xb);
                    va.x += qa.x; va.y += qa.y; vb.x += qb.x; vb.y += qb.y;
                }
                *(float2*)(outf + pAa) = va;
                *(float2*)(outf + pBb) = vb;
            }
        }
    }
}

// ---------------------------------------------------------------------------
// Attention pass 1: flash fp16 MMA + ldmatrix fragments.
// ---------------------------------------------------------------------------
#define HS 72

__global__ __launch_bounds__(128, 4) void k_attn1h(const __half* __restrict__ qk,
                                                   const __half* __restrict__ vT,
                                                   __half* __restrict__ outh) {
    __shared__ __align__(16) __half smh[4 * 64 * HS];
    __half* U  = smh;
    __half* K0 = smh + 64 * HS;
    __half* K1 = smh + 2 * 64 * HS;
    __half* Vt = smh + 3 * 64 * HS;

    const int tid = threadIdx.x, lane = tid & 31, w = tid >> 5;
    const int r = lane >> 2, tg = lane & 3;
    const int bh = blockIdx.y, n = bh / 3, h = bh % 3;
    const int q0 = blockIdx.x * 64;
    const __half* Qg = qk + ((size_t)(n * 1024) + q0) * 384 + h * 128;
    const __half* Kg = qk + (size_t)(n * 1024) * 384 + h * 128 + 64;
    const __half* Vg = vT + (size_t)(n * 192 + h * 64) * 1024;
    const int aRow = (lane & 7) + 8 * ((lane >> 3) & 1);
    const int aCol = 8 * (lane >> 4);
    const int bRow = (lane & 7) + 8 * (lane >> 4);
    const int bCol = 8 * ((lane >> 3) & 1);

    const int stok = tid >> 1, seg = (tid & 1) * 32;

    #pragma unroll
    for (int i = 0; i < 4; i++)
        cp16(sptr(&K0[stok * HS + seg + i * 8]), Kg + (size_t)stok * 384 + seg + i * 8);
    #pragma unroll
    for (int i = 0; i < 4; i++)
        cp16(sptr(&U[stok * HS + seg + i * 8]), Qg + (size_t)stok * 384 + seg + i * 8);
    cp_commit();
    cp_wait<0>();
    __syncthreads();

    uint32 qa[4][4];
    #pragma unroll
    for (int ks = 0; ks < 4; ks++)
        ldsm4(qa[ks], sptr(&U[(16 * w + aRow) * HS + ks * 16 + aCol]));

    float4 o[8];
    #pragma unroll
    for (int nt = 0; nt < 8; nt++) o[nt] = make_float4(0.f, 0.f, 0.f, 0.f);
    float m0 = -1e30f, m1 = -1e30f, s0 = 0.f, s1 = 0.f;
    __half* pr0h = U + (16 * w + r) * HS;
    __half* pr1h = U + (16 * w + r + 8) * HS;
    const float SC = 0.125f;

    for (int kt = 0; kt < 16; kt++) {
        const int buf = kt & 1;
        {
            const int sb = kt * 64;
            #pragma unroll
            for (int i = 0; i < 4; i++)
                cp16(sptr(&Vt[stok * HS + seg + i * 8]),
                     Vg + (size_t)stok * 1024 + sb + seg + i * 8);
            cp_commit();
        }
        if (kt < 15) {
            const int sb = (kt + 1) * 64;
            __half* Kn = buf ? K0 : K1;
            #pragma unroll
            for (int i = 0; i < 4; i++)
                cp16(sptr(&Kn[stok * HS + seg + i * 8]),
                     Kg + (size_t)(sb + stok) * 384 + seg + i * 8);
        }
        cp_commit();
        cp_wait<2>();
        __syncthreads();
        const __half* Ks = buf ? K1 : K0;

        float4 sc[8];
        #pragma unroll
        for (int nt = 0; nt < 8; nt++) sc[nt] = make_float4(0.f, 0.f, 0.f, 0.f);
        #pragma unroll
        for (int ks = 0; ks < 4; ks++) {
            #pragma unroll
            for (int pr = 0; pr < 4; pr++) {
                uint32 b[4];
                ldsm4(b, sptr(&Ks[(pr * 16 + bRow) * HS + ks * 16 + bCol]));
                mmah(sc[2 * pr],     qa[ks], b[0], b[1]);
                mmah(sc[2 * pr + 1], qa[ks], b[2], b[3]);
            }
        }

        float tm0 = -1e30f, tm1 = -1e30f;
        #pragma unroll
        for (int nt = 0; nt < 8; nt++) {
            tm0 = fmaxf(tm0, fmaxf(sc[nt].x, sc[nt].y));
            tm1 = fmaxf(tm1, fmaxf(sc[nt].z, sc[nt].w));
        }
        tm0 = fmaxf(tm0, __shfl_xor_sync(0xffffffffu, tm0, 1));
        tm0 = fmaxf(tm0, __shfl_xor_sync(0xffffffffu, tm0, 2));
        tm1 = fmaxf(tm1, __shfl_xor_sync(0xffffffffu, tm1, 1));
        tm1 = fmaxf(tm1, __shfl_xor_sync(0xffffffffu, tm1, 2));
        tm0 *= SC; tm1 *= SC;
        float nm0 = fmaxf(m0, tm0), nm1 = fmaxf(m1, tm1);
        float a0 = __expf(m0 - nm0), a1 = __expf(m1 - nm1);
        float t0 = 0.f, t1 = 0.f;
        #pragma unroll
        for (int nt = 0; nt < 8; nt++) {
            float px = __expf(fmaf(sc[nt].x, SC, -nm0));
            float py = __expf(fmaf(sc[nt].y, SC, -nm0));
            float pz = __expf(fmaf(sc[nt].z, SC, -nm1));
            float pw = __expf(fmaf(sc[nt].w, SC, -nm1));
            t0 += px + py; t1 += pz + pw;
            const int col = nt * 8 + 2 * tg;
            *(__half2*)(pr0h + col) = __floats2half2_rn(px, py);
            *(__half2*)(pr1h + col) = __floats2half2_rn(pz, pw);
            o[nt].x *= a0; o[nt].y *= a0;
            o[nt].z *= a1; o[nt].w *= a1;
        }
        t0 += __shfl_xor_sync(0xffffffffu, t0, 1);
        t0 += __shfl_xor_sync(0xffffffffu, t0, 2);
        t1 += __shfl_xor_sync(0xffffffffu, t1, 1);
        t1 += __shfl_xor_sync(0xffffffffu, t1, 2);
        s0 = s0 * a0 + t0;
        s1 = s1 * a1 + t1;
        m0 = nm0; m1 = nm1;
        __syncwarp();

        cp_wait<1>();
        __syncthreads();

        #pragma unroll
        for (int ks = 0; ks < 4; ks++) {
            uint32 a[4];
            ldsm4(a, sptr(&U[(16 * w + aRow) * HS + ks * 16 + aCol]));
            #pragma unroll
            for (int pr = 0; pr < 4; pr++) {
                uint32 b[4];
                ldsm4(b, sptr(&Vt[(pr * 16 + bRow) * HS + ks * 16 + bCol]));
                mmah(o[2 * pr],     a, b[0], b[1]);
                mmah(o[2 * pr + 1], a, b[2], b[3]);
            }
        }
        __syncthreads();
    }

    float i0 = 1.f / s0, i1 = 1.f / s1;
    __half* Os = K0;
    #pragma unroll
    for (int nt = 0; nt < 8; nt++) {
        const int col = nt * 8 + 2 * tg;
        *(__half2*)(Os + (16 * w + r) * HS + col)     = __floats2half2_rn(o[nt].x * i0, o[nt].y * i0);
        *(__half2*)(Os + (16 * w + r + 8) * HS + col) = __floats2half2_rn(o[nt].z * i1, o[nt].w * i1);
    }
    __syncthreads();
    __half* dst = outh + ((size_t)(n * 1024) + q0 + stok) * 192 + h * 64 + seg;
    #pragma unroll
    for (int i = 0; i < 4; i++)
        *(uint4*)(dst + i * 8) = *(const uint4*)(Os + stok * HS + seg + i * 8);
}

// ---------------------------------------------------------------------------
// Attention pass 2: L=16, scalar fp32 from half inputs
// ---------------------------------------------------------------------------
__global__ void k_attn2h(const __half* __restrict__ qkh, const __half* __restrict__ vTh,
                         __half* __restrict__ outh) {
    __shared__ float qs[16][68], ks[16][68], vs[1024], S[16 * 17];
    int bh = blockIdx.x, n = bh / 3, h = bh % 3;
    int tid = threadIdx.x;
    const __half* Qb = qkh + (size_t)(n * 16) * 384 + h * 128;
    const __half* Vb = vTh + (size_t)(n * 192 + h * 64) * 16;
    for (int i = tid; i < 1024; i += 256) {
        int q = i >> 6, c = i & 63;
        qs[q][c] = __half2float(Qb[(size_t)q * 384 + c]) * 0.125f;
        ks[q][c] = __half2float(Qb[(size_t)q * 384 + 64 + c]);
        vs[i] = __half2float(Vb[i]);
    }
    __syncthreads();
    {
        int q = tid >> 4, s = tid & 15;
        float a = 0.f;
        #pragma unroll
        for (int c = 0; c < 64; c++) a += qs[q][c] * ks[s][c];
        S[q * 17 + s] = a;
    }
    __syncthreads();
    if (tid < 16) {
        float* row = S + tid * 17;
        float m = -1e30f;
        #pragma unroll
        for (int s = 0; s < 16; s++) m = fmaxf(m, row[s]);
        float sum = 0.f;
        #pragma unroll
        for (int s = 0; s < 16; s++) { float e = __expf(row[s] - m); row[s] = e; sum += e; }
        float inv = 1.f / sum;
        #pragma unroll
        for (int s = 0; s < 16; s++) row[s] *= inv;
    }
    __syncthreads();
    {
        int q = tid & 15;
        int cb = (tid >> 4) << 2;
        float a0 = 0.f, a1 = 0.f, a2 = 0.f, a3 = 0.f;
        #pragma unroll
        for (int s = 0; s < 16; s++) {
            float sv = S[q * 17 + s];
            a0 += vs[(cb + 0) * 16 + s] * sv;
            a1 += vs[(cb + 1) * 16 + s] * sv;
            a2 += vs[(cb + 2) * 16 + s] * sv;
            a3 += vs[(cb + 3) * 16 + s] * sv;
        }
        __half* ob = outh + ((size_t)(n * 16) + q) * 192 + h * 64 + cb;
        ob[0] = __float2half(a0);
        ob[1] = __float2half(a1);
        ob[2] = __float2half(a2);
        ob[3] = __float2half(a3);
    }
}

// ---------------------------------------------------------------------------
extern "C" void kernel_launch(void* const* d_in, const int* in_sizes, int n_in,
                              void* d_out, int out_size) {
    const float* x       = (const float*)d_in[0];
    const float* norm_g  = (const float*)d_in[1];
    const float* norm_b  = (const float*)d_in[2];
    const float* qkv_w   = (const float*)d_in[3];
    const float* qkv_b   = (const float*)d_in[4];
    const float* proj_w  = (const float*)d_in[5];
    const float* proj_b  = (const float*)d_in[6];
    const float* normt_g = (const float*)d_in[7];
    const float* normt_b = (const float*)d_in[8];
    const float* qkvt_w  = (const float*)d_in[9];
    const float* qkvt_b  = (const float*)d_in[10];
    const float* projt_w = (const float*)d_in[11];
    const float* projt_b = (const float*)d_in[12];
    float* out = (float*)d_out;

    float *xs, *y, *yt;
    __half *nrm16, *qk16, *v16T, *att16, *w16;
    cudaGetSymbolAddress((void**)&xs,    g_xs);
    cudaGetSymbolAddress((void**)&y,     g_y);
    cudaGetSymbolAddress((void**)&yt,    g_yt);
    cudaGetSymbolAddress((void**)&nrm16, g_nrm16);
    cudaGetSymbolAddress((void**)&qk16,  g_qk16);
    cudaGetSymbolAddress((void**)&v16T,  g_v16T);
    cudaGetSymbolAddress((void**)&att16, g_att16);
    cudaGetSymbolAddress((void**)&w16,   g_w16);

    const __half* w_qkv  = w16;
    const __half* w_proj = w16 + 110592;
    const __half* w_qkvt = w16 + 147456;
    const __half* w_projt= w16 + 258048;

    k_wprep<<<288, 1024>>>(qkv_w, proj_w, qkvt_w, projt_w);

    // ---- pass 1 (spatial, L=1024) ----
    k_gn1s<<<NBT * 32, 256>>>(x);
    k_gn1at<<<dim3(16, 32), 256>>>(x, norm_g, norm_b);
    k_convh<<<dim3(256, 9), 128>>>(nrm16, w_qkv, qkv_b, nullptr,
                                   nullptr, qk16, v16T, 576, 10, 0);
    k_attn1h<<<dim3(16, 96), 128>>>(qk16, v16T, att16);
    k_convh<<<dim3(256, 3), 128>>>(att16, w_proj, proj_b, x,
                                   y, nullptr, nullptr, 192, 10, 2);

    // ---- pass 2 (temporal, L=16) ----
    k_transpose2c<<<dim3(16, 48, 2), 256>>>();
    k_gn2h<<<2048, 128>>>(yt, normt_g, normt_b, nrm16);
    k_convh<<<dim3(256, 9), 128>>>(nrm16, w_qkvt, qkvt_b, nullptr,
                                   nullptr, qk16, v16T, 576, 4, 0);
    k_attn2h<<<6144, 256>>>(qk16, v16T, att16);
    k_convh<<<dim3(256, 3), 128>>>(att16, w_projt, projt_b, yt,
                                   xs, nullptr, nullptr, 192, 4, 1);
    k_transpose3c<<<dim3(16, 48, 2), 256>>>(out);
}

// round 14
// speedup vs baseline: 10.6974x; 1.0354x over previous
#include <cuda_runtime.h>
#include <cuda_fp16.h>
#include <math.h>

#define NBT 32
#define CCH 192
#define TOT (NBT*CCH*1024)
typedef unsigned int uint32;

// fp32 scratch
__device__ float g_xs [TOT];          // z (bhw,c,t) in pass2
__device__ float g_y  [TOT];
__device__ float g_yt [TOT];
__device__ float g_stat[NBT*32*2];
// fp16 scratch
__device__ __half g_nrm16[32768*192];
__device__ __half g_qk16 [32768*384];
__device__ __half g_v16T [32768*192];
__device__ __half g_att16[32768*192];
__device__ __half g_w16  [294912];

// ---- helpers ----------------------------------------------------------------
__device__ __forceinline__ void mmah(float4 &c, const uint32* a, uint32 b0, uint32 b1) {
    asm("mma.sync.aligned.m16n8k16.row.col.f32.f16.f16.f32 "
        "{%0,%1,%2,%3},{%4,%5,%6,%7},{%8,%9},{%0,%1,%2,%3};"
        : "+f"(c.x), "+f"(c.y), "+f"(c.z), "+f"(c.w)
        : "r"(a[0]), "r"(a[1]), "r"(a[2]), "r"(a[3]), "r"(b0), "r"(b1));
}
__device__ __forceinline__ uint32 sptr(const void* p) {
    return (uint32)__cvta_generic_to_shared(p);
}
__device__ __forceinline__ void ldsm4(uint32* r, uint32 addr) {
    asm volatile("ldmatrix.sync.aligned.m8n8.x4.shared.b16 {%0,%1,%2,%3}, [%4];"
        : "=r"(r[0]), "=r"(r[1]), "=r"(r[2]), "=r"(r[3]) : "r"(addr));
}
__device__ __forceinline__ void cp16(uint32 s, const void* g) {
    asm volatile("cp.async.ca.shared.global [%0], [%1], 16;" :: "r"(s), "l"(g));
}
__device__ __forceinline__ void cp_commit() { asm volatile("cp.async.commit_group;"); }
template<int N> __device__ __forceinline__ void cp_wait() {
    asm volatile("cp.async.wait_group %0;" :: "n"(N));
}

// ---------------------------------------------------------------------------
// Weight fp16 prep
// ---------------------------------------------------------------------------
__global__ void k_wprep(const float* __restrict__ qw, const float* __restrict__ pw,
                        const float* __restrict__ qtw, const float* __restrict__ ptw) {
    int i = blockIdx.x * 1024 + threadIdx.x;
    float v;
    if      (i < 110592) v = qw[i];
    else if (i < 147456) v = pw[i - 110592];
    else if (i < 258048) v = qtw[i - 147456];
    else                 v = ptw[i - 258048];
    g_w16[i] = __float2half(v);
}

// ---------------------------------------------------------------------------
// GroupNorm pass 1 stats
// ---------------------------------------------------------------------------
__global__ void k_gn1s(const float* __restrict__ x) {
    int n = blockIdx.x >> 5, g = blockIdx.x & 31;
    int b = n >> 4, t = n & 15;
    const float* xb = x + (((size_t)(b * CCH + g * 6) * 16 + t) << 10);
    int tid = threadIdx.x;
    float s = 0.f, q = 0.f;
    for (int i = tid; i < 6144; i += 256) {
        float v = xb[((size_t)(i >> 10) << 14) + (i & 1023)];
        s += v; q += v * v;
    }
    __shared__ float rs[256], rq[256];
    rs[tid] = s; rq[tid] = q;
    __syncthreads();
    for (int st = 128; st > 0; st >>= 1) {
        if (tid < st) { rs[tid] += rs[tid + st]; rq[tid] += rq[tid + st]; }
        __syncthreads();
    }
    if (tid == 0) {
        float mean = rs[0] / 6144.f;
        float var  = rq[0] / 6144.f - mean * mean;
        g_stat[blockIdx.x * 2]     = mean;
        g_stat[blockIdx.x * 2 + 1] = rsqrtf(var + 1e-5f);
    }
}

// ---------------------------------------------------------------------------
// GroupNorm pass 1 apply, tiled coalesced
// ---------------------------------------------------------------------------
__global__ __launch_bounds__(256) void k_gn1at(const float* __restrict__ x,
                                               const float* __restrict__ gam,
                                               const float* __restrict__ bet) {
    __shared__ __half sbuf[64 * 200];
    const int hw0 = blockIdx.x * 64, bt = blockIdx.y;
    const int b = bt >> 4, t = bt & 15;
    const int tid = threadIdx.x;
    #pragma unroll
    for (int rep = 0; rep < 3; rep++) {
        const int c = rep * 64 + (tid >> 2);
        const int hwq = (tid & 3) * 16;
        const int g = c / 6;
        const float mu = g_stat[(bt * 32 + g) * 2];
        const float iv = g_stat[(bt * 32 + g) * 2 + 1];
        const float ga = gam[c] * iv;
        const float be = bet[c] - mu * ga;
        const float* src = x + (((size_t)(b * CCH + c) * 16 + t) << 10) + hw0 + hwq;
        #pragma unroll
        for (int j = 0; j < 16; j += 4) {
            float4 v = *(const float4*)(src + j);
            sbuf[(hwq + j + 0) * 200 + c] = __float2half(v.x * ga + be);
            sbuf[(hwq + j + 1) * 200 + c] = __float2half(v.y * ga + be);
            sbuf[(hwq + j + 2) * 200 + c] = __float2half(v.z * ga + be);
            sbuf[(hwq + j + 3) * 200 + c] = __float2half(v.w * ga + be);
        }
    }
    __syncthreads();
    #pragma unroll
    for (int i = tid; i < 1536; i += 256) {
        int tok = i / 24, seg = i - tok * 24;
        *(uint4*)(g_nrm16 + ((size_t)(bt * 1024 + hw0 + tok)) * 192 + seg * 8) =
            *(const uint4*)(sbuf + tok * 200 + seg * 8);
    }
}

// ---------------------------------------------------------------------------
// GroupNorm pass 2
// ---------------------------------------------------------------------------
__global__ void k_gn2h(const float* __restrict__ X, const float* __restrict__ gam,
                       const float* __restrict__ bet, __half* __restrict__ out16) {
    int n = blockIdx.x;
    __shared__ float buf[3072];
    __shared__ float mu[32], iv[32];
    int tid = threadIdx.x;
    const float4* xb = (const float4*)(X + (size_t)n * 3072);
    for (int i = tid; i < 768; i += 128) ((float4*)buf)[i] = xb[i];
    __syncthreads();
    int w = tid >> 5, lane = tid & 31;
    for (int g = w; g < 32; g += 4) {
        float v0 = buf[g * 96 + lane], v1 = buf[g * 96 + 32 + lane], v2 = buf[g * 96 + 64 + lane];
        float s = v0 + v1 + v2, q = v0 * v0 + v1 * v1 + v2 * v2;
        #pragma unroll
        for (int off = 16; off; off >>= 1) {
            s += __shfl_xor_sync(0xffffffffu, s, off);
            q += __shfl_xor_sync(0xffffffffu, q, off);
        }
        if (lane == 0) {
            float m = s / 96.f, va = q / 96.f - m * m;
            mu[g] = m; iv[g] = rsqrtf(va + 1e-5f);
        }
    }
    __syncthreads();
    __half* ob = out16 + (size_t)n * 3072;
    for (int j = tid; j < 3072; j += 128) {
        int t = j / 192, c = j - t * 192;
        int g = c / 6;
        ob[j] = __float2half((buf[c * 16 + t] - mu[g]) * iv[g] * gam[c] + bet[c]);
    }
}

// ---------------------------------------------------------------------------
// c-blocked transposes
// ---------------------------------------------------------------------------
__global__ __launch_bounds__(256) void k_transpose2c() {  // y (bt,c,hw) -> yt (bhw,c,t)
    __shared__ float sb[5168];
    const int hw0 = blockIdx.x * 64, c0 = blockIdx.y * 4, b = blockIdx.z;
    const int tid = threadIdx.x, w = tid >> 5, lane = tid & 31;
    #pragma unroll
    for (int it = 0; it < 8; it++) {
        int p = it * 8 + w;
        int c = p >> 4, t = p & 15;
        float2 v = *(const float2*)&g_y[(((size_t)(b * 16 + t) * CCH + c0 + c) << 10)
                                        + hw0 + lane * 2];
        sb[c * 1296 + (lane * 2) * 20 + t]     = v.x;
        sb[c * 1296 + (lane * 2 + 1) * 20 + t] = v.y;
    }
    __syncthreads();
    #pragma unroll
    for (int i2 = 0; i2 < 4; i2++) {
        int u = tid + 256 * i2;
        int hw = u >> 4, q = u & 15;
        int c = q >> 2, t4 = (q & 3) * 4;
        *(float4*)&g_yt[((size_t)(b * 1024 + hw0 + hw) * CCH + c0 + c) * 16 + t4] =
            *(const float4*)&sb[c * 1296 + hw * 20 + t4];
    }
}

__global__ __launch_bounds__(256) void k_transpose3c(float* __restrict__ out) {
    __shared__ float sb[5168];
    const int hw0 = blockIdx.x * 64, c0 = blockIdx.y * 4, b = blockIdx.z;
    const int tid = threadIdx.x, w = tid >> 5, lane = tid & 31;
    #pragma unroll
    for (int i2 = 0; i2 < 4; i2++) {
        int u = tid + 256 * i2;
        int hw = u >> 4, q = u & 15;
        int c = q >> 2, t4 = (q & 3) * 4;
        *(float4*)&sb[c * 1296 + hw * 20 + t4] =
            *(const float4*)&g_xs[((size_t)(b * 1024 + hw0 + hw) * CCH + c0 + c) * 16 + t4];
    }
    __syncthreads();
    #pragma unroll
    for (int it = 0; it < 8; it++) {
        int p = it * 8 + w;
        int c = p >> 4, t = p & 15;
        float2 v = make_float2(sb[c * 1296 + (lane * 2) * 20 + t],
                               sb[c * 1296 + (lane * 2 + 1) * 20 + t]);
        *(float2*)&out[(((size_t)(b * CCH + c0 + c) * 16 + t) << 10) + hw0 + lane * 2] = v;
    }
}

// ---------------------------------------------------------------------------
// QKV conv: X-persistent. Grid (tokenTiles, 3 heads). CTA stages X[128][192]
// ONCE (stride 200 -> ldmatrix conflict-free), loops head's 3 parts (q,k,v),
// streaming 4KB W chunks double-buffered. Dynamic smem 79,872 B.
// Layout (halves): XS [0,25600) t*200+k; WS [25600,30720) buf*2560+o*40+k;
//                  E  [30720,39936)
// ---------------------------------------------------------------------------
#define CONVQ_SMEM 79872

__global__ __launch_bounds__(128, 2) void k_convq(
    const __half* __restrict__ X, const __half* __restrict__ W,
    const float* __restrict__ bias,
    __half* __restrict__ outqk, __half* __restrict__ outv, int ls) {
    extern __shared__ __half SM[];
    const int tid = threadIdx.x, lane = tid & 31, w = tid >> 5;
    const int r = lane >> 2, tg = lane & 3;
    const int g0 = blockIdx.x * 128, ha = blockIdx.y;
    const int L = 1 << ls, Lm1 = L - 1;
    const int aRow = (lane & 7) + 8 * ((lane >> 3) & 1);
    const int aCol = 8 * (lane >> 4);
    const int bRow = (lane & 7) + 8 * (lane >> 4);
    const int bCol = 8 * ((lane >> 3) & 1);
    const int ob0 = 32 * (w >> 1), coff = (w & 1) * 64;
    const int wo = tid & 63, wp = (tid >> 6) * 16;
    const __half* wbase = W + (size_t)(ha * 192) * 192;
    __half* E = SM + 30720;

    // stage entire X tile (one commit group)
    const __half* xsrc = X + (size_t)(g0 + tid) * 192;
    #pragma unroll
    for (int s = 0; s < 24; s++)
        cp16(sptr(&SM[tid * 200 + s * 8]), xsrc + s * 8);
    cp_commit();
    // W chunk 0 (o-part 0, k-chunk 0)
    {
        const __half* ws = wbase + (size_t)wo * 192 + wp;
        uint32 d = sptr(&SM[25600 + wo * 40 + wp]);
        cp16(d, ws);
        cp16(d + 16, ws + 8);
        cp_commit();
    }

    for (int i = 0; i < 3; i++) {
        float4 acc[2][8];
        #pragma unroll
        for (int ms = 0; ms < 2; ms++)
            #pragma unroll
            for (int nt = 0; nt < 8; nt++) acc[ms][nt] = make_float4(0.f, 0.f, 0.f, 0.f);

        for (int c = 0; c < 6; c++) {
            const int m = i * 6 + c;
            const int buf = m & 1;
            if (m < 17) {
                const int mn = m + 1;
                const int mi = mn / 6, mc = mn - mi * 6;
                const __half* ws = wbase + (size_t)(mi * 64 + wo) * 192 + mc * 32 + wp;
                uint32 d = sptr(&SM[25600 + (buf ^ 1) * 2560 + wo * 40 + wp]);
                cp16(d, ws);
                cp16(d + 16, ws + 8);
                cp_commit();
                cp_wait<1>();
            } else {
                cp_wait<0>();
            }
            __syncthreads();
            const int wsb = 25600 + buf * 2560;
            #pragma unroll
            for (int ks = 0; ks < 2; ks++) {
                uint32 a0[4], a1[4];
                ldsm4(a0, sptr(&SM[wsb + (ob0 + aRow) * 40 + ks * 16 + aCol]));
                ldsm4(a1, sptr(&SM[wsb + (ob0 + 16 + aRow) * 40 + ks * 16 + aCol]));
                #pragma unroll
                for (int pr = 0; pr < 4; pr++) {
                    uint32 b[4];
                    ldsm4(b, sptr(&SM[(coff + pr * 16 + bRow) * 200 + c * 32 + ks * 16 + bCol]));
                    mmah(acc[0][2 * pr],     a0, b[0], b[1]);
                    mmah(acc[0][2 * pr + 1], a0, b[2], b[3]);
                    mmah(acc[1][2 * pr],     a1, b[0], b[1]);
                    mmah(acc[1][2 * pr + 1], a1, b[2], b[3]);
                }
            }
            __syncthreads();
        }

        // ---- epilogue for part i (pa = i) ----
        const int o0 = ha * 192 + i * 64;
        if (i < 2) {  // Q or K -> qk16 channel-last
            #pragma unroll
            for (int ms = 0; ms < 2; ms++) {
                const int c0 = ob0 + 16 * ms + r;
                const float ba = bias[o0 + c0], bb = bias[o0 + c0 + 8];
                #pragma unroll
                for (int nt = 0; nt < 8; nt++) {
                    const int tok = coff + nt * 8 + 2 * tg;
                    E[tok * 72 + c0]           = __float2half(acc[ms][nt].x + ba);
                    E[(tok + 1) * 72 + c0]     = __float2half(acc[ms][nt].y + ba);
                    E[tok * 72 + c0 + 8]       = __float2half(acc[ms][nt].z + bb);
                    E[(tok + 1) * 72 + c0 + 8] = __float2half(acc[ms][nt].w + bb);
                }
            }
            __syncthreads();
            const int base = ha * 128 + i * 64;
            #pragma unroll
            for (int ii = 0; ii < 8; ii++) {
                int j = tid + 128 * ii;
                int tok = j >> 3, seg = j & 7;
                *(uint4*)(outqk + (size_t)(g0 + tok) * 384 + base + seg * 8) =
                    *(const uint4*)(E + tok * 72 + seg * 8);
            }
        } else {      // V -> d-major
            #pragma unroll
            for (int ms = 0; ms < 2; ms++) {
                const int c0 = ob0 + 16 * ms + r;
                const float ba = bias[o0 + c0], bb = bias[o0 + c0 + 8];
                #pragma unroll
                for (int nt = 0; nt < 8; nt++) {
                    const int tok = coff + nt * 8 + 2 * tg;
                    *(__half2*)(E + c0 * 136 + tok) =
                        __floats2half2_rn(acc[ms][nt].x + ba, acc[ms][nt].y + ba);
                    *(__half2*)(E + (c0 + 8) * 136 + tok) =
                        __floats2half2_rn(acc[ms][nt].z + bb, acc[ms][nt].w + bb);
                }
            }
            __syncthreads();
            const int cvb = ha * 64;
            #pragma unroll
            for (int ii = 0; ii < 8; ii++) {
                int j = tid + 128 * ii;
                int ch = j >> 4, seg = j & 15;
                int gt = g0 + seg * 8;
                int img = gt >> ls, tok = gt & Lm1;
                *(uint4*)(outv + ((size_t)img * 192 + cvb + ch) * L + tok) =
                    *(const uint4*)(E + ch * 136 + seg * 8);
            }
        }
        __syncthreads();
    }
}

// ---------------------------------------------------------------------------
// proj conv (modes 1/2): unchanged k_convh
// ---------------------------------------------------------------------------
#define XS(b,t,k) SM[(b)*5120 + (t)*40 + (k)]
#define WS(b,o,k) SM[10240 + (b)*2560 + (o)*40 + (k)]

__global__ __launch_bounds__(128, 4) void k_convh(
    const __half* __restrict__ X, const __half* __restrict__ W,
    const float* __restrict__ bias, const float* __restrict__ res,
    float* __restrict__ outf, int Cout, int ls, int mode) {
    __shared__ __align__(16) __half SM[15360];
    const int tid = threadIdx.x, lane = tid & 31, w = tid >> 5;
    const int r = lane >> 2, tg = lane & 3;
    const int g0 = blockIdx.x * 128, o0 = blockIdx.y * 64;
    const int ob0 = 32 * (w >> 1), coff = (w & 1) * 64;
    const int L = 1 << ls, Lm1 = L - 1;
    const int aRow = (lane & 7) + 8 * ((lane >> 3) & 1);
    const int aCol = 8 * (lane >> 4);
    const int bRow = (lane & 7) + 8 * (lane >> 4);
    const int bCol = 8 * ((lane >> 3) & 1);

    float4 acc[2][8];
    #pragma unroll
    for (int ms = 0; ms < 2; ms++)
        #pragma unroll
        for (int nt = 0; nt < 8; nt++) acc[ms][nt] = make_float4(0.f, 0.f, 0.f, 0.f);

    const __half* xsrc = X + (size_t)(g0 + tid) * 192;
    const int wo = tid & 63, wp = (tid >> 6) * 16;
    const __half* wsrc = W + (size_t)(o0 + wo) * 192 + wp;

    #pragma unroll
    for (int j = 0; j < 4; j++) cp16(sptr(&XS(0, tid, j * 8)), xsrc + j * 8);
    #pragma unroll
    for (int j = 0; j < 2; j++) cp16(sptr(&WS(0, wo, wp + j * 8)), wsrc + j * 8);
    cp_commit();

    for (int c = 0; c < 6; c++) {
        const int buf = c & 1;
        if (c < 5) {
            const int cc = (c + 1) * 32;
            #pragma unroll
            for (int j = 0; j < 4; j++)
                cp16(sptr(&XS(buf ^ 1, tid, j * 8)), xsrc + cc + j * 8);
            #pragma unroll
            for (int j = 0; j < 2; j++)
                cp16(sptr(&WS(buf ^ 1, wo, wp + j * 8)), wsrc + cc + j * 8);
            cp_commit();
            cp_wait<1>();
        } else {
            cp_wait<0>();
        }
        __syncthreads();
        #pragma unroll
        for (int ks = 0; ks < 2; ks++) {
            uint32 a0[4], a1[4];
            ldsm4(a0, sptr(&WS(buf, ob0 + aRow,      ks * 16 + aCol)));
            ldsm4(a1, sptr(&WS(buf, ob0 + 16 + aRow, ks * 16 + aCol)));
            #pragma unroll
            for (int pr = 0; pr < 4; pr++) {
                uint32 b[4];
                ldsm4(b, sptr(&XS(buf, coff + pr * 16 + bRow, ks * 16 + bCol)));
                mmah(acc[0][2 * pr],     a0, b[0], b[1]);
                mmah(acc[0][2 * pr + 1], a0, b[2], b[3]);
                mmah(acc[1][2 * pr],     a1, b[0], b[1]);
                mmah(acc[1][2 * pr + 1], a1, b[2], b[3]);
            }
        }
        __syncthreads();
    }

    #pragma unroll
    for (int ms = 0; ms < 2; ms++) {
        const int oa = o0 + ob0 + 16 * ms + r;
        const int obr = oa + 8;
        const float ba = bias[oa], bb = bias[obr];
        #pragma unroll
        for (int nt = 0; nt < 8; nt++) {
            int g = g0 + coff + nt * 8 + 2 * tg;
            float vax = acc[ms][nt].x + ba, vay = acc[ms][nt].y + ba;
            float vbx = acc[ms][nt].z + bb, vby = acc[ms][nt].w + bb;
            int n = g >> ls, l = g & Lm1;
            size_t pAa = ((size_t)n * Cout + oa) * L + l;
            size_t pBb = ((size_t)n * Cout + obr) * L + l;
            float2 va = make_float2(vax, vay);
            float2 vb = make_float2(vbx, vby);
            if (mode == 1) {
                float2 qa = *(const float2*)(res + pAa);
                float2 qb = *(const float2*)(res + pBb);
                va.x += qa.x; va.y += qa.y; vb.x += qb.x; vb.y += qb.y;
            } else {
                int b = n >> 4, t = n & 15;
                size_t xa = (((size_t)(b * 192 + oa) * 16 + t) << 10) + l;
                size_t xb = (((size_t)(b * 192 + obr) * 16 + t) << 10) + l;
                float2 qa = *(const float2*)(res + xa);
                float2 qb = *(const float2*)(res + xb);
                va.x += qa.x; va.y += qa.y; vb.x += qb.x; vb.y += qb.y;
            }
            *(float2*)(outf + pAa) = va;
            *(float2*)(outf + pBb) = vb;
        }
    }
}

// ---------------------------------------------------------------------------
// Attention pass 1: flash fp16 MMA + ldmatrix fragments.
// ---------------------------------------------------------------------------
#define HS 72

__global__ __launch_bounds__(128, 4) void k_attn1h(const __half* __restrict__ qk,
                                                   const __half* __restrict__ vT,
                                                   __half* __restrict__ outh) {
    __shared__ __align__(16) __half smh[4 * 64 * HS];
    __half* U  = smh;
    __half* K0 = smh + 64 * HS;
    __half* K1 = smh + 2 * 64 * HS;
    __half* Vt = smh + 3 * 64 * HS;

    const int tid = threadIdx.x, lane = tid & 31, w = tid >> 5;
    const int r = lane >> 2, tg = lane & 3;
    const int bh = blockIdx.y, n = bh / 3, h = bh % 3;
    const int q0 = blockIdx.x * 64;
    const __half* Qg = qk + ((size_t)(n * 1024) + q0) * 384 + h * 128;
    const __half* Kg = qk + (size_t)(n * 1024) * 384 + h * 128 + 64;
    const __half* Vg = vT + (size_t)(n * 192 + h * 64) * 1024;
    const int aRow = (lane & 7) + 8 * ((lane >> 3) & 1);
    const int aCol = 8 * (lane >> 4);
    const int bRow = (lane & 7) + 8 * (lane >> 4);
    const int bCol = 8 * ((lane >> 3) & 1);

    const int stok = tid >> 1, seg = (tid & 1) * 32;

    #pragma unroll
    for (int i = 0; i < 4; i++)
        cp16(sptr(&K0[stok * HS + seg + i * 8]), Kg + (size_t)stok * 384 + seg + i * 8);
    #pragma unroll
    for (int i = 0; i < 4; i++)
        cp16(sptr(&U[stok * HS + seg + i * 8]), Qg + (size_t)stok * 384 + seg + i * 8);
    cp_commit();
    cp_wait<0>();
    __syncthreads();

    uint32 qa[4][4];
    #pragma unroll
    for (int ks = 0; ks < 4; ks++)
        ldsm4(qa[ks], sptr(&U[(16 * w + aRow) * HS + ks * 16 + aCol]));

    float4 o[8];
    #pragma unroll
    for (int nt = 0; nt < 8; nt++) o[nt] = make_float4(0.f, 0.f, 0.f, 0.f);
    float m0 = -1e30f, m1 = -1e30f, s0 = 0.f, s1 = 0.f;
    __half* pr0h = U + (16 * w + r) * HS;
    __half* pr1h = U + (16 * w + r + 8) * HS;
    const float SC = 0.125f;

    for (int kt = 0; kt < 16; kt++) {
        const int buf = kt & 1;
        {
            const int sb = kt * 64;
            #pragma unroll
            for (int i = 0; i < 4; i++)
                cp16(sptr(&Vt[stok * HS + seg + i * 8]),
                     Vg + (size_t)stok * 1024 + sb + seg + i * 8);
            cp_commit();
        }
        if (kt < 15) {
            const int sb = (kt + 1) * 64;
            __half* Kn = buf ? K0 : K1;
            #pragma unroll
            for (int i = 0; i < 4; i++)
                cp16(sptr(&Kn[stok * HS + seg + i * 8]),
                     Kg + (size_t)(sb + stok) * 384 + seg + i * 8);
        }
        cp_commit();
        cp_wait<2>();
        __syncthreads();
        const __half* Ks = buf ? K1 : K0;

        float4 sc[8];
        #pragma unroll
        for (int nt = 0; nt < 8; nt++) sc[nt] = make_float4(0.f, 0.f, 0.f, 0.f);
        #pragma unroll
        for (int ks = 0; ks < 4; ks++) {
            #pragma unroll
            for (int pr = 0; pr < 4; pr++) {
                uint32 b[4];
                ldsm4(b, sptr(&Ks[(pr * 16 + bRow) * HS + ks * 16 + bCol]));
                mmah(sc[2 * pr],     qa[ks], b[0], b[1]);
                mmah(sc[2 * pr + 1], qa[ks], b[2], b[3]);
            }
        }

        float tm0 = -1e30f, tm1 = -1e30f;
        #pragma unroll
        for (int nt = 0; nt < 8; nt++) {
            tm0 = fmaxf(tm0, fmaxf(sc[nt].x, sc[nt].y));
            tm1 = fmaxf(tm1, fmaxf(sc[nt].z, sc[nt].w));
        }
        tm0 = fmaxf(tm0, __shfl_xor_sync(0xffffffffu, tm0, 1));
        tm0 = fmaxf(tm0, __shfl_xor_sync(0xffffffffu, tm0, 2));
        tm1 = fmaxf(tm1, __shfl_xor_sync(0xffffffffu, tm1, 1));
        tm1 = fmaxf(tm1, __shfl_xor_sync(0xffffffffu, tm1, 2));
        tm0 *= SC; tm1 *= SC;
        float nm0 = fmaxf(m0, tm0), nm1 = fmaxf(m1, tm1);
        float a0 = __expf(m0 - nm0), a1 = __expf(m1 - nm1);
        float t0 = 0.f, t1 = 0.f;
        #pragma unroll
        for (int nt = 0; nt < 8; nt++) {
            float px = __expf(fmaf(sc[nt].x, SC, -nm0));
            float py = __expf(fmaf(sc[nt].y, SC, -nm0));
            float pz = __expf(fmaf(sc[nt].z, SC, -nm1));
            float pw = __expf(fmaf(sc[nt].w, SC, -nm1));
            t0 += px + py; t1 += pz + pw;
            const int col = nt * 8 + 2 * tg;
            *(__half2*)(pr0h + col) = __floats2half2_rn(px, py);
            *(__half2*)(pr1h + col) = __floats2half2_rn(pz, pw);
            o[nt].x *= a0; o[nt].y *= a0;
            o[nt].z *= a1; o[nt].w *= a1;
        }
        t0 += __shfl_xor_sync(0xffffffffu, t0, 1);
        t0 += __shfl_xor_sync(0xffffffffu, t0, 2);
        t1 += __shfl_xor_sync(0xffffffffu, t1, 1);
        t1 += __shfl_xor_sync(0xffffffffu, t1, 2);
        s0 = s0 * a0 + t0;
        s1 = s1 * a1 + t1;
        m0 = nm0; m1 = nm1;
        __syncwarp();

        cp_wait<1>();
        __syncthreads();

        #pragma unroll
        for (int ks = 0; ks < 4; ks++) {
            uint32 a[4];
            ldsm4(a, sptr(&U[(16 * w + aRow) * HS + ks * 16 + aCol]));
            #pragma unroll
            for (int pr = 0; pr < 4; pr++) {
                uint32 b[4];
                ldsm4(b, sptr(&Vt[(pr * 16 + bRow) * HS + ks * 16 + bCol]));
                mmah(o[2 * pr],     a, b[0], b[1]);
                mmah(o[2 * pr + 1], a, b[2], b[3]);
            }
        }
        __syncthreads();
    }

    float i0 = 1.f / s0, i1 = 1.f / s1;
    __half* Os = K0;
    #pragma unroll
    for (int nt = 0; nt < 8; nt++) {
        const int col = nt * 8 + 2 * tg;
        *(__half2*)(Os + (16 * w + r) * HS + col)     = __floats2half2_rn(o[nt].x * i0, o[nt].y * i0);
        *(__half2*)(Os + (16 * w + r + 8) * HS + col) = __floats2half2_rn(o[nt].z * i1, o[nt].w * i1);
    }
    __syncthreads();
    __half* dst = outh + ((size_t)(n * 1024) + q0 + stok) * 192 + h * 64 + seg;
    #pragma unroll
    for (int i = 0; i < 4; i++)
        *(uint4*)(dst + i * 8) = *(const uint4*)(Os + stok * HS + seg + i * 8);
}

// ---------------------------------------------------------------------------
// Attention pass 2: L=16, scalar fp32 from half inputs
// ---------------------------------------------------------------------------
__global__ void k_attn2h(const __half* __restrict__ qkh, const __half* __restrict__ vTh,
                         __half* __restrict__ outh) {
    __shared__ float qs[16][68], ks[16][68], vs[1024], S[16 * 17];
    int bh = blockIdx.x, n = bh / 3, h = bh % 3;
    int tid = threadIdx.x;
    const __half* Qb = qkh + (size_t)(n * 16) * 384 + h * 128;
    const __half* Vb = vTh + (size_t)(n * 192 + h * 64) * 16;
    for (int i = tid; i < 1024; i += 256) {
        int q = i >> 6, c = i & 63;
        qs[q][c] = __half2float(Qb[(size_t)q * 384 + c]) * 0.125f;
        ks[q][c] = __half2float(Qb[(size_t)q * 384 + 64 + c]);
        vs[i] = __half2float(Vb[i]);
    }
    __syncthreads();
    {
        int q = tid >> 4, s = tid & 15;
        float a = 0.f;
        #pragma unroll
        for (int c = 0; c < 64; c++) a += qs[q][c] * ks[s][c];
        S[q * 17 + s] = a;
    }
    __syncthreads();
    if (tid < 16) {
        float* row = S + tid * 17;
        float m = -1e30f;
        #pragma unroll
        for (int s = 0; s < 16; s++) m = fmaxf(m, row[s]);
        float sum = 0.f;
        #pragma unroll
        for (int s = 0; s < 16; s++) { float e = __expf(row[s] - m); row[s] = e; sum += e; }
        float inv = 1.f / sum;
        #pragma unroll
        for (int s = 0; s < 16; s++) row[s] *= inv;
    }
    __syncthreads();
    {
        int q = tid & 15;
        int cb = (tid >> 4) << 2;
        float a0 = 0.f, a1 = 0.f, a2 = 0.f, a3 = 0.f;
        #pragma unroll
        for (int s = 0; s < 16; s++) {
            float sv = S[q * 17 + s];
            a0 += vs[(cb + 0) * 16 + s] * sv;
            a1 += vs[(cb + 1) * 16 + s] * sv;
            a2 += vs[(cb + 2) * 16 + s] * sv;
            a3 += vs[(cb + 3) * 16 + s] * sv;
        }
        __half* ob = outh + ((size_t)(n * 16) + q) * 192 + h * 64 + cb;
        ob[0] = __float2half(a0);
        ob[1] = __float2half(a1);
        ob[2] = __float2half(a2);
        ob[3] = __float2half(a3);
    }
}

// ---------------------------------------------------------------------------
extern "C" void kernel_launch(void* const* d_in, const int* in_sizes, int n_in,
                              void* d_out, int out_size) {
    const float* x       = (const float*)d_in[0];
    const float* norm_g  = (const float*)d_in[1];
    const float* norm_b  = (const float*)d_in[2];
    const float* qkv_w   = (const float*)d_in[3];
    const float* qkv_b   = (const float*)d_in[4];
    const float* proj_w  = (const float*)d_in[5];
    const float* proj_b  = (const float*)d_in[6];
    const float* normt_g = (const float*)d_in[7];
    const float* normt_b = (const float*)d_in[8];
    const float* qkvt_w  = (const float*)d_in[9];
    const float* qkvt_b  = (const float*)d_in[10];
    const float* projt_w = (const float*)d_in[11];
    const float* projt_b = (const float*)d_in[12];
    float* out = (float*)d_out;

    float *xs, *y, *yt;
    __half *nrm16, *qk16, *v16T, *att16, *w16;
    cudaGetSymbolAddress((void**)&xs,    g_xs);
    cudaGetSymbolAddress((void**)&y,     g_y);
    cudaGetSymbolAddress((void**)&yt,    g_yt);
    cudaGetSymbolAddress((void**)&nrm16, g_nrm16);
    cudaGetSymbolAddress((void**)&qk16,  g_qk16);
    cudaGetSymbolAddress((void**)&v16T,  g_v16T);
    cudaGetSymbolAddress((void**)&att16, g_att16);
    cudaGetSymbolAddress((void**)&w16,   g_w16);

    const __half* w_qkv  = w16;
    const __half* w_proj = w16 + 110592;
    const __half* w_qkvt = w16 + 147456;
    const __half* w_projt= w16 + 258048;

    cudaFuncSetAttribute(k_convq, cudaFuncAttributeMaxDynamicSharedMemorySize, CONVQ_SMEM);

    k_wprep<<<288, 1024>>>(qkv_w, proj_w, qkvt_w, projt_w);

    // ---- pass 1 (spatial, L=1024) ----
    k_gn1s<<<NBT * 32, 256>>>(x);
    k_gn1at<<<dim3(16, 32), 256>>>(x, norm_g, norm_b);
    k_convq<<<dim3(256, 3), 128, CONVQ_SMEM>>>(nrm16, w_qkv, qkv_b, qk16, v16T, 10);
    k_attn1h<<<dim3(16, 96), 128>>>(qk16, v16T, att16);
    k_convh<<<dim3(256, 3), 128>>>(att16, w_proj, proj_b, x, y, 192, 10, 2);

    // ---- pass 2 (temporal, L=16) ----
    k_transpose2c<<<dim3(16, 48, 2), 256>>>();
    k_gn2h<<<2048, 128>>>(yt, normt_g, normt_b, nrm16);
    k_convq<<<dim3(256, 3), 128, CONVQ_SMEM>>>(nrm16, w_qkvt, qkvt_b, qk16, v16T, 4);
    k_attn2h<<<6144, 256>>>(qk16, v16T, att16);
    k_convh<<<dim3(256, 3), 128>>>(att16, w_projt, projt_b, yt, xs, 192, 4, 1);
    k_transpose3c<<<dim3(16, 48, 2), 256>>>(out);
}